// round 2
// baseline (speedup 1.0000x reference)
#include <cuda_runtime.h>
#include <math.h>

#define NN 20000
#define NE 320000
#define CC 14
#define TILES_E (NE/64)            // 5000
#define TILES_N ((NN+63)/64)       // 313

// ---------------- scratch ----------------
__device__ float g_radial[(size_t)NE*256];
__device__ float g_cat[(size_t)NE*384];
__device__ float g_rfeat[(size_t)NE*128];   // rfeat; later reused as n1 output
__device__ float g_ef1[(size_t)NE*128];     // e1 out; later reused as c1 hidden
__device__ float g_ef[(size_t)NE*128];      // e2-gated out; later reused as n2 out
__device__ float g_rinv[NE];
__device__ float g_csum[NN];
__device__ float g_pool3[NN*3];
__device__ float g_aggsum[(size_t)NN*128];
__device__ float g_cnt_col[NN];
__device__ float g_xsum[NN*CC*3];
__device__ float g_cnt_row[NN];
__device__ float g_ncat[(size_t)NN*256];

__device__ __forceinline__ float sigm(float v){ return 1.f/(1.f+__expf(-v)); }
__device__ __forceinline__ float silu_(float v){ return v*sigm(v); }

// ---------------- zero accumulators ----------------
__global__ void k_zero(){
    int i = blockIdx.x*blockDim.x + threadIdx.x;
    const int A = NN*128, B = A+NN, D = B+NN*CC*3, T = D+NN;
    if(i >= T) return;
    if(i < A) g_aggsum[i]=0.f;
    else if(i < B) g_cnt_col[i-A]=0.f;
    else if(i < D) g_xsum[i-B]=0.f;
    else g_cnt_row[i-D]=0.f;
}

// ---------------- node prep: csum + pooled coords ----------------
__global__ void k_prep(const float* __restrict__ x, const float* __restrict__ cw){
    int n = blockIdx.x*blockDim.x + threadIdx.x;
    if(n >= NN) return;
    float cnt=0.f, px=0.f, py=0.f, pz=0.f;
    #pragma unroll
    for(int i=0;i<CC;i++){
        float w = cw[n*CC+i];
        if(w != 0.f){
            cnt += 1.f;
            const float* xp = &x[(n*CC+i)*3];
            px += xp[0]; py += xp[1]; pz += xp[2];
        }
    }
    g_csum[n] = cnt;
    float inv = 1.f/cnt;
    g_pool3[n*3+0]=px*inv; g_pool3[n*3+1]=py*inv; g_pool3[n*3+2]=pz*inv;
}

// ---------------- per-edge geometry: radial[256] + rinv, warp per edge ------
#define GS 992
__global__ void k_geom(const float* __restrict__ x, const int* __restrict__ row,
                       const int* __restrict__ col, const float* __restrict__ attr,
                       const float* __restrict__ cw){
    __shared__ float sm[8][GS];
    int warp = threadIdx.x>>5, lane = threadIdx.x&31;
    int e = blockIdx.x*8 + warp;
    if(e >= NE) return;
    float* s = sm[warp];
    int r = row[e], c = col[e];
    const int oCWR=0,oCWC=14,oXR=28,oXC=70,oAR=112,oAC=336,oM=560,oT=756;
    if(lane < CC){ s[oCWR+lane]=cw[r*CC+lane]; s[oCWC+lane]=cw[c*CC+lane]; }
    for(int i=lane;i<42;i+=32){ s[oXR+i]=x[r*42+i]; s[oXC+i]=x[c*42+i]; }
    for(int i=lane;i<224;i+=32){ s[oAR+i]=attr[r*224+i]; s[oAC+i]=attr[c*224+i]; }
    __syncwarp();
    for(int idx=lane; idx<196; idx+=32){
        int i = idx/14, j = idx - i*14;
        float dx = s[oXR+i*3+0]-s[oXC+j*3+0];
        float dy = s[oXR+i*3+1]-s[oXC+j*3+1];
        float dz = s[oXR+i*3+2]-s[oXC+j*3+2];
        float d = sqrtf(dx*dx+dy*dy+dz*dz);
        s[oM+idx] = d * s[oCWR+i] * s[oCWC+j];
    }
    __syncwarp();
    int b = lane&15, hh = lane>>4;
    {   // T[i][b] = sum_j M[i][j]*attrC[j][b]
        float acj[CC];
        #pragma unroll
        for(int j=0;j<CC;j++) acj[j] = s[oAC + j*16 + b];
        #pragma unroll
        for(int i0=0;i0<7;i0++){
            int i = hh*7 + i0;
            float t = 0.f;
            #pragma unroll
            for(int j=0;j<CC;j++) t += s[oM + i*14 + j]*acj[j];
            s[oT + i*16 + b] = t;
        }
    }
    __syncwarp();
    // radial[a][b] = sum_i attrR[i][a]*T[i][b]; lane owns b, a = hh*8+q
    float racc[8] = {0,0,0,0,0,0,0,0};
    {
        float tb[CC];
        #pragma unroll
        for(int i=0;i<CC;i++) tb[i] = s[oT + i*16 + b];
        #pragma unroll
        for(int i=0;i<CC;i++){
            float tv = tb[i];
            #pragma unroll
            for(int q=0;q<8;q++) racc[q] += s[oAR + i*16 + hh*8 + q]*tv;
        }
    }
    float sq = 0.f;
    float* go = &g_radial[(size_t)e*256];
    #pragma unroll
    for(int q=0;q<8;q++){ sq += racc[q]*racc[q]; go[(hh*8+q)*16 + b] = racc[q]; }
    #pragma unroll
    for(int o=16;o>0;o>>=1) sq += __shfl_xor_sync(0xffffffffu, sq, o);
    if(lane==0) g_rinv[e] = 1.f/(sqrtf(sq)+1.f);
}

// ======= generic batched GEMM: O[M,128] = epi(A[M,K] @ W[128,K]^T + b) ======
// MODE 0: plain (+ optional per-row scale)   MODE 1: silu
// MODE 2: silu + attention gate + scatter-add to agg[col]
template<int K, int MODE>
__global__ void __launch_bounds__(256) kgemm(
    const float* __restrict__ A, const float* __restrict__ Wg, const float* __restrict__ bg,
    float* __restrict__ O, int M, int tiles,
    const float* __restrict__ rowscale,
    const int* __restrict__ colidx, const float* __restrict__ attWg,
    const float* __restrict__ attbg,
    float* __restrict__ agg, float* __restrict__ cnt)
{
    extern __shared__ float smem[];
    float* sW = smem;                // K*128
    float* sA = smem + K*128;        // 16*64
    int* sCol = (int*)(sA + 16*64);  // 64
    int tid = threadIdx.x, tx = tid&15, ty = tid>>4;
    for(int idx=tid; idx<K*128; idx+=256){ int n=idx&127, k=idx>>7; sW[k*128+n]=Wg[n*K+k]; }
    float bb[8], aw[8]; float attb=0.f;
    #pragma unroll
    for(int i=0;i<8;i++) bb[i]=bg[tx*8+i];
    if(MODE==2){
        #pragma unroll
        for(int i=0;i<8;i++) aw[i]=attWg[tx*8+i];
        attb = attbg[0];
    }
    __syncthreads();
    for(int tile=blockIdx.x; tile<tiles; tile+=gridDim.x){
        if(MODE==2 && tid<64){ int rg=tile*64+tid; sCol[tid] = (rg<M)? colidx[rg] : 0; }
        float acc[4][8];
        #pragma unroll
        for(int j=0;j<4;j++)
            #pragma unroll
            for(int i=0;i<8;i++) acc[j][i]=0.f;
        #pragma unroll 1
        for(int kt=0;kt<K/16;kt++){
            {   int ee=tid>>2, q=tid&3, kg=kt*16+q*4; int rg=tile*64+ee;
                float4 v = make_float4(0.f,0.f,0.f,0.f);
                if(rg<M) v = *(const float4*)&A[(size_t)rg*K+kg];
                sA[(q*4+0)*64+ee]=v.x; sA[(q*4+1)*64+ee]=v.y;
                sA[(q*4+2)*64+ee]=v.z; sA[(q*4+3)*64+ee]=v.w; }
            __syncthreads();
            #pragma unroll
            for(int k=0;k<16;k++){
                float4 a4 = *(float4*)&sA[k*64 + ty*4];
                float4 w0 = *(float4*)&sW[(kt*16+k)*128 + tx*8];
                float4 w1 = *(float4*)&sW[(kt*16+k)*128 + tx*8 + 4];
                float av[4]={a4.x,a4.y,a4.z,a4.w};
                float wv[8]={w0.x,w0.y,w0.z,w0.w,w1.x,w1.y,w1.z,w1.w};
                #pragma unroll
                for(int j=0;j<4;j++)
                    #pragma unroll
                    for(int i=0;i<8;i++) acc[j][i] += av[j]*wv[i];
            }
            __syncthreads();
        }
        #pragma unroll
        for(int j=0;j<4;j++){
            int rg = tile*64 + ty*4 + j;
            float v[8];
            #pragma unroll
            for(int i=0;i<8;i++){ v[i]=acc[j][i]+bb[i]; if(MODE>=1) v[i]=silu_(v[i]); }
            if(MODE==0 && rowscale != 0 && rg<M){
                float rs = rowscale[rg];
                #pragma unroll
                for(int i=0;i<8;i++) v[i]*=rs;
            }
            if(MODE==2){
                float d=0.f;
                #pragma unroll
                for(int i=0;i<8;i++) d += v[i]*aw[i];
                #pragma unroll
                for(int o=1;o<16;o<<=1) d += __shfl_xor_sync(0xffffffffu, d, o);
                float gte = sigm(d+attb);
                #pragma unroll
                for(int i=0;i<8;i++) v[i]*=gte;
            }
            if(rg<M){
                *(float4*)&O[(size_t)rg*128+tx*8]   = make_float4(v[0],v[1],v[2],v[3]);
                *(float4*)&O[(size_t)rg*128+tx*8+4] = make_float4(v[4],v[5],v[6],v[7]);
                if(MODE==2){
                    int cc = sCol[ty*4+j];
                    #pragma unroll
                    for(int i=0;i<8;i++) atomicAdd(&agg[(size_t)cc*128+tx*8+i], v[i]);
                    if(tx==0) atomicAdd(&cnt[cc], 1.f);
                }
            }
        }
        __syncthreads();
    }
}

// ---------------- build concat [h_r | h_c | rfeat] ----------------
__global__ void k_cat(const float* __restrict__ h, const int* __restrict__ row,
                      const int* __restrict__ col){
    long long idx = (long long)blockIdx.x*blockDim.x + threadIdx.x;
    if(idx >= (long long)NE*96) return;
    int e = (int)(idx/96), g = (int)(idx%96);
    float4 v;
    if(g<32)       v = *(const float4*)&h[(size_t)row[e]*128 + g*4];
    else if(g<64)  v = *(const float4*)&h[(size_t)col[e]*128 + (g-32)*4];
    else           v = *(const float4*)&g_rfeat[(size_t)e*128 + (g-64)*4];
    *(float4*)&g_cat[(size_t)e*384 + g*4] = v;
}

// ---------------- coord path: ch = hid@c2^T+b, roller pool, trans scatter ----
__global__ void k_coord(const float* __restrict__ x, const int* __restrict__ row,
                        const int* __restrict__ col,
                        const float* __restrict__ c2W, const float* __restrict__ c2b){
    __shared__ float sch[8][16];
    int warp = threadIdx.x>>5, lane = threadIdx.x&31;
    int e = blockIdx.x*8 + warp;
    if(e >= NE) return;
    int r = row[e], c = col[e];
    if(lane < CC){
        float acc = c2b[lane];
        const float* hp = &g_ef1[(size_t)e*128];   // c1-hidden
        const float* wp = &c2W[lane*128];
        #pragma unroll 8
        for(int k=0;k<128;k+=4)
            acc += hp[k]*wp[k]+hp[k+1]*wp[k+1]+hp[k+2]*wp[k+2]+hp[k+3]*wp[k+3];
        sch[warp][lane] = acc;
    }
    __syncwarp();
    int cs = (int)(g_csum[r]+0.5f);
    int w = 15 - cs;                     // window size = C - tsize
    if(lane < CC){
        float s = 0.f;
        int end = min(lane + w - 1, CC-1);
        for(int j=lane; j<=end; j++) s += sch[warp][j];
        float pooled = s/(float)w;
        float px=g_pool3[c*3], py=g_pool3[c*3+1], pz=g_pool3[c*3+2];
        const float* xp = &x[((size_t)r*CC+lane)*3];
        atomicAdd(&g_xsum[(r*CC+lane)*3+0], (xp[0]-px)*pooled);
        atomicAdd(&g_xsum[(r*CC+lane)*3+1], (xp[1]-py)*pooled);
        atomicAdd(&g_xsum[(r*CC+lane)*3+2], (xp[2]-pz)*pooled);
    }
    if(lane==0) atomicAdd(&g_cnt_row[r], 1.f);
}

// ---------------- node concat [h | agg] ----------------
__global__ void k_nodecat(const float* __restrict__ h){
    int idx = blockIdx.x*blockDim.x + threadIdx.x;
    if(idx >= NN*64) return;
    int n = idx>>6, g = idx&63;
    float4 v;
    if(g<32) v = *(const float4*)&h[(size_t)n*128 + g*4];
    else{
        float inv = 1.f/fmaxf(g_cnt_col[n],1.f);
        const float* a = &g_aggsum[(size_t)n*128 + (g-32)*4];
        v = make_float4(a[0]*inv,a[1]*inv,a[2]*inv,a[3]*inv);
    }
    *(float4*)&g_ncat[(size_t)n*256 + g*4] = v;
}

// ---------------- x_out ----------------
__global__ void k_xout(const float* __restrict__ x, float* __restrict__ xout){
    int idx = blockIdx.x*blockDim.x + threadIdx.x;
    if(idx >= NN*CC*3) return;
    int n = idx/(CC*3);
    xout[idx] = x[idx] + g_xsum[idx]/fmaxf(g_cnt_row[n],1.f);
}

// ---------------- layernorm: h_out = LN(h + nh)*g + b ----------------
__global__ void k_ln(const float* __restrict__ h, const float* __restrict__ lng,
                     const float* __restrict__ lnb, float* __restrict__ out){
    __shared__ float red[8];
    int n = blockIdx.x, t = threadIdx.x;
    float y = h[(size_t)n*128+t] + g_ef[(size_t)n*128+t];   // g_ef holds nh
    float s = y;
    #pragma unroll
    for(int o=16;o>0;o>>=1) s += __shfl_xor_sync(0xffffffffu, s, o);
    if((t&31)==0) red[t>>5] = s;
    __syncthreads();
    float mu = (red[0]+red[1]+red[2]+red[3]) * (1.f/128.f);
    float d = y - mu;
    float v = d*d;
    #pragma unroll
    for(int o=16;o>0;o>>=1) v += __shfl_xor_sync(0xffffffffu, v, o);
    if((t&31)==0) red[4+(t>>5)] = v;
    __syncthreads();
    float var = (red[4]+red[5]+red[6]+red[7]) * (1.f/128.f);
    out[(size_t)n*128+t] = d*rsqrtf(var+1e-5f)*lng[t] + lnb[t];
}

// ======================= host launcher =======================
static inline int smbytes(int K){ return K*512 + 16*64*4 + 64*4; }

extern "C" void kernel_launch(void* const* d_in, const int* in_sizes, int n_in,
                              void* d_out, int out_size){
    const float* h    = (const float*)d_in[0];
    const float* x    = (const float*)d_in[1];
    const int*   row  = (const int*)  d_in[2];
    const int*   col  = (const int*)  d_in[3];
    const float* attr = (const float*)d_in[4];
    const float* cw   = (const float*)d_in[5];
    const float* radW = (const float*)d_in[6];  const float* radB = (const float*)d_in[7];
    const float* e1W  = (const float*)d_in[8];  const float* e1B  = (const float*)d_in[9];
    const float* e2W  = (const float*)d_in[10]; const float* e2B  = (const float*)d_in[11];
    const float* attW = (const float*)d_in[12]; const float* attB = (const float*)d_in[13];
    const float* c1W  = (const float*)d_in[14]; const float* c1B  = (const float*)d_in[15];
    const float* c2W  = (const float*)d_in[16]; const float* c2B  = (const float*)d_in[17];
    const float* n1W  = (const float*)d_in[18]; const float* n1B  = (const float*)d_in[19];
    const float* n2W  = (const float*)d_in[20]; const float* n2B  = (const float*)d_in[21];
    const float* lng  = (const float*)d_in[22]; const float* lnb  = (const float*)d_in[23];
    float* outH = (float*)d_out;
    float* outX = outH + (size_t)NN*128;

    void *p_radial,*p_rfeat,*p_cat,*p_ef1,*p_ef,*p_rinv,*p_ncat,*p_agg,*p_cntc;
    cudaGetSymbolAddress(&p_radial, g_radial);
    cudaGetSymbolAddress(&p_rfeat,  g_rfeat);
    cudaGetSymbolAddress(&p_cat,    g_cat);
    cudaGetSymbolAddress(&p_ef1,    g_ef1);
    cudaGetSymbolAddress(&p_ef,     g_ef);
    cudaGetSymbolAddress(&p_rinv,   g_rinv);
    cudaGetSymbolAddress(&p_ncat,   g_ncat);
    cudaGetSymbolAddress(&p_agg,    g_aggsum);
    cudaGetSymbolAddress(&p_cntc,   g_cnt_col);

    cudaFuncSetAttribute(kgemm<256,0>, cudaFuncAttributeMaxDynamicSharedMemorySize, smbytes(256));
    cudaFuncSetAttribute(kgemm<384,1>, cudaFuncAttributeMaxDynamicSharedMemorySize, smbytes(384));
    cudaFuncSetAttribute(kgemm<128,2>, cudaFuncAttributeMaxDynamicSharedMemorySize, smbytes(128));
    cudaFuncSetAttribute(kgemm<128,1>, cudaFuncAttributeMaxDynamicSharedMemorySize, smbytes(128));
    cudaFuncSetAttribute(kgemm<256,1>, cudaFuncAttributeMaxDynamicSharedMemorySize, smbytes(256));
    cudaFuncSetAttribute(kgemm<128,0>, cudaFuncAttributeMaxDynamicSharedMemorySize, smbytes(128));

    const int ZT = NN*128 + NN + NN*CC*3 + NN;
    k_zero<<<(ZT+255)/256, 256>>>();
    k_prep<<<(NN+255)/256, 256>>>(x, cw);
    k_geom<<<NE/8, 256>>>(x, row, col, attr, cw);

    // rfeat = (radial @ radW^T + b) * rinv
    kgemm<256,0><<<152, 256, smbytes(256)>>>((const float*)p_radial, radW, radB,
        (float*)p_rfeat, NE, TILES_E, (const float*)p_rinv, 0,0,0,0,0);
    // cat = [h_r | h_c | rfeat]
    k_cat<<<(int)(((long long)NE*96 + 255)/256), 256>>>(h, row, col);
    // ef1 = silu(cat @ e1^T + b)
    kgemm<384,1><<<152, 256, smbytes(384)>>>((const float*)p_cat, e1W, e1B,
        (float*)p_ef1, NE, TILES_E, 0, 0,0,0,0,0);
    // ef = silu(ef1 @ e2^T + b) * sigmoid(att); scatter agg[col]
    kgemm<128,2><<<456, 256, smbytes(128)>>>((const float*)p_ef1, e2W, e2B,
        (float*)p_ef, NE, TILES_E, 0, col, attW, attB, (float*)p_agg, (float*)p_cntc);
    // hid = silu(ef @ c1^T + b)
    kgemm<128,1><<<456, 256, smbytes(128)>>>((const float*)p_ef, c1W, c1B,
        (float*)p_ef1, NE, TILES_E, 0, 0,0,0,0,0);
    // coord path
    k_coord<<<NE/8, 256>>>(x, row, col, c2W, c2B);
    // node path
    k_nodecat<<<(NN*64+255)/256, 256>>>(h);
    k_xout<<<(NN*CC*3+255)/256, 256>>>(x, outX);
    kgemm<256,1><<<152, 256, smbytes(256)>>>((const float*)p_ncat, n1W, n1B,
        (float*)p_rfeat, NN, TILES_N, 0, 0,0,0,0,0);
    kgemm<128,0><<<313, 256, smbytes(128)>>>((const float*)p_rfeat, n2W, n2B,
        (float*)p_ef, NN, TILES_N, 0, 0,0,0,0,0);
    k_ln<<<NN, 128>>>(h, lng, lnb, outH);
}

// round 3
// speedup vs baseline: 2.3173x; 2.3173x over previous
#include <cuda_runtime.h>
#include <math.h>

#define NN 20000
#define NE 320000
#define CC 14
#define TE128 (NE/128)              // 2500
#define TN128 ((NN+127)/128)        // 157

// ---------------- scratch ----------------
__device__ float g_radial[(size_t)NE*256];
__device__ float g_rfeat[(size_t)NE*128];   // rfeat; later n1 output
__device__ float g_ef1[(size_t)NE*128];     // e1 out; later c1 hidden
__device__ float g_ef[(size_t)NE*128];      // e2-gated out; later n2 out
__device__ float g_rinv[NE];
__device__ float g_csum[NN];
__device__ float g_pool3[NN*3];
__device__ float g_aggsum[(size_t)NN*128];
__device__ float g_cnt_col[NN];
__device__ float g_xsum[NN*CC*3];
__device__ float g_cnt_row[NN];
__device__ float g_ncat[(size_t)NN*256];

__device__ __forceinline__ float sigm(float v){ return 1.f/(1.f+__expf(-v)); }
__device__ __forceinline__ float silu_(float v){ return v*sigm(v); }

// ---------------- zero accumulators ----------------
__global__ void k_zero(){
    int i = blockIdx.x*blockDim.x + threadIdx.x;
    const int A = NN*128, B = A+NN, D = B+NN*CC*3, T = D+NN;
    if(i >= T) return;
    if(i < A) g_aggsum[i]=0.f;
    else if(i < B) g_cnt_col[i-A]=0.f;
    else if(i < D) g_xsum[i-B]=0.f;
    else g_cnt_row[i-D]=0.f;
}

// ---------------- node prep ----------------
__global__ void k_prep(const float* __restrict__ x, const float* __restrict__ cw){
    int n = blockIdx.x*blockDim.x + threadIdx.x;
    if(n >= NN) return;
    float cnt=0.f, px=0.f, py=0.f, pz=0.f;
    #pragma unroll
    for(int i=0;i<CC;i++){
        float w = cw[n*CC+i];
        if(w != 0.f){
            cnt += 1.f;
            const float* xp = &x[(n*CC+i)*3];
            px += xp[0]; py += xp[1]; pz += xp[2];
        }
    }
    g_csum[n] = cnt;
    float inv = 1.f/cnt;
    g_pool3[n*3+0]=px*inv; g_pool3[n*3+1]=py*inv; g_pool3[n*3+2]=pz*inv;
}

// ---------------- per-edge geometry (warp/edge) ----------------
#define GS 992
__global__ void k_geom(const float* __restrict__ x, const int* __restrict__ row,
                       const int* __restrict__ col, const float* __restrict__ attr,
                       const float* __restrict__ cw){
    __shared__ float sm[8][GS];
    int warp = threadIdx.x>>5, lane = threadIdx.x&31;
    int e = blockIdx.x*8 + warp;
    if(e >= NE) return;
    float* s = sm[warp];
    int r = row[e], c = col[e];
    const int oCWR=0,oCWC=14,oXR=28,oXC=70,oAR=112,oAC=336,oM=560,oT=756;
    if(lane < CC){ s[oCWR+lane]=cw[r*CC+lane]; s[oCWC+lane]=cw[c*CC+lane]; }
    for(int i=lane;i<42;i+=32){ s[oXR+i]=x[r*42+i]; s[oXC+i]=x[c*42+i]; }
    for(int i=lane;i<224;i+=32){ s[oAR+i]=attr[r*224+i]; s[oAC+i]=attr[c*224+i]; }
    __syncwarp();
    for(int idx=lane; idx<196; idx+=32){
        int i = idx/14, j = idx - i*14;
        float dx = s[oXR+i*3+0]-s[oXC+j*3+0];
        float dy = s[oXR+i*3+1]-s[oXC+j*3+1];
        float dz = s[oXR+i*3+2]-s[oXC+j*3+2];
        float d = sqrtf(dx*dx+dy*dy+dz*dz);
        s[oM+idx] = d * s[oCWR+i] * s[oCWC+j];
    }
    __syncwarp();
    int b = lane&15, hh = lane>>4;
    {
        float acj[CC];
        #pragma unroll
        for(int j=0;j<CC;j++) acj[j] = s[oAC + j*16 + b];
        #pragma unroll
        for(int i0=0;i0<7;i0++){
            int i = hh*7 + i0;
            float t = 0.f;
            #pragma unroll
            for(int j=0;j<CC;j++) t += s[oM + i*14 + j]*acj[j];
            s[oT + i*16 + b] = t;
        }
    }
    __syncwarp();
    float racc[8] = {0,0,0,0,0,0,0,0};
    {
        float tb[CC];
        #pragma unroll
        for(int i=0;i<CC;i++) tb[i] = s[oT + i*16 + b];
        #pragma unroll
        for(int i=0;i<CC;i++){
            float tv = tb[i];
            #pragma unroll
            for(int q=0;q<8;q++) racc[q] += s[oAR + i*16 + hh*8 + q]*tv;
        }
    }
    float sq = 0.f;
    float* go = &g_radial[(size_t)e*256];
    #pragma unroll
    for(int q=0;q<8;q++){ sq += racc[q]*racc[q]; go[(hh*8+q)*16 + b] = racc[q]; }
    #pragma unroll
    for(int o=16;o>0;o>>=1) sq += __shfl_xor_sync(0xffffffffu, sq, o);
    if(lane==0) g_rinv[e] = 1.f/(sqrtf(sq)+1.f);
}

// ======= double-buffered GEMM: O[M,128] = epi(A[M,K] @ W[128,K]^T + b) ======
// BM=128 BN=128 BK=16, 256 threads, 8x8 regs/thread, 2 CTAs/SM.
// MODE 0: plain (+opt per-row scale); 1: silu; 2: silu+att gate+scatter agg[col]
// GATHER: A row = [h[row] | h[col] | rfeat] (K must be 384)
template<int K, int MODE, bool GATHER>
__global__ void __launch_bounds__(256,2) kgemm(
    const float* __restrict__ A, const float* __restrict__ Wg,
    const float* __restrict__ bg, float* __restrict__ O, int M, int tiles,
    const float* __restrict__ rowscale,
    const int* __restrict__ rowi, const int* __restrict__ coli,
    const float* __restrict__ attWg, const float* __restrict__ attbg,
    float* __restrict__ agg, float* __restrict__ cnt,
    const float* __restrict__ h, const float* __restrict__ rfeat)
{
    __shared__ float sA[2][16][128];
    __shared__ float sW[2][16][128];
    __shared__ int sRow[128], sCol[128];
    const int tid = threadIdx.x, tx = tid&15, ty = tid>>4;
    const int ee = tid>>1, q = tid&1, kq = q*8;

    float bb[8], aw[8]; float attb=0.f;
    #pragma unroll
    for(int i=0;i<8;i++) bb[i]=bg[tx*8+i];
    if(MODE==2){
        #pragma unroll
        for(int i=0;i<8;i++) aw[i]=attWg[tx*8+i];
        attb = attbg[0];
    }

    for(int tile=blockIdx.x; tile<tiles; tile+=gridDim.x){
        if(GATHER || MODE==2){
            if(tid<128){ int rg=tile*128+tid; sRow[tid]= (rg<M && rowi)? rowi[rg]:0; }
            else { int rg=tile*128+tid-128; sCol[tid-128]= (rg<M && coli)? coli[rg]:0; }
            __syncthreads();
        }
        float4 pa0, pa1, pw0, pw1;
        // ---- loaders ----
        auto ldA = [&](int kt, float4& v0, float4& v1){
            int rg = tile*128 + ee;
            int kg = kt*16 + kq;
            if(!GATHER){
                if(rg < M){
                    const float* p = &A[(size_t)rg*K + kg];
                    v0 = *(const float4*)p; v1 = *(const float4*)(p+4);
                } else { v0=v1=make_float4(0,0,0,0); }
            } else {
                const float* p;
                if(kg < 128)      p = &h[(size_t)sRow[ee]*128 + kg];
                else if(kg < 256) p = &h[(size_t)sCol[ee]*128 + (kg-128)];
                else              p = &rfeat[(size_t)(tile*128+ee)*128 + (kg-256)];
                v0 = *(const float4*)p; v1 = *(const float4*)(p+4);
            }
        };
        auto ldW = [&](int kt, float4& v0, float4& v1){
            const float* p = &Wg[(size_t)ee*K + kt*16 + kq];
            v0 = *(const float4*)p; v1 = *(const float4*)(p+4);
        };
        auto sts = [&](int buf, float4 a0, float4 a1, float4 w0, float4 w1){
            sA[buf][kq+0][ee]=a0.x; sA[buf][kq+1][ee]=a0.y;
            sA[buf][kq+2][ee]=a0.z; sA[buf][kq+3][ee]=a0.w;
            sA[buf][kq+4][ee]=a1.x; sA[buf][kq+5][ee]=a1.y;
            sA[buf][kq+6][ee]=a1.z; sA[buf][kq+7][ee]=a1.w;
            sW[buf][kq+0][ee]=w0.x; sW[buf][kq+1][ee]=w0.y;
            sW[buf][kq+2][ee]=w0.z; sW[buf][kq+3][ee]=w0.w;
            sW[buf][kq+4][ee]=w1.x; sW[buf][kq+5][ee]=w1.y;
            sW[buf][kq+6][ee]=w1.z; sW[buf][kq+7][ee]=w1.w;
        };
        // ---- prologue ----
        ldA(0, pa0, pa1); ldW(0, pw0, pw1);
        sts(0, pa0, pa1, pw0, pw1);
        __syncthreads();

        float acc[8][8];
        #pragma unroll
        for(int j=0;j<8;j++)
            #pragma unroll
            for(int i=0;i<8;i++) acc[j][i]=0.f;

        const int KT = K/16;
        #pragma unroll 1
        for(int kt=0; kt<KT; kt++){
            if(kt+1 < KT){ ldA(kt+1, pa0, pa1); ldW(kt+1, pw0, pw1); }
            const int buf = kt&1;
            #pragma unroll
            for(int k=0;k<16;k++){
                float4 a0 = *(const float4*)&sA[buf][k][ty*8];
                float4 a1 = *(const float4*)&sA[buf][k][ty*8+4];
                float4 w0 = *(const float4*)&sW[buf][k][tx*8];
                float4 w1 = *(const float4*)&sW[buf][k][tx*8+4];
                float av[8]={a0.x,a0.y,a0.z,a0.w,a1.x,a1.y,a1.z,a1.w};
                float wv[8]={w0.x,w0.y,w0.z,w0.w,w1.x,w1.y,w1.z,w1.w};
                #pragma unroll
                for(int j=0;j<8;j++)
                    #pragma unroll
                    for(int i=0;i<8;i++) acc[j][i] += av[j]*wv[i];
            }
            if(kt+1 < KT) sts((kt+1)&1, pa0, pa1, pw0, pw1);
            __syncthreads();
        }
        // ---- epilogue ----
        #pragma unroll
        for(int j=0;j<8;j++){
            int rl = ty*8 + j;
            int rg = tile*128 + rl;
            float v[8];
            #pragma unroll
            for(int i=0;i<8;i++){ v[i]=acc[j][i]+bb[i]; if(MODE>=1) v[i]=silu_(v[i]); }
            if(MODE==0 && rowscale && rg<M){
                float rs = rowscale[rg];
                #pragma unroll
                for(int i=0;i<8;i++) v[i]*=rs;
            }
            if(MODE==2){
                float d=0.f;
                #pragma unroll
                for(int i=0;i<8;i++) d += v[i]*aw[i];
                #pragma unroll
                for(int o=1;o<16;o<<=1) d += __shfl_xor_sync(0xffffffffu, d, o);
                float gte = sigm(d+attb);
                #pragma unroll
                for(int i=0;i<8;i++) v[i]*=gte;
            }
            if(rg < M){
                *(float4*)&O[(size_t)rg*128+tx*8]   = make_float4(v[0],v[1],v[2],v[3]);
                *(float4*)&O[(size_t)rg*128+tx*8+4] = make_float4(v[4],v[5],v[6],v[7]);
                if(MODE==2){
                    int cc = sCol[rl];
                    #pragma unroll
                    for(int i=0;i<8;i++) atomicAdd(&agg[(size_t)cc*128+tx*8+i], v[i]);
                    if(tx==0) atomicAdd(&cnt[cc], 1.f);
                }
            }
        }
        if(GATHER || MODE==2) __syncthreads();
    }
}

// ---------------- coord path: ch = hid@c2^T+b, roller pool, trans scatter ----
__global__ void __launch_bounds__(256) k_coord(const float* __restrict__ x,
        const int* __restrict__ row, const int* __restrict__ col,
        const float* __restrict__ c2W, const float* __restrict__ c2b){
    __shared__ float sc2[CC*128];
    __shared__ float scb[CC];
    int tid=threadIdx.x, warp=tid>>5, lane=tid&31;
    for(int i=tid;i<CC*128;i+=256) sc2[i]=c2W[i];
    if(tid<CC) scb[tid]=c2b[tid];
    __syncthreads();
    for(int e = blockIdx.x*8+warp; e < NE; e += gridDim.x*8){
        int r=row[e], c=col[e];
        float4 hv = *(const float4*)&g_ef1[(size_t)e*128 + lane*4];
        float p[CC];
        #pragma unroll
        for(int o=0;o<CC;o++){
            const float* w=&sc2[o*128+lane*4];
            p[o]=hv.x*w[0]+hv.y*w[1]+hv.z*w[2]+hv.w*w[3];
        }
        #pragma unroll
        for(int o=0;o<CC;o++){
            #pragma unroll
            for(int s=16;s>0;s>>=1) p[o]+=__shfl_xor_sync(0xffffffffu,p[o],s);
        }
        int cs = (int)(g_csum[r]+0.5f);
        int w = 15 - cs;                 // window size
        if(lane < CC){
            int end = min(lane + w - 1, CC-1);
            float s = 0.f;
            #pragma unroll
            for(int o=0;o<CC;o++){
                float v = p[o]+scb[o];
                if(o>=lane && o<=end) s += v;
            }
            float pooled = s/(float)w;
            float px=g_pool3[c*3], py=g_pool3[c*3+1], pz=g_pool3[c*3+2];
            const float* xp = &x[((size_t)r*CC+lane)*3];
            atomicAdd(&g_xsum[(r*CC+lane)*3+0], (xp[0]-px)*pooled);
            atomicAdd(&g_xsum[(r*CC+lane)*3+1], (xp[1]-py)*pooled);
            atomicAdd(&g_xsum[(r*CC+lane)*3+2], (xp[2]-pz)*pooled);
        }
        if(lane==0) atomicAdd(&g_cnt_row[r], 1.f);
    }
}

// ---------------- node concat [h | agg/cnt] ----------------
__global__ void k_nodecat(const float* __restrict__ h){
    int idx = blockIdx.x*blockDim.x + threadIdx.x;
    if(idx >= NN*64) return;
    int n = idx>>6, g = idx&63;
    float4 v;
    if(g<32) v = *(const float4*)&h[(size_t)n*128 + g*4];
    else{
        float inv = 1.f/fmaxf(g_cnt_col[n],1.f);
        const float* a = &g_aggsum[(size_t)n*128 + (g-32)*4];
        v = make_float4(a[0]*inv,a[1]*inv,a[2]*inv,a[3]*inv);
    }
    *(float4*)&g_ncat[(size_t)n*256 + g*4] = v;
}

// ---------------- x_out ----------------
__global__ void k_xout(const float* __restrict__ x, float* __restrict__ xout){
    int idx = blockIdx.x*blockDim.x + threadIdx.x;
    if(idx >= NN*CC*3) return;
    int n = idx/(CC*3);
    xout[idx] = x[idx] + g_xsum[idx]/fmaxf(g_cnt_row[n],1.f);
}

// ---------------- layernorm ----------------
__global__ void k_ln(const float* __restrict__ h, const float* __restrict__ lng,
                     const float* __restrict__ lnb, float* __restrict__ out){
    __shared__ float red[8];
    int n = blockIdx.x, t = threadIdx.x;
    float y = h[(size_t)n*128+t] + g_ef[(size_t)n*128+t];
    float s = y;
    #pragma unroll
    for(int o=16;o>0;o>>=1) s += __shfl_xor_sync(0xffffffffu, s, o);
    if((t&31)==0) red[t>>5] = s;
    __syncthreads();
    float mu = (red[0]+red[1]+red[2]+red[3]) * (1.f/128.f);
    float d = y - mu;
    float v = d*d;
    #pragma unroll
    for(int o=16;o>0;o>>=1) v += __shfl_xor_sync(0xffffffffu, v, o);
    if((t&31)==0) red[4+(t>>5)] = v;
    __syncthreads();
    float var = (red[4]+red[5]+red[6]+red[7]) * (1.f/128.f);
    out[(size_t)n*128+t] = d*rsqrtf(var+1e-5f)*lng[t] + lnb[t];
}

// ======================= host launcher =======================
extern "C" void kernel_launch(void* const* d_in, const int* in_sizes, int n_in,
                              void* d_out, int out_size){
    const float* h    = (const float*)d_in[0];
    const float* x    = (const float*)d_in[1];
    const int*   row  = (const int*)  d_in[2];
    const int*   col  = (const int*)  d_in[3];
    const float* attr = (const float*)d_in[4];
    const float* cw   = (const float*)d_in[5];
    const float* radW = (const float*)d_in[6];  const float* radB = (const float*)d_in[7];
    const float* e1W  = (const float*)d_in[8];  const float* e1B  = (const float*)d_in[9];
    const float* e2W  = (const float*)d_in[10]; const float* e2B  = (const float*)d_in[11];
    const float* attW = (const float*)d_in[12]; const float* attB = (const float*)d_in[13];
    const float* c1W  = (const float*)d_in[14]; const float* c1B  = (const float*)d_in[15];
    const float* c2W  = (const float*)d_in[16]; const float* c2B  = (const float*)d_in[17];
    const float* n1W  = (const float*)d_in[18]; const float* n1B  = (const float*)d_in[19];
    const float* n2W  = (const float*)d_in[20]; const float* n2B  = (const float*)d_in[21];
    const float* lng  = (const float*)d_in[22]; const float* lnb  = (const float*)d_in[23];
    float* outH = (float*)d_out;
    float* outX = outH + (size_t)NN*128;

    void *p_radial,*p_rfeat,*p_ef1,*p_ef,*p_rinv,*p_ncat,*p_agg,*p_cntc;
    cudaGetSymbolAddress(&p_radial, g_radial);
    cudaGetSymbolAddress(&p_rfeat,  g_rfeat);
    cudaGetSymbolAddress(&p_ef1,    g_ef1);
    cudaGetSymbolAddress(&p_ef,     g_ef);
    cudaGetSymbolAddress(&p_rinv,   g_rinv);
    cudaGetSymbolAddress(&p_ncat,   g_ncat);
    cudaGetSymbolAddress(&p_agg,    g_aggsum);
    cudaGetSymbolAddress(&p_cntc,   g_cnt_col);

    const int ZT = NN*128 + NN + NN*CC*3 + NN;
    k_zero<<<(ZT+255)/256, 256>>>();
    k_prep<<<(NN+255)/256, 256>>>(x, cw);
    k_geom<<<NE/8, 256>>>(x, row, col, attr, cw);

    const int GB = 304;   // 2 CTAs/SM persistent
    // rfeat = (radial @ radW^T + b) * rinv
    kgemm<256,0,false><<<GB,256>>>((const float*)p_radial, radW, radB,
        (float*)p_rfeat, NE, TE128, (const float*)p_rinv, 0,0,0,0,0,0, 0,0);
    // ef1 = silu([h_r|h_c|rfeat] @ e1^T + b)   (fused gather)
    kgemm<384,1,true><<<GB,256>>>(0, e1W, e1B,
        (float*)p_ef1, NE, TE128, 0, row, col, 0,0,0,0, h, (const float*)p_rfeat);
    // ef = silu(ef1 @ e2^T + b) * sigmoid(att); scatter agg[col]
    kgemm<128,2,false><<<GB,256>>>((const float*)p_ef1, e2W, e2B,
        (float*)p_ef, NE, TE128, 0, 0, col, attW, attB,
        (float*)p_agg, (float*)p_cntc, 0,0);
    // hid = silu(ef @ c1^T + b)
    kgemm<128,1,false><<<GB,256>>>((const float*)p_ef, c1W, c1B,
        (float*)p_ef1, NE, TE128, 0, 0,0,0,0,0,0, 0,0);
    // coord path (reads hid in g_ef1)
    k_coord<<<1216, 256>>>(x, row, col, c2W, c2B);
    // node path
    k_nodecat<<<(NN*64+255)/256, 256>>>(h);
    k_xout<<<(NN*CC*3+255)/256, 256>>>(x, outX);
    kgemm<256,1,false><<<GB,256>>>((const float*)p_ncat, n1W, n1B,
        (float*)p_rfeat, NN, TN128, 0, 0,0,0,0,0,0, 0,0);
    kgemm<128,0,false><<<GB,256>>>((const float*)p_rfeat, n2W, n2B,
        (float*)p_ef, NN, TN128, 0, 0,0,0,0,0,0, 0,0);
    k_ln<<<NN, 128>>>(h, lng, lnb, outH);
}

// round 5
// speedup vs baseline: 3.7993x; 1.6395x over previous
#include <cuda_runtime.h>
#include <math.h>
#include <stdint.h>

#define NN 20000
#define NE 320000
#define CC 14
#define TE128 (NE/128)              // 2500
#define TN128 ((NN+127)/128)        // 157

// ---------------- scratch ----------------
__device__ float g_radial[(size_t)NE*256];
__device__ float g_rfeat[(size_t)NE*128];   // rfeat; later n1 output
__device__ float g_ef1[(size_t)NE*128];     // e1 out; later c1 hidden
__device__ float g_ef[(size_t)NE*128];      // e2-gated out; later n2 out
__device__ float g_rinv[NE];
__device__ float g_csum[NN];
__device__ float g_pool3[NN*3];
__device__ float g_aggsum[(size_t)NN*128];
__device__ float g_cnt_col[NN];
__device__ float g_xsum[NN*CC*3];
__device__ float g_cnt_row[NN];
__device__ float g_ncat[(size_t)NN*256];

__device__ __forceinline__ float sigm(float v){ return 1.f/(1.f+__expf(-v)); }
__device__ __forceinline__ float silu_(float v){ return v*sigm(v); }
__device__ __forceinline__ uint32_t tf32c(float f){
    uint32_t u; asm("cvt.rna.tf32.f32 %0, %1;" : "=r"(u) : "f"(f)); return u;
}
__device__ __forceinline__ void mma8(float* c, const uint32_t* a, const uint32_t* b){
    asm volatile("mma.sync.aligned.m16n8k8.row.col.f32.tf32.tf32.f32 "
        "{%0,%1,%2,%3}, {%4,%5,%6,%7}, {%8,%9}, {%0,%1,%2,%3};"
        : "+f"(c[0]),"+f"(c[1]),"+f"(c[2]),"+f"(c[3])
        : "r"(a[0]),"r"(a[1]),"r"(a[2]),"r"(a[3]), "r"(b[0]),"r"(b[1]));
}

// ---------------- zero accumulators ----------------
__global__ void k_zero(){
    int i = blockIdx.x*blockDim.x + threadIdx.x;
    const int A = NN*128, B = A+NN, D = B+NN*CC*3, T = D+NN;
    if(i >= T) return;
    if(i < A) g_aggsum[i]=0.f;
    else if(i < B) g_cnt_col[i-A]=0.f;
    else if(i < D) g_xsum[i-B]=0.f;
    else g_cnt_row[i-D]=0.f;
}

// ---------------- node prep ----------------
__global__ void k_prep(const float* __restrict__ x, const float* __restrict__ cw){
    int n = blockIdx.x*blockDim.x + threadIdx.x;
    if(n >= NN) return;
    float cnt=0.f, px=0.f, py=0.f, pz=0.f;
    #pragma unroll
    for(int i=0;i<CC;i++){
        float w = cw[n*CC+i];
        if(w != 0.f){
            cnt += 1.f;
            const float* xp = &x[(n*CC+i)*3];
            px += xp[0]; py += xp[1]; pz += xp[2];
        }
    }
    g_csum[n] = cnt;
    float inv = 1.f/cnt;
    g_pool3[n*3+0]=px*inv; g_pool3[n*3+1]=py*inv; g_pool3[n*3+2]=pz*inv;
}

// ---------------- per-edge geometry (warp/edge) ----------------
#define GS 992
__global__ void k_geom(const float* __restrict__ x, const int* __restrict__ row,
                       const int* __restrict__ col, const float* __restrict__ attr,
                       const float* __restrict__ cw){
    __shared__ float sm[8][GS];
    int warp = threadIdx.x>>5, lane = threadIdx.x&31;
    int e = blockIdx.x*8 + warp;
    if(e >= NE) return;
    float* s = sm[warp];
    int r = row[e], c = col[e];
    const int oCWR=0,oCWC=14,oXR=28,oXC=70,oAR=112,oAC=336,oM=560,oT=756;
    if(lane < CC){ s[oCWR+lane]=cw[r*CC+lane]; s[oCWC+lane]=cw[c*CC+lane]; }
    for(int i=lane;i<42;i+=32){ s[oXR+i]=x[r*42+i]; s[oXC+i]=x[c*42+i]; }
    for(int i=lane;i<224;i+=32){ s[oAR+i]=attr[r*224+i]; s[oAC+i]=attr[c*224+i]; }
    __syncwarp();
    for(int idx=lane; idx<196; idx+=32){
        int i = idx/14, j = idx - i*14;
        float dx = s[oXR+i*3+0]-s[oXC+j*3+0];
        float dy = s[oXR+i*3+1]-s[oXC+j*3+1];
        float dz = s[oXR+i*3+2]-s[oXC+j*3+2];
        float d = sqrtf(dx*dx+dy*dy+dz*dz);
        s[oM+idx] = d * s[oCWR+i] * s[oCWC+j];
    }
    __syncwarp();
    int b = lane&15, hh = lane>>4;
    {
        float acj[CC];
        #pragma unroll
        for(int j=0;j<CC;j++) acj[j] = s[oAC + j*16 + b];
        #pragma unroll
        for(int i0=0;i0<7;i0++){
            int i = hh*7 + i0;
            float t = 0.f;
            #pragma unroll
            for(int j=0;j<CC;j++) t += s[oM + i*14 + j]*acj[j];
            s[oT + i*16 + b] = t;
        }
    }
    __syncwarp();
    float racc[8] = {0,0,0,0,0,0,0,0};
    {
        float tb[CC];
        #pragma unroll
        for(int i=0;i<CC;i++) tb[i] = s[oT + i*16 + b];
        #pragma unroll
        for(int i=0;i<CC;i++){
            float tv = tb[i];
            #pragma unroll
            for(int q=0;q<8;q++) racc[q] += s[oAR + i*16 + hh*8 + q]*tv;
        }
    }
    float sq = 0.f;
    float* go = &g_radial[(size_t)e*256];
    #pragma unroll
    for(int q=0;q<8;q++){ sq += racc[q]*racc[q]; go[(hh*8+q)*16 + b] = racc[q]; }
    #pragma unroll
    for(int o=16;o>0;o>>=1) sq += __shfl_xor_sync(0xffffffffu, sq, o);
    if(lane==0) g_rinv[e] = 1.f/(sqrtf(sq)+1.f);
}

// ===== tf32 mma.sync GEMM: O[M,128]=epi(A[M,128*?]@W^T+b), M mult of 128 =====
// 256 thr = 8 warps (4M x 2N), warp tile 32x64, m16n8k8 atoms, BK=16 dbl-buf.
// MODE 0: +bias (*rowscale)   1: silu   2: silu + att gate + scatter agg[col]
// GATHER: A row = [h[row] | h[col] | rfeat]  (K=384)
template<int KT, int MODE, bool GATHER>
__global__ void __launch_bounds__(256,2) tmma(
    const float* __restrict__ A, const float* __restrict__ Wg,
    const float* __restrict__ bg, float* __restrict__ O, int tiles,
    const float* __restrict__ rowscale,
    const int* __restrict__ rowi, const int* __restrict__ coli,
    const float* __restrict__ attWg, const float* __restrict__ attbg,
    float* __restrict__ agg, float* __restrict__ cnt,
    const float* __restrict__ hsrc, const float* __restrict__ rfeat)
{
    __shared__ uint32_t sA[2][16][136];
    __shared__ uint32_t sW[2][16][136];
    __shared__ int sRow[128], sCol[128];
    __shared__ float sBias[128], sAtt[128], sDot[2][128];
    const int tid = threadIdx.x, wid = tid>>5, lane = tid&31;
    const int warpM = (wid&3)*32, warpN = (wid>>2)*64;
    const int ee = tid>>1, q = tid&1, kq = q*8;
    const int r4 = lane>>2, c4 = lane&3;
    const int K = KT*16;

    if(tid<128){ sBias[tid]=bg[tid]; if(MODE==2) sAtt[tid]=attWg[tid]; }
    const float attb = (MODE==2)? attbg[0] : 0.f;

    for(int tile=blockIdx.x; tile<tiles; tile+=gridDim.x){
        if(GATHER && tid<128){ sRow[tid]=rowi[tile*128+tid]; sCol[tid]=coli[tile*128+tid]; }
        else if(MODE==2 && tid<128){ sCol[tid]=coli[tile*128+tid]; }
        if(GATHER) __syncthreads();      // sRow needed by ldA(0)

        float4 pa0, pa1, pw0, pw1;
        auto ldA = [&](int kt, float4& v0, float4& v1){
            const int kg = kt*16 + kq;
            const float* p;
            if(!GATHER)            p = &A[(size_t)(tile*128+ee)*K + kg];
            else if(kg < 128)      p = &hsrc[(size_t)sRow[ee]*128 + kg];
            else if(kg < 256)      p = &hsrc[(size_t)sCol[ee]*128 + (kg-128)];
            else                   p = &rfeat[(size_t)(tile*128+ee)*128 + (kg-256)];
            v0 = *(const float4*)p; v1 = *(const float4*)(p+4);
        };
        auto ldW = [&](int kt, float4& v0, float4& v1){
            const float* p = &Wg[(size_t)ee*K + kt*16 + kq];
            v0 = *(const float4*)p; v1 = *(const float4*)(p+4);
        };
        auto sts = [&](int buf, float4 a0, float4 a1, float4 w0, float4 w1){
            sA[buf][kq+0][ee]=tf32c(a0.x); sA[buf][kq+1][ee]=tf32c(a0.y);
            sA[buf][kq+2][ee]=tf32c(a0.z); sA[buf][kq+3][ee]=tf32c(a0.w);
            sA[buf][kq+4][ee]=tf32c(a1.x); sA[buf][kq+5][ee]=tf32c(a1.y);
            sA[buf][kq+6][ee]=tf32c(a1.z); sA[buf][kq+7][ee]=tf32c(a1.w);
            sW[buf][kq+0][ee]=tf32c(w0.x); sW[buf][kq+1][ee]=tf32c(w0.y);
            sW[buf][kq+2][ee]=tf32c(w0.z); sW[buf][kq+3][ee]=tf32c(w0.w);
            sW[buf][kq+4][ee]=tf32c(w1.x); sW[buf][kq+5][ee]=tf32c(w1.y);
            sW[buf][kq+6][ee]=tf32c(w1.z); sW[buf][kq+7][ee]=tf32c(w1.w);
        };

        float acc[2][8][4];
        #pragma unroll
        for(int am=0;am<2;am++)
            #pragma unroll
            for(int bn=0;bn<8;bn++)
                #pragma unroll
                for(int i=0;i<4;i++) acc[am][bn][i]=0.f;

        ldA(0, pa0, pa1); ldW(0, pw0, pw1);
        sts(0, pa0, pa1, pw0, pw1);
        __syncthreads();

        #pragma unroll 1
        for(int kt=0; kt<KT; kt++){
            if(kt+1 < KT){ ldA(kt+1, pa0, pa1); ldW(kt+1, pw0, pw1); }
            const int buf = kt&1;
            #pragma unroll
            for(int ks=0; ks<2; ks++){
                const int k0 = ks*8;
                uint32_t bf[8][2];
                #pragma unroll
                for(int bn=0;bn<8;bn++){
                    int n = warpN + bn*8 + r4;
                    bf[bn][0] = sW[buf][k0+c4  ][n];
                    bf[bn][1] = sW[buf][k0+c4+4][n];
                }
                #pragma unroll
                for(int am=0;am<2;am++){
                    int m0 = warpM + am*16 + r4;
                    uint32_t af[4];
                    af[0] = sA[buf][k0+c4  ][m0];
                    af[1] = sA[buf][k0+c4  ][m0+8];
                    af[2] = sA[buf][k0+c4+4][m0];
                    af[3] = sA[buf][k0+c4+4][m0+8];
                    #pragma unroll
                    for(int bn=0;bn<8;bn++) mma8(acc[am][bn], af, bf[bn]);
                }
            }
            if(kt+1 < KT) sts((kt+1)&1, pa0, pa1, pw0, pw1);
            __syncthreads();
        }

        // ---- epilogue: bias (+silu) in place ----
        #pragma unroll
        for(int am=0;am<2;am++)
            #pragma unroll
            for(int bn=0;bn<8;bn++){
                int c0 = warpN + bn*8 + c4*2;
                float b0=sBias[c0], b1=sBias[c0+1];
                float* a = acc[am][bn];
                a[0]+=b0; a[1]+=b1; a[2]+=b0; a[3]+=b1;
                if(MODE>=1){ a[0]=silu_(a[0]); a[1]=silu_(a[1]);
                             a[2]=silu_(a[2]); a[3]=silu_(a[3]); }
            }
        if(MODE==0 && rowscale){
            #pragma unroll
            for(int am=0;am<2;am++){
                float rs0 = rowscale[tile*128 + warpM + am*16 + r4];
                float rs1 = rowscale[tile*128 + warpM + am*16 + r4 + 8];
                #pragma unroll
                for(int bn=0;bn<8;bn++){
                    float* a = acc[am][bn];
                    a[0]*=rs0; a[1]*=rs0; a[2]*=rs1; a[3]*=rs1;
                }
            }
        }
        if(MODE==2){
            float dot[2][2] = {{0.f,0.f},{0.f,0.f}};
            #pragma unroll
            for(int am=0;am<2;am++)
                #pragma unroll
                for(int bn=0;bn<8;bn++){
                    int c0 = warpN + bn*8 + c4*2;
                    float w0=sAtt[c0], w1=sAtt[c0+1];
                    dot[am][0] += acc[am][bn][0]*w0 + acc[am][bn][1]*w1;
                    dot[am][1] += acc[am][bn][2]*w0 + acc[am][bn][3]*w1;
                }
            #pragma unroll
            for(int am=0;am<2;am++)
                #pragma unroll
                for(int hf=0;hf<2;hf++){
                    dot[am][hf] += __shfl_xor_sync(0xffffffffu, dot[am][hf], 1);
                    dot[am][hf] += __shfl_xor_sync(0xffffffffu, dot[am][hf], 2);
                }
            if(c4==0){
                #pragma unroll
                for(int am=0;am<2;am++){
                    sDot[wid>>2][warpM+am*16+r4]   = dot[am][0];
                    sDot[wid>>2][warpM+am*16+r4+8] = dot[am][1];
                }
            }
            __syncthreads();
            #pragma unroll
            for(int am=0;am<2;am++)
                #pragma unroll
                for(int hf=0;hf<2;hf++){
                    int rl = warpM + am*16 + r4 + hf*8;
                    float g = sigm(sDot[0][rl] + sDot[1][rl] + attb);
                    #pragma unroll
                    for(int bn=0;bn<8;bn++){
                        acc[am][bn][hf*2]   *= g;
                        acc[am][bn][hf*2+1] *= g;
                    }
                }
        }
        // ---- store (+ scatter) ----
        #pragma unroll
        for(int am=0;am<2;am++)
            #pragma unroll
            for(int hf=0;hf<2;hf++){
                int rl = warpM + am*16 + r4 + hf*8;
                int rg = tile*128 + rl;
                float* op = &O[(size_t)rg*128];
                #pragma unroll
                for(int bn=0;bn<8;bn++){
                    int c0 = warpN + bn*8 + c4*2;
                    *(float2*)(op+c0) =
                        make_float2(acc[am][bn][hf*2], acc[am][bn][hf*2+1]);
                }
                if(MODE==2){
                    int cc = sCol[rl];
                    float* ag = &agg[(size_t)cc*128];
                    #pragma unroll
                    for(int bn=0;bn<8;bn++){
                        int c0 = warpN + bn*8 + c4*2;
                        atomicAdd(ag+c0,   acc[am][bn][hf*2]);
                        atomicAdd(ag+c0+1, acc[am][bn][hf*2+1]);
                    }
                    if(warpN==0 && c4==0) atomicAdd(&cnt[cc], 1.f);
                }
            }
        __syncthreads();
    }
}

// ======= SIMT GEMM (node MLP, small M with bounds) =======
template<int K, int MODE>
__global__ void __launch_bounds__(256,2) kgemm(
    const float* __restrict__ A, const float* __restrict__ Wg,
    const float* __restrict__ bg, float* __restrict__ O, int M, int tiles)
{
    __shared__ float sA[2][16][128];
    __shared__ float sW[2][16][128];
    const int tid = threadIdx.x, tx = tid&15, ty = tid>>4;
    const int ee = tid>>1, q = tid&1, kq = q*8;
    float bb[8];
    #pragma unroll
    for(int i=0;i<8;i++) bb[i]=bg[tx*8+i];

    for(int tile=blockIdx.x; tile<tiles; tile+=gridDim.x){
        float4 pa0, pa1, pw0, pw1;
        auto ldA = [&](int kt, float4& v0, float4& v1){
            int rg = tile*128 + ee;
            if(rg < M){
                const float* p = &A[(size_t)rg*K + kt*16 + kq];
                v0 = *(const float4*)p; v1 = *(const float4*)(p+4);
            } else { v0=v1=make_float4(0,0,0,0); }
        };
        auto ldW = [&](int kt, float4& v0, float4& v1){
            const float* p = &Wg[(size_t)ee*K + kt*16 + kq];
            v0 = *(const float4*)p; v1 = *(const float4*)(p+4);
        };
        auto sts = [&](int buf, float4 a0, float4 a1, float4 w0, float4 w1){
            sA[buf][kq+0][ee]=a0.x; sA[buf][kq+1][ee]=a0.y;
            sA[buf][kq+2][ee]=a0.z; sA[buf][kq+3][ee]=a0.w;
            sA[buf][kq+4][ee]=a1.x; sA[buf][kq+5][ee]=a1.y;
            sA[buf][kq+6][ee]=a1.z; sA[buf][kq+7][ee]=a1.w;
            sW[buf][kq+0][ee]=w0.x; sW[buf][kq+1][ee]=w0.y;
            sW[buf][kq+2][ee]=w0.z; sW[buf][kq+3][ee]=w0.w;
            sW[buf][kq+4][ee]=w1.x; sW[buf][kq+5][ee]=w1.y;
            sW[buf][kq+6][ee]=w1.z; sW[buf][kq+7][ee]=w1.w;
        };
        ldA(0, pa0, pa1); ldW(0, pw0, pw1);
        sts(0, pa0, pa1, pw0, pw1);
        __syncthreads();
        float acc[8][8];
        #pragma unroll
        for(int j=0;j<8;j++)
            #pragma unroll
            for(int i=0;i<8;i++) acc[j][i]=0.f;
        const int KT = K/16;
        #pragma unroll 1
        for(int kt=0; kt<KT; kt++){
            if(kt+1 < KT){ ldA(kt+1, pa0, pa1); ldW(kt+1, pw0, pw1); }
            const int buf = kt&1;
            #pragma unroll
            for(int k=0;k<16;k++){
                float4 a0 = *(const float4*)&sA[buf][k][ty*8];
                float4 a1 = *(const float4*)&sA[buf][k][ty*8+4];
                float4 w0 = *(const float4*)&sW[buf][k][tx*8];
                float4 w1 = *(const float4*)&sW[buf][k][tx*8+4];
                float av[8]={a0.x,a0.y,a0.z,a0.w,a1.x,a1.y,a1.z,a1.w};
                float wv[8]={w0.x,w0.y,w0.z,w0.w,w1.x,w1.y,w1.z,w1.w};
                #pragma unroll
                for(int j=0;j<8;j++)
                    #pragma unroll
                    for(int i=0;i<8;i++) acc[j][i] += av[j]*wv[i];
            }
            if(kt+1 < KT) sts((kt+1)&1, pa0, pa1, pw0, pw1);
            __syncthreads();
        }
        #pragma unroll
        for(int j=0;j<8;j++){
            int rg = tile*128 + ty*8 + j;
            if(rg >= M) continue;
            float v[8];
            #pragma unroll
            for(int i=0;i<8;i++){ v[i]=acc[j][i]+bb[i]; if(MODE>=1) v[i]=silu_(v[i]); }
            *(float4*)&O[(size_t)rg*128+tx*8]   = make_float4(v[0],v[1],v[2],v[3]);
            *(float4*)&O[(size_t)rg*128+tx*8+4] = make_float4(v[4],v[5],v[6],v[7]);
        }
    }
}

// ---------------- coord path ----------------
__global__ void __launch_bounds__(256) k_coord(const float* __restrict__ x,
        const int* __restrict__ row, const int* __restrict__ col,
        const float* __restrict__ c2W, const float* __restrict__ c2b){
    __shared__ float sc2[CC*128];
    __shared__ float scb[CC];
    int tid=threadIdx.x, warp=tid>>5, lane=tid&31;
    for(int i=tid;i<CC*128;i+=256) sc2[i]=c2W[i];
    if(tid<CC) scb[tid]=c2b[tid];
    __syncthreads();
    for(int e = blockIdx.x*8+warp; e < NE; e += gridDim.x*8){
        int r=row[e], c=col[e];
        float4 hv = *(const float4*)&g_ef1[(size_t)e*128 + lane*4];
        float p[CC];
        #pragma unroll
        for(int o=0;o<CC;o++){
            const float* w=&sc2[o*128+lane*4];
            p[o]=hv.x*w[0]+hv.y*w[1]+hv.z*w[2]+hv.w*w[3];
        }
        #pragma unroll
        for(int o=0;o<CC;o++){
            #pragma unroll
            for(int s=16;s>0;s>>=1) p[o]+=__shfl_xor_sync(0xffffffffu,p[o],s);
        }
        int cs = (int)(g_csum[r]+0.5f);
        int w = 15 - cs;
        if(lane < CC){
            int end = min(lane + w - 1, CC-1);
            float s = 0.f;
            #pragma unroll
            for(int o=0;o<CC;o++){
                float v = p[o]+scb[o];
                if(o>=lane && o<=end) s += v;
            }
            float pooled = s/(float)w;
            float px=g_pool3[c*3], py=g_pool3[c*3+1], pz=g_pool3[c*3+2];
            const float* xp = &x[((size_t)r*CC+lane)*3];
            atomicAdd(&g_xsum[(r*CC+lane)*3+0], (xp[0]-px)*pooled);
            atomicAdd(&g_xsum[(r*CC+lane)*3+1], (xp[1]-py)*pooled);
            atomicAdd(&g_xsum[(r*CC+lane)*3+2], (xp[2]-pz)*pooled);
        }
        if(lane==0) atomicAdd(&g_cnt_row[r], 1.f);
    }
}

// ---------------- node concat [h | agg/cnt] ----------------
__global__ void k_nodecat(const float* __restrict__ h){
    int idx = blockIdx.x*blockDim.x + threadIdx.x;
    if(idx >= NN*64) return;
    int n = idx>>6, g = idx&63;
    float4 v;
    if(g<32) v = *(const float4*)&h[(size_t)n*128 + g*4];
    else{
        float inv = 1.f/fmaxf(g_cnt_col[n],1.f);
        const float* a = &g_aggsum[(size_t)n*128 + (g-32)*4];
        v = make_float4(a[0]*inv,a[1]*inv,a[2]*inv,a[3]*inv);
    }
    *(float4*)&g_ncat[(size_t)n*256 + g*4] = v;
}

// ---------------- x_out ----------------
__global__ void k_xout(const float* __restrict__ x, float* __restrict__ xout){
    int idx = blockIdx.x*blockDim.x + threadIdx.x;
    if(idx >= NN*CC*3) return;
    int n = idx/(CC*3);
    xout[idx] = x[idx] + g_xsum[idx]/fmaxf(g_cnt_row[n],1.f);
}

// ---------------- layernorm ----------------
__global__ void k_ln(const float* __restrict__ h, const float* __restrict__ lng,
                     const float* __restrict__ lnb, float* __restrict__ out){
    __shared__ float red[8];
    int n = blockIdx.x, t = threadIdx.x;
    float y = h[(size_t)n*128+t] + g_ef[(size_t)n*128+t];
    float s = y;
    #pragma unroll
    for(int o=16;o>0;o>>=1) s += __shfl_xor_sync(0xffffffffu, s, o);
    if((t&31)==0) red[t>>5] = s;
    __syncthreads();
    float mu = (red[0]+red[1]+red[2]+red[3]) * (1.f/128.f);
    float d = y - mu;
    float v = d*d;
    #pragma unroll
    for(int o=16;o>0;o>>=1) v += __shfl_xor_sync(0xffffffffu, v, o);
    if((t&31)==0) red[4+(t>>5)] = v;
    __syncthreads();
    float var = (red[4]+red[5]+red[6]+red[7]) * (1.f/128.f);
    out[(size_t)n*128+t] = d*rsqrtf(var+1e-5f)*lng[t] + lnb[t];
}

// ======================= host launcher =======================
extern "C" void kernel_launch(void* const* d_in, const int* in_sizes, int n_in,
                              void* d_out, int out_size){
    const float* h    = (const float*)d_in[0];
    const float* x    = (const float*)d_in[1];
    const int*   row  = (const int*)  d_in[2];
    const int*   col  = (const int*)  d_in[3];
    const float* attr = (const float*)d_in[4];
    const float* cw   = (const float*)d_in[5];
    const float* radW = (const float*)d_in[6];  const float* radB = (const float*)d_in[7];
    const float* e1W  = (const float*)d_in[8];  const float* e1B  = (const float*)d_in[9];
    const float* e2W  = (const float*)d_in[10]; const float* e2B  = (const float*)d_in[11];
    const float* attW = (const float*)d_in[12]; const float* attB = (const float*)d_in[13];
    const float* c1W  = (const float*)d_in[14]; const float* c1B  = (const float*)d_in[15];
    const float* c2W  = (const float*)d_in[16]; const float* c2B  = (const float*)d_in[17];
    const float* n1W  = (const float*)d_in[18]; const float* n1B  = (const float*)d_in[19];
    const float* n2W  = (const float*)d_in[20]; const float* n2B  = (const float*)d_in[21];
    const float* lng  = (const float*)d_in[22]; const float* lnb  = (const float*)d_in[23];
    float* outH = (float*)d_out;
    float* outX = outH + (size_t)NN*128;

    void *p_radial,*p_rfeat,*p_ef1,*p_ef,*p_rinv,*p_ncat,*p_agg,*p_cntc;
    cudaGetSymbolAddress(&p_radial, g_radial);
    cudaGetSymbolAddress(&p_rfeat,  g_rfeat);
    cudaGetSymbolAddress(&p_ef1,    g_ef1);
    cudaGetSymbolAddress(&p_ef,     g_ef);
    cudaGetSymbolAddress(&p_rinv,   g_rinv);
    cudaGetSymbolAddress(&p_ncat,   g_ncat);
    cudaGetSymbolAddress(&p_agg,    g_aggsum);
    cudaGetSymbolAddress(&p_cntc,   g_cnt_col);

    const int ZT = NN*128 + NN + NN*CC*3 + NN;
    k_zero<<<(ZT+255)/256, 256>>>();
    k_prep<<<(NN+255)/256, 256>>>(x, cw);
    k_geom<<<NE/8, 256>>>(x, row, col, attr, cw);

    const int TB = 304;   // persistent, 2 CTAs/SM
    // rfeat = (radial @ radW^T + b) * rinv
    tmma<16,0,false><<<TB,256>>>((const float*)p_radial, radW, radB,
        (float*)p_rfeat, TE128, (const float*)p_rinv, 0,0,0,0,0,0, 0,0);
    // ef1 = silu([h_r|h_c|rfeat] @ e1^T + b)
    tmma<24,1,true><<<TB,256>>>(0, e1W, e1B,
        (float*)p_ef1, TE128, 0, row, col, 0,0,0,0, h, (const float*)p_rfeat);
    // ef = silu(ef1 @ e2^T + b) * sigmoid(att); scatter agg[col]
    tmma<8,2,false><<<TB,256>>>((const float*)p_ef1, e2W, e2B,
        (float*)p_ef, TE128, 0, 0, col, attW, attB,
        (float*)p_agg, (float*)p_cntc, 0,0);
    // hid = silu(ef @ c1^T + b)
    tmma<8,1,false><<<TB,256>>>((const float*)p_ef, c1W, c1B,
        (float*)p_ef1, TE128, 0, 0,0,0,0,0,0, 0,0);
    // coord path (reads hid in g_ef1)
    k_coord<<<1216, 256>>>(x, row, col, c2W, c2B);
    // node path (SIMT fp32)
    k_nodecat<<<(NN*64+255)/256, 256>>>(h);
    k_xout<<<(NN*CC*3+255)/256, 256>>>(x, outX);
    kgemm<256,1><<<304,256>>>((const float*)p_ncat, n1W, n1B, (float*)p_rfeat, NN, TN128);
    kgemm<128,0><<<304,256>>>((const float*)p_rfeat, n2W, n2B, (float*)p_ef, NN, TN128);
    k_ln<<<NN, 128>>>(h, lng, lnb, outH);
}

// round 6
// speedup vs baseline: 4.5249x; 1.1910x over previous
#include <cuda_runtime.h>
#include <cuda_bf16.h>
#include <math.h>
#include <stdint.h>

#define NN 20000
#define NE 320000
#define CC 14
#define TE128 (NE/128)              // 2500
#define TN128 ((NN+127)/128)        // 157

// ---------------- scratch ----------------
// edge buffers used as bf16x2-packed (half the declared bytes used)
__device__ float g_radial[(size_t)NE*128];  // bf16 [E][256]
__device__ float g_rfeat[(size_t)NE*128];   // bf16 [E][128] edge; later fp32 n1 out (node)
__device__ float g_ef1[(size_t)NE*64];      // bf16 [E][128]: e1 out, later c1 hidden
__device__ float g_ef[(size_t)NE*128];      // bf16 [E][128] edge; later fp32 n2 out (node)
__device__ float g_rinv[NE];
__device__ float g_csum[NN];
__device__ float g_pool3[NN*3];
__device__ float g_aggsum[(size_t)NN*128];
__device__ float g_cnt_col[NN];
__device__ float g_xsum[NN*CC*3];
__device__ float g_cnt_row[NN];
__device__ float g_ncat[(size_t)NN*256];

__device__ __forceinline__ float sigm(float v){ return 1.f/(1.f+__expf(-v)); }
__device__ __forceinline__ float silu_(float v){ return v*sigm(v); }
__device__ __forceinline__ uint32_t pk2(float lo, float hi){
    __nv_bfloat162 t = __floats2bfloat162_rn(lo, hi);
    return *(uint32_t*)&t;
}
__device__ __forceinline__ void mma16(float* c, const uint32_t* a, const uint32_t* b){
    asm volatile("mma.sync.aligned.m16n8k16.row.col.f32.bf16.bf16.f32 "
        "{%0,%1,%2,%3}, {%4,%5,%6,%7}, {%8,%9}, {%0,%1,%2,%3};"
        : "+f"(c[0]),"+f"(c[1]),"+f"(c[2]),"+f"(c[3])
        : "r"(a[0]),"r"(a[1]),"r"(a[2]),"r"(a[3]), "r"(b[0]),"r"(b[1]));
}

// ---------------- zero accumulators ----------------
__global__ void k_zero(){
    int i = blockIdx.x*blockDim.x + threadIdx.x;
    const int A = NN*128, B = A+NN, D = B+NN*CC*3, T = D+NN;
    if(i >= T) return;
    if(i < A) g_aggsum[i]=0.f;
    else if(i < B) g_cnt_col[i-A]=0.f;
    else if(i < D) g_xsum[i-B]=0.f;
    else g_cnt_row[i-D]=0.f;
}

// ---------------- node prep ----------------
__global__ void k_prep(const float* __restrict__ x, const float* __restrict__ cw){
    int n = blockIdx.x*blockDim.x + threadIdx.x;
    if(n >= NN) return;
    float cnt=0.f, px=0.f, py=0.f, pz=0.f;
    #pragma unroll
    for(int i=0;i<CC;i++){
        float w = cw[n*CC+i];
        if(w != 0.f){
            cnt += 1.f;
            const float* xp = &x[(n*CC+i)*3];
            px += xp[0]; py += xp[1]; pz += xp[2];
        }
    }
    g_csum[n] = cnt;
    float inv = 1.f/cnt;
    g_pool3[n*3+0]=px*inv; g_pool3[n*3+1]=py*inv; g_pool3[n*3+2]=pz*inv;
}

// ---------------- per-edge geometry (warp/edge), bf16 radial out ------------
#define GS 992
__global__ void k_geom(const float* __restrict__ x, const int* __restrict__ row,
                       const int* __restrict__ col, const float* __restrict__ attr,
                       const float* __restrict__ cw){
    __shared__ float sm[8][GS];
    int warp = threadIdx.x>>5, lane = threadIdx.x&31;
    int e = blockIdx.x*8 + warp;
    if(e >= NE) return;
    float* s = sm[warp];
    int r = row[e], c = col[e];
    const int oCWR=0,oCWC=14,oXR=28,oXC=70,oAR=112,oAC=336,oM=560,oT=756;
    if(lane < CC){ s[oCWR+lane]=cw[r*CC+lane]; s[oCWC+lane]=cw[c*CC+lane]; }
    for(int i=lane;i<42;i+=32){ s[oXR+i]=x[r*42+i]; s[oXC+i]=x[c*42+i]; }
    for(int i=lane;i<224;i+=32){ s[oAR+i]=attr[r*224+i]; s[oAC+i]=attr[c*224+i]; }
    __syncwarp();
    for(int idx=lane; idx<196; idx+=32){
        int i = idx/14, j = idx - i*14;
        float dx = s[oXR+i*3+0]-s[oXC+j*3+0];
        float dy = s[oXR+i*3+1]-s[oXC+j*3+1];
        float dz = s[oXR+i*3+2]-s[oXC+j*3+2];
        float d = sqrtf(dx*dx+dy*dy+dz*dz);
        s[oM+idx] = d * s[oCWR+i] * s[oCWC+j];
    }
    __syncwarp();
    int b = lane&15, hh = lane>>4;
    {
        float acj[CC];
        #pragma unroll
        for(int j=0;j<CC;j++) acj[j] = s[oAC + j*16 + b];
        #pragma unroll
        for(int i0=0;i0<7;i0++){
            int i = hh*7 + i0;
            float t = 0.f;
            #pragma unroll
            for(int j=0;j<CC;j++) t += s[oM + i*14 + j]*acj[j];
            s[oT + i*16 + b] = t;
        }
    }
    __syncwarp();
    float racc[8] = {0,0,0,0,0,0,0,0};
    {
        float tb[CC];
        #pragma unroll
        for(int i=0;i<CC;i++) tb[i] = s[oT + i*16 + b];
        #pragma unroll
        for(int i=0;i<CC;i++){
            float tv = tb[i];
            #pragma unroll
            for(int q=0;q<8;q++) racc[q] += s[oAR + i*16 + hh*8 + q]*tv;
        }
    }
    float sq = 0.f;
    __nv_bfloat16* go = (__nv_bfloat16*)g_radial + (size_t)e*256;
    #pragma unroll
    for(int q=0;q<8;q++){ sq += racc[q]*racc[q]; go[(hh*8+q)*16 + b] = __float2bfloat16(racc[q]); }
    #pragma unroll
    for(int o=16;o>0;o>>=1) sq += __shfl_xor_sync(0xffffffffu, sq, o);
    if(lane==0) g_rinv[e] = 1.f/(sqrtf(sq)+1.f);
}

// ===== bf16 mma GEMM: O[M,128]=epi(A[M,K]@W[128,K]^T+b), M mult of 128 =====
// 256 thr = 8 warps (4M x 2N), warp tile 32x64, m16n8k16 atoms, BK=16 dbl-buf.
// A stored as bf16x2-packed pairs (uint32 per 2 k). Weights fp32 (converted at STS).
// MODE 0: +bias (*rowscale)   1: silu   2: silu + att gate + scatter agg[col]
// GATHER: A row = [h[row] | h[col] | rfeat]  (K=384, h fp32, rfeat bf16-packed)
template<int KT, int MODE, bool GATHER>
__global__ void __launch_bounds__(256,2) tmma(
    const uint32_t* __restrict__ Abf, const float* __restrict__ Wg,
    const float* __restrict__ bg, uint32_t* __restrict__ Obf, int tiles,
    const float* __restrict__ rowscale,
    const int* __restrict__ rowi, const int* __restrict__ coli,
    const float* __restrict__ attWg, const float* __restrict__ attbg,
    float* __restrict__ agg, float* __restrict__ cnt,
    const float* __restrict__ hsrc, const uint32_t* __restrict__ rfbf)
{
    __shared__ uint32_t sA[2][8][136];   // [kpair][m]
    __shared__ uint32_t sW[2][8][136];   // [kpair][n]
    __shared__ int sRow[128], sCol[128];
    __shared__ float sBias[128], sAtt[128], sDot[2][128];
    const int tid = threadIdx.x, wid = tid>>5, lane = tid&31;
    const int warpM = (wid&3)*32, warpN = (wid>>2)*64;
    const int ee = tid>>1, q = tid&1;
    const int r4 = lane>>2, c4 = lane&3;
    const int K = KT*16, KP = K/2;

    if(tid<128){ sBias[tid]=bg[tid]; if(MODE==2) sAtt[tid]=attWg[tid]; }
    const float attb = (MODE==2)? attbg[0] : 0.f;

    for(int tile=blockIdx.x; tile<tiles; tile+=gridDim.x){
        if(GATHER && tid<128){ sRow[tid]=rowi[tile*128+tid]; sCol[tid]=coli[tile*128+tid]; }
        else if(MODE==2 && tid<128){ sCol[tid]=coli[tile*128+tid]; }
        if(GATHER) __syncthreads();

        uint32_t pa[4], pw[4];
        // loaders: thread covers row ee, k-pairs q*4..q*4+3 of the BK=16 tile
        auto ldA = [&](int kt, uint32_t* v){
            if(!GATHER){
                const uint4 u = *(const uint4*)&Abf[(size_t)(tile*128+ee)*KP + kt*8 + q*4];
                v[0]=u.x; v[1]=u.y; v[2]=u.z; v[3]=u.w;
            } else {
                const int kg = kt*16 + q*8;
                if(kg < 256){
                    const float* p = (kg<128) ? &hsrc[(size_t)sRow[ee]*128 + kg]
                                              : &hsrc[(size_t)sCol[ee]*128 + (kg-128)];
                    float4 a = *(const float4*)p;
                    float4 b = *(const float4*)(p+4);
                    v[0]=pk2(a.x,a.y); v[1]=pk2(a.z,a.w);
                    v[2]=pk2(b.x,b.y); v[3]=pk2(b.z,b.w);
                } else {
                    const uint4 u = *(const uint4*)&rfbf[(size_t)(tile*128+ee)*64 + (kg-256)/2];
                    v[0]=u.x; v[1]=u.y; v[2]=u.z; v[3]=u.w;
                }
            }
        };
        auto ldW = [&](int kt, uint32_t* v){
            const float* p = &Wg[(size_t)ee*K + kt*16 + q*8];
            float4 a = *(const float4*)p;
            float4 b = *(const float4*)(p+4);
            v[0]=pk2(a.x,a.y); v[1]=pk2(a.z,a.w);
            v[2]=pk2(b.x,b.y); v[3]=pk2(b.z,b.w);
        };
        auto sts = [&](int buf, const uint32_t* va, const uint32_t* vw){
            #pragma unroll
            for(int j=0;j<4;j++){
                sA[buf][q*4+j][ee] = va[j];
                sW[buf][q*4+j][ee] = vw[j];
            }
        };

        float acc[2][8][4];
        #pragma unroll
        for(int am=0;am<2;am++)
            #pragma unroll
            for(int bn=0;bn<8;bn++)
                #pragma unroll
                for(int i=0;i<4;i++) acc[am][bn][i]=0.f;

        ldA(0, pa); ldW(0, pw);
        sts(0, pa, pw);
        __syncthreads();

        #pragma unroll 1
        for(int kt=0; kt<KT; kt++){
            if(kt+1 < KT){ ldA(kt+1, pa); ldW(kt+1, pw); }
            const int buf = kt&1;
            uint32_t bf[8][2];
            #pragma unroll
            for(int bn=0;bn<8;bn++){
                int n = warpN + bn*8 + r4;
                bf[bn][0] = sW[buf][c4  ][n];
                bf[bn][1] = sW[buf][c4+4][n];
            }
            #pragma unroll
            for(int am=0;am<2;am++){
                int m0 = warpM + am*16 + r4;
                uint32_t af[4];
                af[0] = sA[buf][c4  ][m0];
                af[1] = sA[buf][c4  ][m0+8];
                af[2] = sA[buf][c4+4][m0];
                af[3] = sA[buf][c4+4][m0+8];
                #pragma unroll
                for(int bn=0;bn<8;bn++) mma16(acc[am][bn], af, bf[bn]);
            }
            if(kt+1 < KT) sts((kt+1)&1, pa, pw);
            __syncthreads();
        }

        // ---- epilogue: bias (+silu) ----
        #pragma unroll
        for(int am=0;am<2;am++)
            #pragma unroll
            for(int bn=0;bn<8;bn++){
                int c0 = warpN + bn*8 + c4*2;
                float b0=sBias[c0], b1=sBias[c0+1];
                float* a = acc[am][bn];
                a[0]+=b0; a[1]+=b1; a[2]+=b0; a[3]+=b1;
                if(MODE>=1){ a[0]=silu_(a[0]); a[1]=silu_(a[1]);
                             a[2]=silu_(a[2]); a[3]=silu_(a[3]); }
            }
        if(MODE==0 && rowscale){
            #pragma unroll
            for(int am=0;am<2;am++){
                float rs0 = rowscale[tile*128 + warpM + am*16 + r4];
                float rs1 = rowscale[tile*128 + warpM + am*16 + r4 + 8];
                #pragma unroll
                for(int bn=0;bn<8;bn++){
                    float* a = acc[am][bn];
                    a[0]*=rs0; a[1]*=rs0; a[2]*=rs1; a[3]*=rs1;
                }
            }
        }
        if(MODE==2){
            float dot[2][2] = {{0.f,0.f},{0.f,0.f}};
            #pragma unroll
            for(int am=0;am<2;am++)
                #pragma unroll
                for(int bn=0;bn<8;bn++){
                    int c0 = warpN + bn*8 + c4*2;
                    float w0=sAtt[c0], w1=sAtt[c0+1];
                    dot[am][0] += acc[am][bn][0]*w0 + acc[am][bn][1]*w1;
                    dot[am][1] += acc[am][bn][2]*w0 + acc[am][bn][3]*w1;
                }
            #pragma unroll
            for(int am=0;am<2;am++)
                #pragma unroll
                for(int hf=0;hf<2;hf++){
                    dot[am][hf] += __shfl_xor_sync(0xffffffffu, dot[am][hf], 1);
                    dot[am][hf] += __shfl_xor_sync(0xffffffffu, dot[am][hf], 2);
                }
            if(c4==0){
                #pragma unroll
                for(int am=0;am<2;am++){
                    sDot[wid>>2][warpM+am*16+r4]   = dot[am][0];
                    sDot[wid>>2][warpM+am*16+r4+8] = dot[am][1];
                }
            }
            __syncthreads();
            #pragma unroll
            for(int am=0;am<2;am++)
                #pragma unroll
                for(int hf=0;hf<2;hf++){
                    int rl = warpM + am*16 + r4 + hf*8;
                    float g = sigm(sDot[0][rl] + sDot[1][rl] + attb);
                    #pragma unroll
                    for(int bn=0;bn<8;bn++){
                        acc[am][bn][hf*2]   *= g;
                        acc[am][bn][hf*2+1] *= g;
                    }
                }
        }
        // ---- store bf16-packed (+ fp32 scatter) ----
        #pragma unroll
        for(int am=0;am<2;am++)
            #pragma unroll
            for(int hf=0;hf<2;hf++){
                int rl = warpM + am*16 + r4 + hf*8;
                int rg = tile*128 + rl;
                uint32_t* op = &Obf[(size_t)rg*64];
                #pragma unroll
                for(int bn=0;bn<8;bn++){
                    int c0 = warpN + bn*8 + c4*2;
                    op[c0>>1] = pk2(acc[am][bn][hf*2], acc[am][bn][hf*2+1]);
                }
                if(MODE==2){
                    int cc = sCol[rl];
                    float* ag = &agg[(size_t)cc*128];
                    #pragma unroll
                    for(int bn=0;bn<8;bn++){
                        int c0 = warpN + bn*8 + c4*2;
                        atomicAdd(ag+c0,   acc[am][bn][hf*2]);
                        atomicAdd(ag+c0+1, acc[am][bn][hf*2+1]);
                    }
                    if(warpN==0 && c4==0) atomicAdd(&cnt[cc], 1.f);
                }
            }
        __syncthreads();
    }
}

// ======= SIMT GEMM (node MLP, fp32, small M with bounds) =======
template<int K, int MODE>
__global__ void __launch_bounds__(256,2) kgemm(
    const float* __restrict__ A, const float* __restrict__ Wg,
    const float* __restrict__ bg, float* __restrict__ O, int M, int tiles)
{
    __shared__ float sA[2][16][128];
    __shared__ float sW[2][16][128];
    const int tid = threadIdx.x, tx = tid&15, ty = tid>>4;
    const int ee = tid>>1, q = tid&1, kq = q*8;
    float bb[8];
    #pragma unroll
    for(int i=0;i<8;i++) bb[i]=bg[tx*8+i];

    for(int tile=blockIdx.x; tile<tiles; tile+=gridDim.x){
        float4 pa0, pa1, pw0, pw1;
        auto ldA = [&](int kt, float4& v0, float4& v1){
            int rg = tile*128 + ee;
            if(rg < M){
                const float* p = &A[(size_t)rg*K + kt*16 + kq];
                v0 = *(const float4*)p; v1 = *(const float4*)(p+4);
            } else { v0=v1=make_float4(0,0,0,0); }
        };
        auto ldW = [&](int kt, float4& v0, float4& v1){
            const float* p = &Wg[(size_t)ee*K + kt*16 + kq];
            v0 = *(const float4*)p; v1 = *(const float4*)(p+4);
        };
        auto sts = [&](int buf, float4 a0, float4 a1, float4 w0, float4 w1){
            sA[buf][kq+0][ee]=a0.x; sA[buf][kq+1][ee]=a0.y;
            sA[buf][kq+2][ee]=a0.z; sA[buf][kq+3][ee]=a0.w;
            sA[buf][kq+4][ee]=a1.x; sA[buf][kq+5][ee]=a1.y;
            sA[buf][kq+6][ee]=a1.z; sA[buf][kq+7][ee]=a1.w;
            sW[buf][kq+0][ee]=w0.x; sW[buf][kq+1][ee]=w0.y;
            sW[buf][kq+2][ee]=w0.z; sW[buf][kq+3][ee]=w0.w;
            sW[buf][kq+4][ee]=w1.x; sW[buf][kq+5][ee]=w1.y;
            sW[buf][kq+6][ee]=w1.z; sW[buf][kq+7][ee]=w1.w;
        };
        ldA(0, pa0, pa1); ldW(0, pw0, pw1);
        sts(0, pa0, pa1, pw0, pw1);
        __syncthreads();
        float acc[8][8];
        #pragma unroll
        for(int j=0;j<8;j++)
            #pragma unroll
            for(int i=0;i<8;i++) acc[j][i]=0.f;
        const int KT = K/16;
        #pragma unroll 1
        for(int kt=0; kt<KT; kt++){
            if(kt+1 < KT){ ldA(kt+1, pa0, pa1); ldW(kt+1, pw0, pw1); }
            const int buf = kt&1;
            #pragma unroll
            for(int k=0;k<16;k++){
                float4 a0 = *(const float4*)&sA[buf][k][ty*8];
                float4 a1 = *(const float4*)&sA[buf][k][ty*8+4];
                float4 w0 = *(const float4*)&sW[buf][k][tx*8];
                float4 w1 = *(const float4*)&sW[buf][k][tx*8+4];
                float av[8]={a0.x,a0.y,a0.z,a0.w,a1.x,a1.y,a1.z,a1.w};
                float wv[8]={w0.x,w0.y,w0.z,w0.w,w1.x,w1.y,w1.z,w1.w};
                #pragma unroll
                for(int j=0;j<8;j++)
                    #pragma unroll
                    for(int i=0;i<8;i++) acc[j][i] += av[j]*wv[i];
            }
            if(kt+1 < KT) sts((kt+1)&1, pa0, pa1, pw0, pw1);
            __syncthreads();
        }
        #pragma unroll
        for(int j=0;j<8;j++){
            int rg = tile*128 + ty*8 + j;
            if(rg >= M) continue;
            float v[8];
            #pragma unroll
            for(int i=0;i<8;i++){ v[i]=acc[j][i]+bb[i]; if(MODE>=1) v[i]=silu_(v[i]); }
            *(float4*)&O[(size_t)rg*128+tx*8]   = make_float4(v[0],v[1],v[2],v[3]);
            *(float4*)&O[(size_t)rg*128+tx*8+4] = make_float4(v[4],v[5],v[6],v[7]);
        }
    }
}

// ---------------- coord path (hidden read as bf16) ----------------
__global__ void __launch_bounds__(256) k_coord(const float* __restrict__ x,
        const int* __restrict__ row, const int* __restrict__ col,
        const float* __restrict__ c2W, const float* __restrict__ c2b){
    __shared__ float sc2[CC*128];
    __shared__ float scb[CC];
    int tid=threadIdx.x, warp=tid>>5, lane=tid&31;
    for(int i=tid;i<CC*128;i+=256) sc2[i]=c2W[i];
    if(tid<CC) scb[tid]=c2b[tid];
    __syncthreads();
    const __nv_bfloat162* hid = (const __nv_bfloat162*)g_ef1;
    for(int e = blockIdx.x*8+warp; e < NE; e += gridDim.x*8){
        int r=row[e], c=col[e];
        __nv_bfloat162 h01 = hid[(size_t)e*64 + lane*2];
        __nv_bfloat162 h23 = hid[(size_t)e*64 + lane*2 + 1];
        float4 hv = make_float4(__low2float(h01), __high2float(h01),
                                __low2float(h23), __high2float(h23));
        float p[CC];
        #pragma unroll
        for(int o=0;o<CC;o++){
            const float* w=&sc2[o*128+lane*4];
            p[o]=hv.x*w[0]+hv.y*w[1]+hv.z*w[2]+hv.w*w[3];
        }
        #pragma unroll
        for(int o=0;o<CC;o++){
            #pragma unroll
            for(int s=16;s>0;s>>=1) p[o]+=__shfl_xor_sync(0xffffffffu,p[o],s);
        }
        int cs = (int)(g_csum[r]+0.5f);
        int w = 15 - cs;
        if(lane < CC){
            int end = min(lane + w - 1, CC-1);
            float s = 0.f;
            #pragma unroll
            for(int o=0;o<CC;o++){
                float v = p[o]+scb[o];
                if(o>=lane && o<=end) s += v;
            }
            float pooled = s/(float)w;
            float px=g_pool3[c*3], py=g_pool3[c*3+1], pz=g_pool3[c*3+2];
            const float* xp = &x[((size_t)r*CC+lane)*3];
            atomicAdd(&g_xsum[(r*CC+lane)*3+0], (xp[0]-px)*pooled);
            atomicAdd(&g_xsum[(r*CC+lane)*3+1], (xp[1]-py)*pooled);
            atomicAdd(&g_xsum[(r*CC+lane)*3+2], (xp[2]-pz)*pooled);
        }
        if(lane==0) atomicAdd(&g_cnt_row[r], 1.f);
    }
}

// ---------------- node concat [h | agg/cnt] ----------------
__global__ void k_nodecat(const float* __restrict__ h){
    int idx = blockIdx.x*blockDim.x + threadIdx.x;
    if(idx >= NN*64) return;
    int n = idx>>6, g = idx&63;
    float4 v;
    if(g<32) v = *(const float4*)&h[(size_t)n*128 + g*4];
    else{
        float inv = 1.f/fmaxf(g_cnt_col[n],1.f);
        const float* a = &g_aggsum[(size_t)n*128 + (g-32)*4];
        v = make_float4(a[0]*inv,a[1]*inv,a[2]*inv,a[3]*inv);
    }
    *(float4*)&g_ncat[(size_t)n*256 + g*4] = v;
}

// ---------------- x_out ----------------
__global__ void k_xout(const float* __restrict__ x, float* __restrict__ xout){
    int idx = blockIdx.x*blockDim.x + threadIdx.x;
    if(idx >= NN*CC*3) return;
    int n = idx/(CC*3);
    xout[idx] = x[idx] + g_xsum[idx]/fmaxf(g_cnt_row[n],1.f);
}

// ---------------- layernorm ----------------
__global__ void k_ln(const float* __restrict__ h, const float* __restrict__ lng,
                     const float* __restrict__ lnb, float* __restrict__ out){
    __shared__ float red[8];
    int n = blockIdx.x, t = threadIdx.x;
    float y = h[(size_t)n*128+t] + g_ef[(size_t)n*128+t];
    float s = y;
    #pragma unroll
    for(int o=16;o>0;o>>=1) s += __shfl_xor_sync(0xffffffffu, s, o);
    if((t&31)==0) red[t>>5] = s;
    __syncthreads();
    float mu = (red[0]+red[1]+red[2]+red[3]) * (1.f/128.f);
    float d = y - mu;
    float v = d*d;
    #pragma unroll
    for(int o=16;o>0;o>>=1) v += __shfl_xor_sync(0xffffffffu, v, o);
    if((t&31)==0) red[4+(t>>5)] = v;
    __syncthreads();
    float var = (red[4]+red[5]+red[6]+red[7]) * (1.f/128.f);
    out[(size_t)n*128+t] = d*rsqrtf(var+1e-5f)*lng[t] + lnb[t];
}

// ======================= host launcher =======================
extern "C" void kernel_launch(void* const* d_in, const int* in_sizes, int n_in,
                              void* d_out, int out_size){
    const float* h    = (const float*)d_in[0];
    const float* x    = (const float*)d_in[1];
    const int*   row  = (const int*)  d_in[2];
    const int*   col  = (const int*)  d_in[3];
    const float* attr = (const float*)d_in[4];
    const float* cw   = (const float*)d_in[5];
    const float* radW = (const float*)d_in[6];  const float* radB = (const float*)d_in[7];
    const float* e1W  = (const float*)d_in[8];  const float* e1B  = (const float*)d_in[9];
    const float* e2W  = (const float*)d_in[10]; const float* e2B  = (const float*)d_in[11];
    const float* attW = (const float*)d_in[12]; const float* attB = (const float*)d_in[13];
    const float* c1W  = (const float*)d_in[14]; const float* c1B  = (const float*)d_in[15];
    const float* c2W  = (const float*)d_in[16]; const float* c2B  = (const float*)d_in[17];
    const float* n1W  = (const float*)d_in[18]; const float* n1B  = (const float*)d_in[19];
    const float* n2W  = (const float*)d_in[20]; const float* n2B  = (const float*)d_in[21];
    const float* lng  = (const float*)d_in[22]; const float* lnb  = (const float*)d_in[23];
    float* outH = (float*)d_out;
    float* outX = outH + (size_t)NN*128;

    void *p_radial,*p_rfeat,*p_ef1,*p_ef,*p_rinv,*p_ncat,*p_agg,*p_cntc;
    cudaGetSymbolAddress(&p_radial, g_radial);
    cudaGetSymbolAddress(&p_rfeat,  g_rfeat);
    cudaGetSymbolAddress(&p_ef1,    g_ef1);
    cudaGetSymbolAddress(&p_ef,     g_ef);
    cudaGetSymbolAddress(&p_rinv,   g_rinv);
    cudaGetSymbolAddress(&p_ncat,   g_ncat);
    cudaGetSymbolAddress(&p_agg,    g_aggsum);
    cudaGetSymbolAddress(&p_cntc,   g_cnt_col);

    const int ZT = NN*128 + NN + NN*CC*3 + NN;
    k_zero<<<(ZT+255)/256, 256>>>();
    k_prep<<<(NN+255)/256, 256>>>(x, cw);
    k_geom<<<NE/8, 256>>>(x, row, col, attr, cw);

    const int TB = 304;   // persistent, 2 CTAs/SM
    // rfeat(bf16) = (radial(bf16) @ radW^T + b) * rinv
    tmma<16,0,false><<<TB,256>>>((const uint32_t*)p_radial, radW, radB,
        (uint32_t*)p_rfeat, TE128, (const float*)p_rinv, 0,0,0,0,0,0, 0,0);
    // ef1(bf16) = silu([h_r|h_c|rfeat] @ e1^T + b)
    tmma<24,1,true><<<TB,256>>>(0, e1W, e1B,
        (uint32_t*)p_ef1, TE128, 0, row, col, 0,0,0,0, h, (const uint32_t*)p_rfeat);
    // ef(bf16) = silu(ef1 @ e2^T + b) * sigmoid(att); scatter agg[col] fp32
    tmma<8,2,false><<<TB,256>>>((const uint32_t*)p_ef1, e2W, e2B,
        (uint32_t*)p_ef, TE128, 0, 0, col, attW, attB,
        (float*)p_agg, (float*)p_cntc, 0,0);
    // hid(bf16) = silu(ef @ c1^T + b)  -> overwrite g_ef1
    tmma<8,1,false><<<TB,256>>>((const uint32_t*)p_ef, c1W, c1B,
        (uint32_t*)p_ef1, TE128, 0, 0,0,0,0,0,0, 0,0);
    // coord path (reads bf16 hidden in g_ef1)
    k_coord<<<1216, 256>>>(x, row, col, c2W, c2B);
    // node path (fp32 SIMT)
    k_nodecat<<<(NN*64+255)/256, 256>>>(h);
    k_xout<<<(NN*CC*3+255)/256, 256>>>(x, outX);
    kgemm<256,1><<<304,256>>>((const float*)p_ncat, n1W, n1B, (float*)p_rfeat, NN, TN128);
    kgemm<128,0><<<304,256>>>((const float*)p_rfeat, n2W, n2B, (float*)p_ef, NN, TN128);
    k_ln<<<NN, 128>>>(h, lng, lnb, outH);
}

// round 8
// speedup vs baseline: 5.3867x; 1.1905x over previous
#include <cuda_runtime.h>
#include <cuda_bf16.h>
#include <math.h>
#include <stdint.h>

#define NN 20000
#define NE 320000
#define CC 14
#define TE128 (NE/128)              // 2500
#define TN128 ((NN+127)/128)        // 157

// ---------------- scratch ----------------
__device__ float g_radial[(size_t)NE*128];  // bf16 [E][256] = radial * rinv
__device__ float g_ef1[(size_t)NE*64];      // bf16 [E][128]: e1 out -> hid (in place)
__device__ float g_rfeat[(size_t)NN*128];   // fp32 node n1 out
__device__ float g_ef[(size_t)NN*128];      // fp32 node n2 out
__device__ float g_rinv[NE];
__device__ float g_csum[NN];
__device__ float g_pool3[NN*3];
__device__ float g_aggsum[(size_t)NN*128];
__device__ float g_cnt_col[NN];
__device__ float g_xsum[NN*CC*3];
__device__ float g_cnt_row[NN];
__device__ float g_ncat[(size_t)NN*256];
__device__ float g_hbf[NN*64];              // bf16 h
__device__ float g_waug[128*264];           // bf16 [128][528] augmented e1 weight
__device__ float g_we2[128*64];             // bf16 e2W
__device__ float g_wc1[128*64];             // bf16 c1W

__device__ __forceinline__ float sigm(float v){ return 1.f/(1.f+__expf(-v)); }
__device__ __forceinline__ float silu_(float v){ return v*sigm(v); }
__device__ __forceinline__ uint32_t pk2(float lo, float hi){
    __nv_bfloat162 t = __floats2bfloat162_rn(lo, hi);
    return *(uint32_t*)&t;
}
__device__ __forceinline__ void mma16(float* c, const uint32_t* a, const uint32_t* b){
    asm volatile("mma.sync.aligned.m16n8k16.row.col.f32.bf16.bf16.f32 "
        "{%0,%1,%2,%3}, {%4,%5,%6,%7}, {%8,%9}, {%0,%1,%2,%3};"
        : "+f"(c[0]),"+f"(c[1]),"+f"(c[2]),"+f"(c[3])
        : "r"(a[0]),"r"(a[1]),"r"(a[2]),"r"(a[3]), "r"(b[0]),"r"(b[1]));
}

// ---------------- zero accumulators ----------------
__global__ void k_zero(){
    int i = blockIdx.x*blockDim.x + threadIdx.x;
    const int A = NN*128, B = A+NN, D = B+NN*CC*3, T = D+NN;
    if(i >= T) return;
    if(i < A) g_aggsum[i]=0.f;
    else if(i < B) g_cnt_col[i-A]=0.f;
    else if(i < D) g_xsum[i-B]=0.f;
    else g_cnt_row[i-D]=0.f;
}

// ---------------- node prep ----------------
__global__ void k_prep(const float* __restrict__ x, const float* __restrict__ cw){
    int n = blockIdx.x*blockDim.x + threadIdx.x;
    if(n >= NN) return;
    float cnt=0.f, px=0.f, py=0.f, pz=0.f;
    #pragma unroll
    for(int i=0;i<CC;i++){
        float w = cw[n*CC+i];
        if(w != 0.f){
            cnt += 1.f;
            const float* xp = &x[(n*CC+i)*3];
            px += xp[0]; py += xp[1]; pz += xp[2];
        }
    }
    g_csum[n] = cnt;
    float inv = 1.f/cnt;
    g_pool3[n*3+0]=px*inv; g_pool3[n*3+1]=py*inv; g_pool3[n*3+2]=pz*inv;
}

// ---------------- h -> bf16 ----------------
__global__ void k_hconv(const float* __restrict__ h){
    int i = blockIdx.x*blockDim.x + threadIdx.x;
    if(i >= NN*64) return;
    float2 v = ((const float2*)h)[i];
    ((uint32_t*)g_hbf)[i] = pk2(v.x, v.y);
}

// ---------------- e2W / c1W -> bf16 ----------------
__global__ void k_wcvt(const float* __restrict__ e2W, const float* __restrict__ c1W){
    int i = blockIdx.x*blockDim.x + threadIdx.x;
    if(i >= 2*128*64) return;
    if(i < 128*64){ float2 v=((const float2*)e2W)[i]; ((uint32_t*)g_we2)[i]=pk2(v.x,v.y); }
    else { int j=i-128*64; float2 v=((const float2*)c1W)[j]; ((uint32_t*)g_wc1)[j]=pk2(v.x,v.y); }
}

// ---------------- build augmented e1 weight (bf16) ----------------
// Waug[n] = [ e1W[n][0:256] | (e1c @ radW)[n] | (e1c@radB)[n], 0...0 ]  (528 cols)
__global__ void k_waug(const float* __restrict__ e1W, const float* __restrict__ radW,
                       const float* __restrict__ radB){
    __shared__ float s[128];
    int n = blockIdx.x, tid = threadIdx.x;
    if(tid < 128) s[tid] = e1W[n*384 + 256 + tid];
    __syncthreads();
    uint32_t* out = (uint32_t*)g_waug + n*264;
    if(tid < 128) out[tid] = pk2(e1W[n*384 + 2*tid], e1W[n*384 + 2*tid + 1]);
    else if(tid-128 < 128){
        int kpl = tid-128;
        int kk = 2*kpl;
        float d0=0.f, d1=0.f;
        #pragma unroll 4
        for(int j=0;j<128;j++){
            float sj = s[j];
            d0 += sj*radW[j*256+kk];
            d1 += sj*radW[j*256+kk+1];
        }
        out[128+kpl] = pk2(d0,d1);
    }
    if(tid==0){
        float bc=0.f;
        for(int j=0;j<128;j++) bc += s[j]*radB[j];
        out[256] = pk2(bc, 0.f);
    }
    if(tid>=1 && tid<8) out[256+tid] = 0u;
}

// ---------------- per-edge geometry: radial' = radial*rinv (bf16) ------------
#define GS 992
__global__ void k_geom(const float* __restrict__ x, const int* __restrict__ row,
                       const int* __restrict__ col, const float* __restrict__ attr,
                       const float* __restrict__ cw){
    __shared__ float sm[8][GS];
    int warp = threadIdx.x>>5, lane = threadIdx.x&31;
    int e = blockIdx.x*8 + warp;
    if(e >= NE) return;
    float* s = sm[warp];
    int r = row[e], c = col[e];
    const int oCWR=0,oCWC=14,oXR=28,oXC=70,oAR=112,oAC=336,oM=560,oT=756;
    if(lane < CC){ s[oCWR+lane]=cw[r*CC+lane]; s[oCWC+lane]=cw[c*CC+lane]; }
    for(int i=lane;i<42;i+=32){ s[oXR+i]=x[r*42+i]; s[oXC+i]=x[c*42+i]; }
    for(int i=lane;i<224;i+=32){ s[oAR+i]=attr[r*224+i]; s[oAC+i]=attr[c*224+i]; }
    __syncwarp();
    for(int idx=lane; idx<196; idx+=32){
        int i = idx/14, j = idx - i*14;
        float dx = s[oXR+i*3+0]-s[oXC+j*3+0];
        float dy = s[oXR+i*3+1]-s[oXC+j*3+1];
        float dz = s[oXR+i*3+2]-s[oXC+j*3+2];
        float d = sqrtf(dx*dx+dy*dy+dz*dz);
        s[oM+idx] = d * s[oCWR+i] * s[oCWC+j];
    }
    __syncwarp();
    int b = lane&15, hh = lane>>4;
    {
        float acj[CC];
        #pragma unroll
        for(int j=0;j<CC;j++) acj[j] = s[oAC + j*16 + b];
        #pragma unroll
        for(int i0=0;i0<7;i0++){
            int i = hh*7 + i0;
            float t = 0.f;
            #pragma unroll
            for(int j=0;j<CC;j++) t += s[oM + i*14 + j]*acj[j];
            s[oT + i*16 + b] = t;
        }
    }
    __syncwarp();
    float racc[8] = {0,0,0,0,0,0,0,0};
    {
        float tb[CC];
        #pragma unroll
        for(int i=0;i<CC;i++) tb[i] = s[oT + i*16 + b];
        #pragma unroll
        for(int i=0;i<CC;i++){
            float tv = tb[i];
            #pragma unroll
            for(int q=0;q<8;q++) racc[q] += s[oAR + i*16 + hh*8 + q]*tv;
        }
    }
    float sq = 0.f;
    #pragma unroll
    for(int q=0;q<8;q++) sq += racc[q]*racc[q];
    #pragma unroll
    for(int o=16;o>0;o>>=1) sq += __shfl_xor_sync(0xffffffffu, sq, o);
    float rinv = 1.f/(sqrtf(sq)+1.f);
    __nv_bfloat16* go = (__nv_bfloat16*)g_radial + (size_t)e*256;
    #pragma unroll
    for(int q=0;q<8;q++) go[(hh*8+q)*16 + b] = __float2bfloat16(racc[q]*rinv);
    if(lane==0) g_rinv[e] = rinv;
}

// ===== e1 GEMM: ef1 = silu([h_r|h_c|radial'|rinv,pad] @ Waug^T + e1B) =====
// K=528 (33 chunks of 16), BM=128 BN=128, 8 warps (4Mx2N), m16n8k16.
__global__ void __launch_bounds__(256,2) k_e1(
    const float* __restrict__ e1B, const int* __restrict__ rowi,
    const int* __restrict__ coli, int tiles)
{
    __shared__ uint32_t sA[2][8][136];
    __shared__ uint32_t sW[2][8][136];
    __shared__ int sRow[128], sCol[128];
    __shared__ float sBias[128];
    const int tid = threadIdx.x, wid = tid>>5, lane = tid&31;
    const int warpM = (wid&3)*32, warpN = (wid>>2)*64;
    const int ee = tid>>1, q = tid&1;
    const int r4 = lane>>2, c4 = lane&3;
    const int KT = 33;
    const uint32_t* hbf  = (const uint32_t*)g_hbf;
    const uint32_t* rad  = (const uint32_t*)g_radial;
    const uint32_t* waug = (const uint32_t*)g_waug;
    uint32_t* Obf = (uint32_t*)g_ef1;

    if(tid<128) sBias[tid]=e1B[tid];

    for(int tile=blockIdx.x; tile<tiles; tile+=gridDim.x){
        if(tid<128){ sRow[tid]=rowi[tile*128+tid]; sCol[tid]=coli[tile*128+tid]; }
        __syncthreads();

        uint32_t pa[4], pw[4];
        auto ldA = [&](int kt, uint32_t* v){
            const int kg = kt*16 + q*8;
            const int rg = tile*128 + ee;
            if(kg < 256){
                const uint32_t* p = (kg<128) ? &hbf[sRow[ee]*64 + (kg>>1)]
                                             : &hbf[sCol[ee]*64 + ((kg-128)>>1)];
                uint4 u = *(const uint4*)p;
                v[0]=u.x; v[1]=u.y; v[2]=u.z; v[3]=u.w;
            } else if(kg < 512){
                uint4 u = *(const uint4*)&rad[(size_t)rg*128 + ((kg-256)>>1)];
                v[0]=u.x; v[1]=u.y; v[2]=u.z; v[3]=u.w;
            } else if(kg == 512){
                v[0]=pk2(g_rinv[rg],0.f); v[1]=0u; v[2]=0u; v[3]=0u;
            } else { v[0]=v[1]=v[2]=v[3]=0u; }
        };
        auto ldW = [&](int kt, uint32_t* v){
            uint4 u = *(const uint4*)&waug[ee*264 + kt*8 + q*4];
            v[0]=u.x; v[1]=u.y; v[2]=u.z; v[3]=u.w;
        };
        auto sts = [&](int buf, const uint32_t* va, const uint32_t* vw){
            #pragma unroll
            for(int j=0;j<4;j++){
                sA[buf][q*4+j][ee] = va[j];
                sW[buf][q*4+j][ee] = vw[j];
            }
        };

        float acc[2][8][4];
        #pragma unroll
        for(int am=0;am<2;am++)
            #pragma unroll
            for(int bn=0;bn<8;bn++)
                #pragma unroll
                for(int i=0;i<4;i++) acc[am][bn][i]=0.f;

        ldA(0, pa); ldW(0, pw);
        sts(0, pa, pw);
        __syncthreads();

        #pragma unroll 1
        for(int kt=0; kt<KT; kt++){
            if(kt+1 < KT){ ldA(kt+1, pa); ldW(kt+1, pw); }
            const int buf = kt&1;
            uint32_t bf[8][2];
            #pragma unroll
            for(int bn=0;bn<8;bn++){
                int n = warpN + bn*8 + r4;
                bf[bn][0] = sW[buf][c4  ][n];
                bf[bn][1] = sW[buf][c4+4][n];
            }
            #pragma unroll
            for(int am=0;am<2;am++){
                int m0 = warpM + am*16 + r4;
                uint32_t af[4];
                af[0] = sA[buf][c4  ][m0];
                af[1] = sA[buf][c4  ][m0+8];
                af[2] = sA[buf][c4+4][m0];
                af[3] = sA[buf][c4+4][m0+8];
                #pragma unroll
                for(int bn=0;bn<8;bn++) mma16(acc[am][bn], af, bf[bn]);
            }
            if(kt+1 < KT) sts((kt+1)&1, pa, pw);
            __syncthreads();
        }

        #pragma unroll
        for(int am=0;am<2;am++)
            #pragma unroll
            for(int hf=0;hf<2;hf++){
                int rl = warpM + am*16 + r4 + hf*8;
                int rg = tile*128 + rl;
                uint32_t* op = &Obf[(size_t)rg*64];
                #pragma unroll
                for(int bn=0;bn<8;bn++){
                    int c0 = warpN + bn*8 + c4*2;
                    float v0 = silu_(acc[am][bn][hf*2]   + sBias[c0]);
                    float v1 = silu_(acc[am][bn][hf*2+1] + sBias[c0+1]);
                    op[c0>>1] = pk2(v0, v1);
                }
            }
        __syncthreads();
    }
}

// ===== fused e2 + c1: ef = gate(silu(ef1@e2^T+b)); agg scatter; hid = silu(ef@c1^T+b) =====
#define E2SM (13824*4)
__global__ void __launch_bounds__(256,2) k_e2c1(
    const float* __restrict__ e2B, const float* __restrict__ c1B,
    const int* __restrict__ coli, const float* __restrict__ attWg,
    const float* __restrict__ attbg,
    float* __restrict__ agg, float* __restrict__ cnt, int tiles)
{
    extern __shared__ uint32_t dsm[];
    uint32_t* sA   = dsm;                    // [2][8][136]
    uint32_t* sW   = dsm + 2176;             // [2][8][136]
    uint32_t* sEF  = dsm + 4352;             // [64][136]
    int*   sCol    = (int*)(dsm + 13056);
    float* sBias   = (float*)(dsm + 13184);
    float* sAtt    = (float*)(dsm + 13312);
    float* sBias2  = (float*)(dsm + 13440);
    float* sDot    = (float*)(dsm + 13568);  // [2][128]
    const int tid = threadIdx.x, wid = tid>>5, lane = tid&31;
    const int warpM = (wid&3)*32, warpN = (wid>>2)*64;
    const int ee = tid>>1, q = tid&1;
    const int r4 = lane>>2, c4 = lane&3;
    const uint32_t* Abf = (const uint32_t*)g_ef1;
    const uint32_t* W2  = (const uint32_t*)g_we2;
    const uint32_t* W3  = (const uint32_t*)g_wc1;
    uint32_t* hid = (uint32_t*)g_ef1;

    if(tid<128){ sBias[tid]=e2B[tid]; sAtt[tid]=attWg[tid]; sBias2[tid]=c1B[tid]; }
    const float attb = attbg[0];

    for(int tile=blockIdx.x; tile<tiles; tile+=gridDim.x){
        if(tid<128) sCol[tid]=coli[tile*128+tid];

        uint32_t pa[4], pw[4];
        auto sts = [&](int buf, const uint32_t* va, const uint32_t* vw){
            #pragma unroll
            for(int j=0;j<4;j++){
                sA[buf*1088 + (q*4+j)*136 + ee] = va[j];
                sW[buf*1088 + (q*4+j)*136 + ee] = vw[j];
            }
        };
        auto stsW = [&](int buf, const uint32_t* vw){
            #pragma unroll
            for(int j=0;j<4;j++) sW[buf*1088 + (q*4+j)*136 + ee] = vw[j];
        };

        float acc[2][8][4];
        #pragma unroll
        for(int am=0;am<2;am++)
            #pragma unroll
            for(int bn=0;bn<8;bn++)
                #pragma unroll
                for(int i=0;i<4;i++) acc[am][bn][i]=0.f;

        // ---- phase A: e2 GEMM, K=128 ----
        {
            uint4 u = *(const uint4*)&Abf[(size_t)(tile*128+ee)*64 + q*4];
            pa[0]=u.x; pa[1]=u.y; pa[2]=u.z; pa[3]=u.w;
            uint4 w = *(const uint4*)&W2[ee*64 + q*4];
            pw[0]=w.x; pw[1]=w.y; pw[2]=w.z; pw[3]=w.w;
        }
        sts(0, pa, pw);
        __syncthreads();
        #pragma unroll 1
        for(int kt=0; kt<8; kt++){
            if(kt+1 < 8){
                uint4 u = *(const uint4*)&Abf[(size_t)(tile*128+ee)*64 + (kt+1)*8 + q*4];
                pa[0]=u.x; pa[1]=u.y; pa[2]=u.z; pa[3]=u.w;
                uint4 w = *(const uint4*)&W2[ee*64 + (kt+1)*8 + q*4];
                pw[0]=w.x; pw[1]=w.y; pw[2]=w.z; pw[3]=w.w;
            }
            const int buf = kt&1;
            uint32_t bfr[8][2];
            #pragma unroll
            for(int bn=0;bn<8;bn++){
                int n = warpN + bn*8 + r4;
                bfr[bn][0] = sW[buf*1088 + c4*136 + n];
                bfr[bn][1] = sW[buf*1088 + (c4+4)*136 + n];
            }
            #pragma unroll
            for(int am=0;am<2;am++){
                int m0 = warpM + am*16 + r4;
                uint32_t af[4];
                af[0] = sA[buf*1088 + c4*136 + m0];
                af[1] = sA[buf*1088 + c4*136 + m0+8];
                af[2] = sA[buf*1088 + (c4+4)*136 + m0];
                af[3] = sA[buf*1088 + (c4+4)*136 + m0+8];
                #pragma unroll
                for(int bn=0;bn<8;bn++) mma16(acc[am][bn], af, bfr[bn]);
            }
            if(kt+1 < 8) sts((kt+1)&1, pa, pw);
            __syncthreads();
        }
        // epilogue A: bias + silu + gate
        #pragma unroll
        for(int am=0;am<2;am++)
            #pragma unroll
            for(int bn=0;bn<8;bn++){
                int c0 = warpN + bn*8 + c4*2;
                float* a = acc[am][bn];
                a[0]=silu_(a[0]+sBias[c0]);   a[1]=silu_(a[1]+sBias[c0+1]);
                a[2]=silu_(a[2]+sBias[c0]);   a[3]=silu_(a[3]+sBias[c0+1]);
            }
        {
            float dot[2][2] = {{0.f,0.f},{0.f,0.f}};
            #pragma unroll
            for(int am=0;am<2;am++)
                #pragma unroll
                for(int bn=0;bn<8;bn++){
                    int c0 = warpN + bn*8 + c4*2;
                    float w0=sAtt[c0], w1=sAtt[c0+1];
                    dot[am][0] += acc[am][bn][0]*w0 + acc[am][bn][1]*w1;
                    dot[am][1] += acc[am][bn][2]*w0 + acc[am][bn][3]*w1;
                }
            #pragma unroll
            for(int am=0;am<2;am++)
                #pragma unroll
                for(int hf=0;hf<2;hf++){
                    dot[am][hf] += __shfl_xor_sync(0xffffffffu, dot[am][hf], 1);
                    dot[am][hf] += __shfl_xor_sync(0xffffffffu, dot[am][hf], 2);
                }
            if(c4==0){
                #pragma unroll
                for(int am=0;am<2;am++){
                    sDot[(wid>>2)*128 + warpM+am*16+r4]   = dot[am][0];
                    sDot[(wid>>2)*128 + warpM+am*16+r4+8] = dot[am][1];
                }
            }
            __syncthreads();
            #pragma unroll
            for(int am=0;am<2;am++)
                #pragma unroll
                for(int hf=0;hf<2;hf++){
                    int rl = warpM + am*16 + r4 + hf*8;
                    float g = sigm(sDot[rl] + sDot[128+rl] + attb);
                    acc[am][0][hf*2]*=g; acc[am][0][hf*2+1]*=g;
                    #pragma unroll
                    for(int bn=1;bn<8;bn++){
                        acc[am][bn][hf*2]   *= g;
                        acc[am][bn][hf*2+1] *= g;
                    }
                }
        }
        // scatter agg + stage ef tile into sEF
        #pragma unroll
        for(int am=0;am<2;am++)
            #pragma unroll
            for(int hf=0;hf<2;hf++){
                int rl = warpM + am*16 + r4 + hf*8;
                int cc = sCol[rl];
                float* ag = &agg[(size_t)cc*128];
                #pragma unroll
                for(int bn=0;bn<8;bn++){
                    int c0 = warpN + bn*8 + c4*2;
                    float v0 = acc[am][bn][hf*2], v1 = acc[am][bn][hf*2+1];
                    atomicAdd(ag+c0,   v0);
                    atomicAdd(ag+c0+1, v1);
                    sEF[(c0>>1)*136 + rl] = pk2(v0, v1);
                }
                if(warpN==0 && c4==0) atomicAdd(&cnt[cc], 1.f);
            }
        __syncthreads();

        // ---- phase B: c1 GEMM from sEF, K=128 ----
        #pragma unroll
        for(int am=0;am<2;am++)
            #pragma unroll
            for(int bn=0;bn<8;bn++)
                #pragma unroll
                for(int i=0;i<4;i++) acc[am][bn][i]=0.f;
        {
            uint4 w = *(const uint4*)&W3[ee*64 + q*4];
            pw[0]=w.x; pw[1]=w.y; pw[2]=w.z; pw[3]=w.w;
        }
        stsW(0, pw);
        __syncthreads();
        #pragma unroll 1
        for(int kt=0; kt<8; kt++){
            if(kt+1 < 8){
                uint4 w = *(const uint4*)&W3[ee*64 + (kt+1)*8 + q*4];
                pw[0]=w.x; pw[1]=w.y; pw[2]=w.z; pw[3]=w.w;
            }
            const int buf = kt&1;
            uint32_t bfr[8][2];
            #pragma unroll
            for(int bn=0;bn<8;bn++){
                int n = warpN + bn*8 + r4;
                bfr[bn][0] = sW[buf*1088 + c4*136 + n];
                bfr[bn][1] = sW[buf*1088 + (c4+4)*136 + n];
            }
            #pragma unroll
            for(int am=0;am<2;am++){
                int m0 = warpM + am*16 + r4;
                uint32_t af[4];
                af[0] = sEF[(kt*8+c4)*136 + m0];
                af[1] = sEF[(kt*8+c4)*136 + m0+8];
                af[2] = sEF[(kt*8+c4+4)*136 + m0];
                af[3] = sEF[(kt*8+c4+4)*136 + m0+8];
                #pragma unroll
                for(int bn=0;bn<8;bn++) mma16(acc[am][bn], af, bfr[bn]);
            }
            if(kt+1 < 8) stsW((kt+1)&1, pw);
            __syncthreads();
        }
        // epilogue B: bias + silu -> hid (overwrite g_ef1 tile)
        #pragma unroll
        for(int am=0;am<2;am++)
            #pragma unroll
            for(int hf=0;hf<2;hf++){
                int rl = warpM + am*16 + r4 + hf*8;
                int rg = tile*128 + rl;
                uint32_t* op = &hid[(size_t)rg*64];
                #pragma unroll
                for(int bn=0;bn<8;bn++){
                    int c0 = warpN + bn*8 + c4*2;
                    float v0 = silu_(acc[am][bn][hf*2]   + sBias2[c0]);
                    float v1 = silu_(acc[am][bn][hf*2+1] + sBias2[c0+1]);
                    op[c0>>1] = pk2(v0, v1);
                }
            }
        __syncthreads();
    }
}

// ======= SIMT GEMM (node MLP, fp32, small M with bounds) =======
template<int K, int MODE>
__global__ void __launch_bounds__(256,2) kgemm(
    const float* __restrict__ A, const float* __restrict__ Wg,
    const float* __restrict__ bg, float* __restrict__ O, int M, int tiles)
{
    __shared__ float sA[2][16][128];
    __shared__ float sW[2][16][128];
    const int tid = threadIdx.x, tx = tid&15, ty = tid>>4;
    const int ee = tid>>1, q = tid&1, kq = q*8;
    float bb[8];
    #pragma unroll
    for(int i=0;i<8;i++) bb[i]=bg[tx*8+i];

    for(int tile=blockIdx.x; tile<tiles; tile+=gridDim.x){
        float4 pa0, pa1, pw0, pw1;
        auto ldA = [&](int kt, float4& v0, float4& v1){
            int rg = tile*128 + ee;
            if(rg < M){
                const float* p = &A[(size_t)rg*K + kt*16 + kq];
                v0 = *(const float4*)p; v1 = *(const float4*)(p+4);
            } else { v0=v1=make_float4(0,0,0,0); }
        };
        auto ldW = [&](int kt, float4& v0, float4& v1){
            const float* p = &Wg[(size_t)ee*K + kt*16 + kq];
            v0 = *(const float4*)p; v1 = *(const float4*)(p+4);
        };
        auto sts = [&](int buf, float4 a0, float4 a1, float4 w0, float4 w1){
            sA[buf][kq+0][ee]=a0.x; sA[buf][kq+1][ee]=a0.y;
            sA[buf][kq+2][ee]=a0.z; sA[buf][kq+3][ee]=a0.w;
            sA[buf][kq+4][ee]=a1.x; sA[buf][kq+5][ee]=a1.y;
            sA[buf][kq+6][ee]=a1.z; sA[buf][kq+7][ee]=a1.w;
            sW[buf][kq+0][ee]=w0.x; sW[buf][kq+1][ee]=w0.y;
            sW[buf][kq+2][ee]=w0.z; sW[buf][kq+3][ee]=w0.w;
            sW[buf][kq+4][ee]=w1.x; sW[buf][kq+5][ee]=w1.y;
            sW[buf][kq+6][ee]=w1.z; sW[buf][kq+7][ee]=w1.w;
        };
        ldA(0, pa0, pa1); ldW(0, pw0, pw1);
        sts(0, pa0, pa1, pw0, pw1);
        __syncthreads();
        float acc[8][8];
        #pragma unroll
        for(int j=0;j<8;j++)
            #pragma unroll
            for(int i=0;i<8;i++) acc[j][i]=0.f;
        const int KT = K/16;
        #pragma unroll 1
        for(int kt=0; kt<KT; kt++){
            if(kt+1 < KT){ ldA(kt+1, pa0, pa1); ldW(kt+1, pw0, pw1); }
            const int buf = kt&1;
            #pragma unroll
            for(int k=0;k<16;k++){
                float4 a0 = *(const float4*)&sA[buf][k][ty*8];
                float4 a1 = *(const float4*)&sA[buf][k][ty*8+4];
                float4 w0 = *(const float4*)&sW[buf][k][tx*8];
                float4 w1 = *(const float4*)&sW[buf][k][tx*8+4];
                float av[8]={a0.x,a0.y,a0.z,a0.w,a1.x,a1.y,a1.z,a1.w};
                float wv[8]={w0.x,w0.y,w0.z,w0.w,w1.x,w1.y,w1.z,w1.w};
                #pragma unroll
                for(int j=0;j<8;j++)
                    #pragma unroll
                    for(int i=0;i<8;i++) acc[j][i] += av[j]*wv[i];
            }
            if(kt+1 < KT) sts((kt+1)&1, pa0, pa1, pw0, pw1);
            __syncthreads();
        }
        #pragma unroll
        for(int j=0;j<8;j++){
            int rg = tile*128 + ty*8 + j;
            if(rg >= M) continue;
            float v[8];
            #pragma unroll
            for(int i=0;i<8;i++){ v[i]=acc[j][i]+bb[i]; if(MODE>=1) v[i]=silu_(v[i]); }
            *(float4*)&O[(size_t)rg*128+tx*8]   = make_float4(v[0],v[1],v[2],v[3]);
            *(float4*)&O[(size_t)rg*128+tx*8+4] = make_float4(v[4],v[5],v[6],v[7]);
        }
    }
}

// ---------------- coord path (hidden read as bf16) ----------------
__global__ void __launch_bounds__(256) k_coord(const float* __restrict__ x,
        const int* __restrict__ row, const int* __restrict__ col,
        const float* __restrict__ c2W, const float* __restrict__ c2b){
    __shared__ float sc2[CC*128];
    __shared__ float scb[CC];
    int tid=threadIdx.x, warp=tid>>5, lane=tid&31;
    for(int i=tid;i<CC*128;i+=256) sc2[i]=c2W[i];
    if(tid<CC) scb[tid]=c2b[tid];
    __syncthreads();
    const __nv_bfloat162* hid = (const __nv_bfloat162*)g_ef1;
    for(int e = blockIdx.x*8+warp; e < NE; e += gridDim.x*8){
        int r=row[e], c=col[e];
        __nv_bfloat162 h01 = hid[(size_t)e*64 + lane*2];
        __nv_bfloat162 h23 = hid[(size_t)e*64 + lane*2 + 1];
        float4 hv = make_float4(__low2float(h01), __high2float(h01),
                                __low2float(h23), __high2float(h23));
        float p[CC];
        #pragma unroll
        for(int o=0;o<CC;o++){
            const float* w=&sc2[o*128+lane*4];
            p[o]=hv.x*w[0]+hv.y*w[1]+hv.z*w[2]+hv.w*w[3];
        }
        #pragma unroll
        for(int o=0;o<CC;o++){
            #pragma unroll
            for(int s=16;s>0;s>>=1) p[o]+=__shfl_xor_sync(0xffffffffu,p[o],s);
        }
        int cs = (int)(g_csum[r]+0.5f);
        int w = 15 - cs;
        if(lane < CC){
            int end = min(lane + w - 1, CC-1);
            float s = 0.f;
            #pragma unroll
            for(int o=0;o<CC;o++){
                float v = p[o]+scb[o];
                if(o>=lane && o<=end) s += v;
            }
            float pooled = s/(float)w;
            float px=g_pool3[c*3], py=g_pool3[c*3+1], pz=g_pool3[c*3+2];
            const float* xp = &x[((size_t)r*CC+lane)*3];
            atomicAdd(&g_xsum[(r*CC+lane)*3+0], (xp[0]-px)*pooled);
            atomicAdd(&g_xsum[(r*CC+lane)*3+1], (xp[1]-py)*pooled);
            atomicAdd(&g_xsum[(r*CC+lane)*3+2], (xp[2]-pz)*pooled);
        }
        if(lane==0) atomicAdd(&g_cnt_row[r], 1.f);
    }
}

// ---------------- node concat [h | agg/cnt] ----------------
__global__ void k_nodecat(const float* __restrict__ h){
    int idx = blockIdx.x*blockDim.x + threadIdx.x;
    if(idx >= NN*64) return;
    int n = idx>>6, g = idx&63;
    float4 v;
    if(g<32) v = *(const float4*)&h[(size_t)n*128 + g*4];
    else{
        float inv = 1.f/fmaxf(g_cnt_col[n],1.f);
        const float* a = &g_aggsum[(size_t)n*128 + (g-32)*4];
        v = make_float4(a[0]*inv,a[1]*inv,a[2]*inv,a[3]*inv);
    }
    *(float4*)&g_ncat[(size_t)n*256 + g*4] = v;
}

// ---------------- x_out ----------------
__global__ void k_xout(const float* __restrict__ x, float* __restrict__ xout){
    int idx = blockIdx.x*blockDim.x + threadIdx.x;
    if(idx >= NN*CC*3) return;
    int n = idx/(CC*3);
    xout[idx] = x[idx] + g_xsum[idx]/fmaxf(g_cnt_row[n],1.f);
}

// ---------------- layernorm ----------------
__global__ void k_ln(const float* __restrict__ h, const float* __restrict__ lng,
                     const float* __restrict__ lnb, float* __restrict__ out){
    __shared__ float red[8];
    int n = blockIdx.x, t = threadIdx.x;
    float y = h[(size_t)n*128+t] + g_ef[(size_t)n*128+t];
    float s = y;
    #pragma unroll
    for(int o=16;o>0;o>>=1) s += __shfl_xor_sync(0xffffffffu, s, o);
    if((t&31)==0) red[t>>5] = s;
    __syncthreads();
    float mu = (red[0]+red[1]+red[2]+red[3]) * (1.f/128.f);
    float d = y - mu;
    float v = d*d;
    #pragma unroll
    for(int o=16;o>0;o>>=1) v += __shfl_xor_sync(0xffffffffu, v, o);
    if((t&31)==0) red[4+(t>>5)] = v;
    __syncthreads();
    float var = (red[4]+red[5]+red[6]+red[7]) * (1.f/128.f);
    out[(size_t)n*128+t] = d*rsqrtf(var+1e-5f)*lng[t] + lnb[t];
}

// ======================= host launcher =======================
extern "C" void kernel_launch(void* const* d_in, const int* in_sizes, int n_in,
                              void* d_out, int out_size){
    const float* h    = (const float*)d_in[0];
    const float* x    = (const float*)d_in[1];
    const int*   row  = (const int*)  d_in[2];
    const int*   col  = (const int*)  d_in[3];
    const float* attr = (const float*)d_in[4];
    const float* cw   = (const float*)d_in[5];
    const float* radW = (const float*)d_in[6];  const float* radB = (const float*)d_in[7];
    const float* e1W  = (const float*)d_in[8];  const float* e1B  = (const float*)d_in[9];
    const float* e2W  = (const float*)d_in[10]; const float* e2B  = (const float*)d_in[11];
    const float* attW = (const float*)d_in[12]; const float* attB = (const float*)d_in[13];
    const float* c1W  = (const float*)d_in[14]; const float* c1B  = (const float*)d_in[15];
    const float* c2W  = (const float*)d_in[16]; const float* c2B  = (const float*)d_in[17];
    const float* n1W  = (const float*)d_in[18]; const float* n1B  = (const float*)d_in[19];
    const float* n2W  = (const float*)d_in[20]; const float* n2B  = (const float*)d_in[21];
    const float* lng  = (const float*)d_in[22]; const float* lnb  = (const float*)d_in[23];
    float* outH = (float*)d_out;
    float* outX = outH + (size_t)NN*128;

    void *p_rfeat,*p_ef,*p_ncat,*p_agg,*p_cntc;
    cudaGetSymbolAddress(&p_rfeat,  g_rfeat);
    cudaGetSymbolAddress(&p_ef,     g_ef);
    cudaGetSymbolAddress(&p_ncat,   g_ncat);
    cudaGetSymbolAddress(&p_agg,    g_aggsum);
    cudaGetSymbolAddress(&p_cntc,   g_cnt_col);

    cudaFuncSetAttribute(k_e2c1, cudaFuncAttributeMaxDynamicSharedMemorySize, E2SM);

    const int ZT = NN*128 + NN + NN*CC*3 + NN;
    k_zero<<<(ZT+255)/256, 256>>>();
    k_prep<<<(NN+255)/256, 256>>>(x, cw);
    k_hconv<<<(NN*64+255)/256, 256>>>(h);
    k_wcvt<<<(2*128*64+255)/256, 256>>>(e2W, c1W);
    k_waug<<<128, 256>>>(e1W, radW, radB);
    k_geom<<<NE/8, 256>>>(x, row, col, attr, cw);

    const int TB = 304;
    // ef1(bf16) = silu([h_r|h_c|radial'|rinv] @ Waug^T + e1B)
    k_e1<<<TB,256>>>(e1B, row, col, TE128);
    // fused e2 + gate + agg-scatter + c1 -> hid (in place in g_ef1)
    k_e2c1<<<TB,256,E2SM>>>(e2B, c1B, col, attW, attB,
                            (float*)p_agg, (float*)p_cntc, TE128);
    // coord path (reads bf16 hidden in g_ef1)
    k_coord<<<1216, 256>>>(x, row, col, c2W, c2B);
    // node path (fp32 SIMT)
    k_nodecat<<<(NN*64+255)/256, 256>>>(h);
    k_xout<<<(NN*CC*3+255)/256, 256>>>(x, outX);
    kgemm<256,1><<<304,256>>>((const float*)p_ncat, n1W, n1B, (float*)p_rfeat, NN, TN128);
    kgemm<128,0><<<304,256>>>((const float*)p_rfeat, n2W, n2B, (float*)p_ef, NN, TN128);
    k_ln<<<NN, 128>>>(h, lng, lnb, outH);
}

// round 9
// speedup vs baseline: 5.4562x; 1.0129x over previous
#include <cuda_runtime.h>
#include <cuda_bf16.h>
#include <math.h>
#include <stdint.h>

#define NN 20000
#define NE 320000
#define CC 14
#define TE128 (NE/128)              // 2500
#define TN128 ((NN+127)/128)        // 157

// ---------------- scratch ----------------
__device__ __align__(16) float g_radial[(size_t)NE*128];  // bf16 [E][256] = radial*rinv
__device__ __align__(16) float g_ef1[(size_t)NE*64];      // bf16 [E][128] e1 out
__device__ float g_rfeat[(size_t)NN*128];   // fp32 node n1 out
__device__ float g_ef[(size_t)NN*128];      // fp32 node n2 out
__device__ float g_rinv[NE];
__device__ float g_csum[NN];
__device__ float g_pool3[NN*3];
__device__ float g_aggsum[(size_t)NN*128];
__device__ float g_cnt_col[NN];
__device__ float g_xsum[NN*CC*3];
__device__ float g_cnt_row[NN];
__device__ float g_ncat[(size_t)NN*256];
__device__ __align__(16) float g_hbf[NN*64];      // bf16 h
__device__ __align__(16) float g_abf[NN*112];     // bf16 attr
__device__ __align__(16) float g_waug[128*272];   // bf16 [128][544] augmented e1 weight
__device__ __align__(16) float g_we2[128*64];     // bf16 e2W
__device__ __align__(16) float g_wc1[128*64];     // bf16 c1W

__device__ __forceinline__ float sigm(float v){ return 1.f/(1.f+__expf(-v)); }
__device__ __forceinline__ float silu_(float v){ return v*sigm(v); }
__device__ __forceinline__ uint32_t pk2(float lo, float hi){
    __nv_bfloat162 t = __floats2bfloat162_rn(lo, hi);
    return *(uint32_t*)&t;
}
__device__ __forceinline__ void mma16(float* c, const uint32_t* a, const uint32_t* b){
    asm volatile("mma.sync.aligned.m16n8k16.row.col.f32.bf16.bf16.f32 "
        "{%0,%1,%2,%3}, {%4,%5,%6,%7}, {%8,%9}, {%0,%1,%2,%3};"
        : "+f"(c[0]),"+f"(c[1]),"+f"(c[2]),"+f"(c[3])
        : "r"(a[0]),"r"(a[1]),"r"(a[2]),"r"(a[3]), "r"(b[0]),"r"(b[1]));
}

// ---------------- zero accumulators ----------------
__global__ void k_zero(){
    int i = blockIdx.x*blockDim.x + threadIdx.x;
    const int A = NN*128, B = A+NN, D = B+NN*CC*3, T = D+NN;
    if(i >= T) return;
    if(i < A) g_aggsum[i]=0.f;
    else if(i < B) g_cnt_col[i-A]=0.f;
    else if(i < D) g_xsum[i-B]=0.f;
    else g_cnt_row[i-D]=0.f;
}

// ---------------- node prep ----------------
__global__ void k_prep(const float* __restrict__ x, const float* __restrict__ cw){
    int n = blockIdx.x*blockDim.x + threadIdx.x;
    if(n >= NN) return;
    float cnt=0.f, px=0.f, py=0.f, pz=0.f;
    #pragma unroll
    for(int i=0;i<CC;i++){
        float w = cw[n*CC+i];
        if(w != 0.f){
            cnt += 1.f;
            const float* xp = &x[(n*CC+i)*3];
            px += xp[0]; py += xp[1]; pz += xp[2];
        }
    }
    g_csum[n] = cnt;
    float inv = 1.f/cnt;
    g_pool3[n*3+0]=px*inv; g_pool3[n*3+1]=py*inv; g_pool3[n*3+2]=pz*inv;
}

// ---------------- h -> bf16 ----------------
__global__ void k_hconv(const float* __restrict__ h){
    int i = blockIdx.x*blockDim.x + threadIdx.x;
    if(i >= NN*64) return;
    float2 v = ((const float2*)h)[i];
    ((uint32_t*)g_hbf)[i] = pk2(v.x, v.y);
}
// ---------------- attr -> bf16 ----------------
__global__ void k_aconv(const float* __restrict__ attr){
    int i = blockIdx.x*blockDim.x + threadIdx.x;
    if(i >= NN*112) return;
    float2 v = ((const float2*)attr)[i];
    ((uint32_t*)g_abf)[i] = pk2(v.x, v.y);
}
// ---------------- e2W / c1W -> bf16 ----------------
__global__ void k_wcvt(const float* __restrict__ e2W, const float* __restrict__ c1W){
    int i = blockIdx.x*blockDim.x + threadIdx.x;
    if(i >= 2*128*64) return;
    if(i < 128*64){ float2 v=((const float2*)e2W)[i]; ((uint32_t*)g_we2)[i]=pk2(v.x,v.y); }
    else { int j=i-128*64; float2 v=((const float2*)c1W)[j]; ((uint32_t*)g_wc1)[j]=pk2(v.x,v.y); }
}

// ---------------- build augmented e1 weight (bf16, 272 kp = 544 k) ----------
__global__ void k_waug(const float* __restrict__ e1W, const float* __restrict__ radW,
                       const float* __restrict__ radB){
    __shared__ float s[128];
    int n = blockIdx.x, tid = threadIdx.x;
    if(tid < 128) s[tid] = e1W[n*384 + 256 + tid];
    __syncthreads();
    uint32_t* out = (uint32_t*)g_waug + n*272;
    if(tid < 128) out[tid] = pk2(e1W[n*384 + 2*tid], e1W[n*384 + 2*tid + 1]);
    else if(tid-128 < 128){
        int kpl = tid-128;
        int kk = 2*kpl;
        float d0=0.f, d1=0.f;
        #pragma unroll 4
        for(int j=0;j<128;j++){
            float sj = s[j];
            d0 += sj*radW[j*256+kk];
            d1 += sj*radW[j*256+kk+1];
        }
        out[128+kpl] = pk2(d0,d1);
    }
    if(tid==0){
        float bc=0.f;
        for(int j=0;j<128;j++) bc += s[j]*radB[j];
        out[256] = pk2(bc, 0.f);
    }
    if(tid>=1 && tid<16) out[256+tid] = 0u;
}

// ---------------- per-edge geometry (warp/edge), bf16 attr in -------------
#define GS 992
__global__ void k_geom(const float* __restrict__ x, const int* __restrict__ row,
                       const int* __restrict__ col, const float* __restrict__ cw){
    __shared__ float sm[8][GS];
    int warp = threadIdx.x>>5, lane = threadIdx.x&31;
    int e = blockIdx.x*8 + warp;
    if(e >= NE) return;
    float* s = sm[warp];
    int r = row[e], c = col[e];
    const int oCWR=0,oCWC=14,oXR=28,oXC=70,oAR=112,oAC=336,oM=560,oT=756;
    const uint32_t* ab = (const uint32_t*)g_abf;
    if(lane < CC){ s[oCWR+lane]=cw[r*CC+lane]; s[oCWC+lane]=cw[c*CC+lane]; }
    for(int i=lane;i<42;i+=32){ s[oXR+i]=x[r*42+i]; s[oXC+i]=x[c*42+i]; }
    for(int i=lane;i<112;i+=32){
        uint32_t ur = ab[r*112+i], uc = ab[c*112+i];
        __nv_bfloat162 br = *(__nv_bfloat162*)&ur;
        __nv_bfloat162 bc = *(__nv_bfloat162*)&uc;
        s[oAR+2*i]=__low2float(br); s[oAR+2*i+1]=__high2float(br);
        s[oAC+2*i]=__low2float(bc); s[oAC+2*i+1]=__high2float(bc);
    }
    __syncwarp();
    for(int idx=lane; idx<196; idx+=32){
        int i = idx/14, j = idx - i*14;
        float dx = s[oXR+i*3+0]-s[oXC+j*3+0];
        float dy = s[oXR+i*3+1]-s[oXC+j*3+1];
        float dz = s[oXR+i*3+2]-s[oXC+j*3+2];
        float d = sqrtf(dx*dx+dy*dy+dz*dz);
        s[oM+idx] = d * s[oCWR+i] * s[oCWC+j];
    }
    __syncwarp();
    int b = lane&15, hh = lane>>4;
    {
        float acj[CC];
        #pragma unroll
        for(int j=0;j<CC;j++) acj[j] = s[oAC + j*16 + b];
        #pragma unroll
        for(int i0=0;i0<7;i0++){
            int i = hh*7 + i0;
            float t = 0.f;
            #pragma unroll
            for(int j=0;j<CC;j++) t += s[oM + i*14 + j]*acj[j];
            s[oT + i*16 + b] = t;
        }
    }
    __syncwarp();
    float racc[8] = {0,0,0,0,0,0,0,0};
    {
        float tb[CC];
        #pragma unroll
        for(int i=0;i<CC;i++) tb[i] = s[oT + i*16 + b];
        #pragma unroll
        for(int i=0;i<CC;i++){
            float tv = tb[i];
            #pragma unroll
            for(int q=0;q<8;q++) racc[q] += s[oAR + i*16 + hh*8 + q]*tv;
        }
    }
    float sq = 0.f;
    #pragma unroll
    for(int q=0;q<8;q++) sq += racc[q]*racc[q];
    #pragma unroll
    for(int o=16;o>0;o>>=1) sq += __shfl_xor_sync(0xffffffffu, sq, o);
    float rinv = 1.f/(sqrtf(sq)+1.f);
    __nv_bfloat16* go = (__nv_bfloat16*)g_radial + (size_t)e*256;
    #pragma unroll
    for(int q=0;q<8;q++) go[(hh*8+q)*16 + b] = __float2bfloat16(racc[q]*rinv);
    if(lane==0) g_rinv[e] = rinv;
}

// ===== e1 GEMM: K=544, BK=32, 3-stage smem ring, prefetch distance 2 =====
#define E1SM 53760
__global__ void __launch_bounds__(256,2) k_e1(
    const float* __restrict__ e1B, const int* __restrict__ rowi,
    const int* __restrict__ coli, int tiles)
{
    extern __shared__ uint32_t dsm[];
    uint32_t* SA = dsm;                 // 3*16*136
    uint32_t* SW = dsm + 6528;          // 3*16*136
    int* sRow = (int*)(dsm + 13056);
    int* sCol = sRow + 128;
    float* sBias = (float*)(sCol + 128);
    const int tid=threadIdx.x, wid=tid>>5, lane=tid&31;
    const int warpM=(wid&3)*32, warpN=(wid>>2)*64;
    const int ee=tid>>1, q=tid&1;
    const int r4=lane>>2, c4=lane&3;
    const uint32_t* hbf=(const uint32_t*)g_hbf;
    const uint32_t* rad=(const uint32_t*)g_radial;
    const uint32_t* waug=(const uint32_t*)g_waug;
    uint32_t* Obf=(uint32_t*)g_ef1;
    if(tid<128) sBias[tid]=e1B[tid];

    for(int tile=blockIdx.x; tile<tiles; tile+=gridDim.x){
        if(tid<128){ sRow[tid]=rowi[tile*128+tid]; sCol[tid]=coli[tile*128+tid]; }
        __syncthreads();
        const int rg = tile*128 + ee;
        auto ldA = [&](int kt, uint4& u0, uint4& u1){
            const int kp = kt*16 + q*8;
            if(kp < 64){ const uint32_t* p=&hbf[sRow[ee]*64+kp];
                u0=*(const uint4*)p; u1=*(const uint4*)(p+4); }
            else if(kp < 128){ const uint32_t* p=&hbf[sCol[ee]*64+(kp-64)];
                u0=*(const uint4*)p; u1=*(const uint4*)(p+4); }
            else if(kp < 256){ const uint32_t* p=&rad[(size_t)rg*128+(kp-128)];
                u0=*(const uint4*)p; u1=*(const uint4*)(p+4); }
            else if(kp == 256){ u0=make_uint4(pk2(g_rinv[rg],0.f),0u,0u,0u);
                u1=make_uint4(0u,0u,0u,0u); }
            else { u0=make_uint4(0u,0u,0u,0u); u1=u0; }
        };
        auto ldW = [&](int kt, uint4& u0, uint4& u1){
            const uint32_t* p=&waug[ee*272 + kt*16 + q*8];
            u0=*(const uint4*)p; u1=*(const uint4*)(p+4);
        };
        auto sts = [&](int b, uint4 a0, uint4 a1, uint4 w0, uint4 w1){
            uint32_t* pa=&SA[b*2176 + (q*8)*136 + ee];
            pa[0]=a0.x; pa[136]=a0.y; pa[272]=a0.z; pa[408]=a0.w;
            pa[544]=a1.x; pa[680]=a1.y; pa[816]=a1.z; pa[952]=a1.w;
            uint32_t* pw=&SW[b*2176 + (q*8)*136 + ee];
            pw[0]=w0.x; pw[136]=w0.y; pw[272]=w0.z; pw[408]=w0.w;
            pw[544]=w1.x; pw[680]=w1.y; pw[816]=w1.z; pw[952]=w1.w;
        };

        float acc[2][8][4];
        #pragma unroll
        for(int am=0;am<2;am++)
            #pragma unroll
            for(int bn=0;bn<8;bn++)
                #pragma unroll
                for(int i=0;i<4;i++) acc[am][bn][i]=0.f;

        uint4 a0,a1,w0,w1;
        ldA(0,a0,a1); ldW(0,w0,w1); sts(0,a0,a1,w0,w1);
        ldA(1,a0,a1); ldW(1,w0,w1); sts(1,a0,a1,w0,w1);
        __syncthreads();

        #pragma unroll 1
        for(int kt=0; kt<17; kt++){
            bool pf = kt < 15;
            if(pf){ ldA(kt+2,a0,a1); ldW(kt+2,w0,w1); }
            const uint32_t* Ab=&SA[(kt%3)*2176];
            const uint32_t* Wb=&SW[(kt%3)*2176];
            #pragma unroll
            for(int g=0; g<2; g++){
                uint32_t bfr[8][2];
                #pragma unroll
                for(int bn=0;bn<8;bn++){
                    int n = warpN + bn*8 + r4;
                    bfr[bn][0] = Wb[(g*8+c4)*136 + n];
                    bfr[bn][1] = Wb[(g*8+c4+4)*136 + n];
                }
                #pragma unroll
                for(int am=0;am<2;am++){
                    int m0 = warpM + am*16 + r4;
                    uint32_t af[4] = { Ab[(g*8+c4)*136+m0], Ab[(g*8+c4)*136+m0+8],
                                       Ab[(g*8+c4+4)*136+m0], Ab[(g*8+c4+4)*136+m0+8] };
                    #pragma unroll
                    for(int bn=0;bn<8;bn++) mma16(acc[am][bn], af, bfr[bn]);
                }
            }
            if(pf) sts((kt+2)%3, a0,a1,w0,w1);
            __syncthreads();
        }

        #pragma unroll
        for(int am=0;am<2;am++)
            #pragma unroll
            for(int hf=0;hf<2;hf++){
                int rl = warpM + am*16 + r4 + hf*8;
                int rgo = tile*128 + rl;
                uint32_t* op = &Obf[(size_t)rgo*64];
                #pragma unroll
                for(int bn=0;bn<8;bn++){
                    int c0 = warpN + bn*8 + c4*2;
                    float v0 = silu_(acc[am][bn][hf*2]   + sBias[c0]);
                    float v1 = silu_(acc[am][bn][hf*2+1] + sBias[c0+1]);
                    op[c0>>1] = pk2(v0, v1);
                }
            }
        __syncthreads();
    }
}

// ===== fused e2 + gate + agg + c1 + c2 + roller + trans scatter ==========
// 1 CTA/SM persistent, 182 KB smem: weights resident, A double-buffered.
#define E2SM 181824
__global__ void __launch_bounds__(256) k_e2c1(
    const float* __restrict__ e2B, const float* __restrict__ c1B,
    const float* __restrict__ c2Wf, const float* __restrict__ c2bf,
    const int* __restrict__ rowi, const int* __restrict__ coli,
    const float* __restrict__ attWg, const float* __restrict__ attbg,
    const float* __restrict__ x,
    float* __restrict__ agg, float* __restrict__ cnt, int tiles)
{
    extern __shared__ uint32_t dsm[];
    uint32_t* SA   = dsm;            // 2 x 64x136
    uint32_t* SW2  = dsm + 17408;    // 64x136
    uint32_t* SW3  = dsm + 26112;    // 64x136
    uint32_t* SEF  = dsm + 34816;    // 64x136 (phase C: sCh fp32 128x16)
    uint32_t* SC2P = dsm + 43520;    // 64x16
    int*   sRow   = (int*)(dsm + 44544);
    int*   sCol   = sRow + 128;
    float* sBias  = (float*)(sCol + 128);
    float* sBias2 = sBias + 128;
    float* sAtt   = sBias2 + 128;
    float* sDot   = sAtt + 128;      // 256
    float* scb    = sDot + 256;      // 16
    const int tid=threadIdx.x, wid=tid>>5, lane=tid&31;
    const int warpM=(wid&3)*32, warpN=(wid>>2)*64;
    const int r4=lane>>2, c4=lane&3;
    const uint32_t* Abf=(const uint32_t*)g_ef1;
    const uint32_t* W2g=(const uint32_t*)g_we2;
    const uint32_t* W3g=(const uint32_t*)g_wc1;

    // one-time weight preload
    for(int idx=tid; idx<128*64; idx+=256){
        int n = idx>>6, kp = idx&63;
        SW2[kp*136+n] = W2g[idx];
        SW3[kp*136+n] = W3g[idx];
    }
    for(int idx=tid; idx<64*16; idx+=256){
        int kp = idx>>4, n = idx&15;
        SC2P[idx] = (n<14)? pk2(c2Wf[n*128+2*kp], c2Wf[n*128+2*kp+1]) : 0u;
    }
    if(tid<16) scb[tid] = (tid<14)? c2bf[tid] : 0.f;
    if(tid<128){ sBias[tid]=e2B[tid]; sBias2[tid]=c1B[tid]; sAtt[tid]=attWg[tid]; }
    const float attb = attbg[0];

    auto ldAfull = [&](int t, uint4* v){
        const uint32_t* p = &Abf[(size_t)(t*128 + (tid>>1))*64 + (tid&1)*32];
        #pragma unroll
        for(int j=0;j<8;j++) v[j] = ((const uint4*)p)[j];
    };
    auto stsA = [&](int b, const uint4* v){
        uint32_t* base = &SA[b*8704 + ((tid&1)*32)*136 + (tid>>1)];
        #pragma unroll
        for(int j=0;j<8;j++){
            base[(j*4+0)*136]=v[j].x; base[(j*4+1)*136]=v[j].y;
            base[(j*4+2)*136]=v[j].z; base[(j*4+3)*136]=v[j].w;
        }
    };
    float acc[2][8][4];
    auto gemm128 = [&](const uint32_t* Ab, const uint32_t* Wb){
        #pragma unroll
        for(int g=0; g<8; g++){
            uint32_t bfr[8][2];
            #pragma unroll
            for(int bn=0;bn<8;bn++){
                int n = warpN + bn*8 + r4;
                bfr[bn][0] = Wb[(g*8+c4)*136 + n];
                bfr[bn][1] = Wb[(g*8+c4+4)*136 + n];
            }
            #pragma unroll
            for(int am=0;am<2;am++){
                int m0 = warpM + am*16 + r4;
                uint32_t af[4] = { Ab[(g*8+c4)*136+m0], Ab[(g*8+c4)*136+m0+8],
                                   Ab[(g*8+c4+4)*136+m0], Ab[(g*8+c4+4)*136+m0+8] };
                #pragma unroll
                for(int bn=0;bn<8;bn++) mma16(acc[am][bn], af, bfr[bn]);
            }
        }
    };

    { uint4 v[8]; ldAfull(blockIdx.x, v); stsA(0, v); }
    int pb = 0;

    for(int tile=blockIdx.x; tile<tiles; tile+=gridDim.x){
        if(tid<128){ sRow[tid]=rowi[tile*128+tid]; sCol[tid]=coli[tile*128+tid]; }
        __syncthreads();                       // A[pb] + indices ready
        int nt = tile + gridDim.x;
        bool pf = nt < tiles;
        uint4 an[8];
        if(pf) ldAfull(nt, an);

        // ---- phase A: e2 GEMM ----
        #pragma unroll
        for(int am=0;am<2;am++)
            #pragma unroll
            for(int bn=0;bn<8;bn++)
                #pragma unroll
                for(int i=0;i<4;i++) acc[am][bn][i]=0.f;
        gemm128(&SA[pb*8704], SW2);
        if(pf) stsA(pb^1, an);

        // epilogue A: bias + silu + attention gate
        #pragma unroll
        for(int am=0;am<2;am++)
            #pragma unroll
            for(int bn=0;bn<8;bn++){
                int c0 = warpN + bn*8 + c4*2;
                float* a = acc[am][bn];
                a[0]=silu_(a[0]+sBias[c0]);   a[1]=silu_(a[1]+sBias[c0+1]);
                a[2]=silu_(a[2]+sBias[c0]);   a[3]=silu_(a[3]+sBias[c0+1]);
            }
        {
            float dot[2][2] = {{0.f,0.f},{0.f,0.f}};
            #pragma unroll
            for(int am=0;am<2;am++)
                #pragma unroll
                for(int bn=0;bn<8;bn++){
                    int c0 = warpN + bn*8 + c4*2;
                    float w0=sAtt[c0], w1=sAtt[c0+1];
                    dot[am][0] += acc[am][bn][0]*w0 + acc[am][bn][1]*w1;
                    dot[am][1] += acc[am][bn][2]*w0 + acc[am][bn][3]*w1;
                }
            #pragma unroll
            for(int am=0;am<2;am++)
                #pragma unroll
                for(int hf=0;hf<2;hf++){
                    dot[am][hf] += __shfl_xor_sync(0xffffffffu, dot[am][hf], 1);
                    dot[am][hf] += __shfl_xor_sync(0xffffffffu, dot[am][hf], 2);
                }
            if(c4==0){
                #pragma unroll
                for(int am=0;am<2;am++){
                    sDot[(wid>>2)*128 + warpM+am*16+r4]   = dot[am][0];
                    sDot[(wid>>2)*128 + warpM+am*16+r4+8] = dot[am][1];
                }
            }
            __syncthreads();
            #pragma unroll
            for(int am=0;am<2;am++)
                #pragma unroll
                for(int hf=0;hf<2;hf++){
                    int rl = warpM + am*16 + r4 + hf*8;
                    float g = sigm(sDot[rl] + sDot[128+rl] + attb);
                    #pragma unroll
                    for(int bn=0;bn<8;bn++){
                        acc[am][bn][hf*2]   *= g;
                        acc[am][bn][hf*2+1] *= g;
                    }
                }
        }
        // scatter agg + stage ef into SEF
        #pragma unroll
        for(int am=0;am<2;am++)
            #pragma unroll
            for(int hf=0;hf<2;hf++){
                int rl = warpM + am*16 + r4 + hf*8;
                int cc = sCol[rl];
                float* ag = &agg[(size_t)cc*128];
                #pragma unroll
                for(int bn=0;bn<8;bn++){
                    int c0 = warpN + bn*8 + c4*2;
                    float v0 = acc[am][bn][hf*2], v1 = acc[am][bn][hf*2+1];
                    atomicAdd(ag+c0,   v0);
                    atomicAdd(ag+c0+1, v1);
                    SEF[(c0>>1)*136 + rl] = pk2(v0, v1);
                }
                if(warpN==0 && c4==0) atomicAdd(&cnt[cc], 1.f);
            }
        __syncthreads();                       // SEF ready

        // ---- phase B: c1 GEMM from SEF ----
        #pragma unroll
        for(int am=0;am<2;am++)
            #pragma unroll
            for(int bn=0;bn<8;bn++)
                #pragma unroll
                for(int i=0;i<4;i++) acc[am][bn][i]=0.f;
        gemm128(SEF, SW3);
        // epilogue B: hid = silu(acc+bias2) -> SA[pb] (bf16 [kp][m])
        #pragma unroll
        for(int am=0;am<2;am++)
            #pragma unroll
            for(int hf=0;hf<2;hf++){
                int rl = warpM + am*16 + r4 + hf*8;
                #pragma unroll
                for(int bn=0;bn<8;bn++){
                    int c0 = warpN + bn*8 + c4*2;
                    float v0 = silu_(acc[am][bn][hf*2]   + sBias2[c0]);
                    float v1 = silu_(acc[am][bn][hf*2+1] + sBias2[c0+1]);
                    SA[pb*8704 + (c0>>1)*136 + rl] = pk2(v0, v1);
                }
            }
        __syncthreads();                       // hid tile ready

        // ---- phase C: ch = hid @ c2W^T (N=16 MMA, warps 0..3) ----
        if(wid < 4){
            float accC[2][2][4];
            #pragma unroll
            for(int am=0;am<2;am++)
                #pragma unroll
                for(int bn=0;bn<2;bn++)
                    #pragma unroll
                    for(int i=0;i<4;i++) accC[am][bn][i]=0.f;
            #pragma unroll
            for(int g=0; g<8; g++){
                uint32_t bfr[2][2];
                #pragma unroll
                for(int bn=0;bn<2;bn++){
                    int n = bn*8 + r4;
                    bfr[bn][0] = SC2P[(g*8+c4)*16 + n];
                    bfr[bn][1] = SC2P[(g*8+c4+4)*16 + n];
                }
                #pragma unroll
                for(int am=0;am<2;am++){
                    int m0 = warpM + am*16 + r4;
                    uint32_t af[4] = { SA[pb*8704+(g*8+c4)*136+m0],
                                       SA[pb*8704+(g*8+c4)*136+m0+8],
                                       SA[pb*8704+(g*8+c4+4)*136+m0],
                                       SA[pb*8704+(g*8+c4+4)*136+m0+8] };
                    #pragma unroll
                    for(int bn=0;bn<2;bn++) mma16(accC[am][bn], af, bfr[bn]);
                }
            }
            float* sCh = (float*)SEF;
            #pragma unroll
            for(int am=0;am<2;am++)
                #pragma unroll
                for(int hf=0;hf<2;hf++){
                    int rl = warpM + am*16 + r4 + hf*8;
                    #pragma unroll
                    for(int bn=0;bn<2;bn++){
                        int c0 = bn*8 + c4*2;
                        sCh[rl*16+c0]   = accC[am][bn][hf*2];
                        sCh[rl*16+c0+1] = accC[am][bn][hf*2+1];
                    }
                }
        }
        __syncthreads();                       // sCh ready

        // ---- roller pooling + trans scatter (one thread per row) ----
        if(tid < 128){
            const float* sCh = (const float*)SEF;
            int rl = tid;
            int r = sRow[rl], c = sCol[rl];
            float P[15]; P[0]=0.f;
            #pragma unroll
            for(int j=0;j<14;j++) P[j+1] = P[j] + sCh[rl*16+j] + scb[j];
            int cs = (int)(g_csum[r]+0.5f);
            int w = 15 - cs;
            float invw = 1.f/(float)w;
            float px=g_pool3[c*3], py=g_pool3[c*3+1], pz=g_pool3[c*3+2];
            #pragma unroll
            for(int i=0;i<14;i++){
                int e2 = min(i+w, 14);
                float pooled = (P[e2]-P[i])*invw;
                const float* xp = &x[((size_t)r*14+i)*3];
                atomicAdd(&g_xsum[(r*14+i)*3+0], (xp[0]-px)*pooled);
                atomicAdd(&g_xsum[(r*14+i)*3+1], (xp[1]-py)*pooled);
                atomicAdd(&g_xsum[(r*14+i)*3+2], (xp[2]-pz)*pooled);
            }
            atomicAdd(&g_cnt_row[r], 1.f);
        }
        __syncthreads();                       // protect SEF/sRow for next tile
        pb ^= 1;
    }
}

// ======= SIMT GEMM (node MLP, fp32, small M with bounds) =======
template<int K, int MODE>
__global__ void __launch_bounds__(256,2) kgemm(
    const float* __restrict__ A, const float* __restrict__ Wg,
    const float* __restrict__ bg, float* __restrict__ O, int M, int tiles)
{
    __shared__ float sA[2][16][128];
    __shared__ float sW[2][16][128];
    const int tid = threadIdx.x, tx = tid&15, ty = tid>>4;
    const int ee = tid>>1, q = tid&1, kq = q*8;
    float bb[8];
    #pragma unroll
    for(int i=0;i<8;i++) bb[i]=bg[tx*8+i];

    for(int tile=blockIdx.x; tile<tiles; tile+=gridDim.x){
        float4 pa0, pa1, pw0, pw1;
        auto ldA = [&](int kt, float4& v0, float4& v1){
            int rg = tile*128 + ee;
            if(rg < M){
                const float* p = &A[(size_t)rg*K + kt*16 + kq];
                v0 = *(const float4*)p; v1 = *(const float4*)(p+4);
            } else { v0=v1=make_float4(0,0,0,0); }
        };
        auto ldW = [&](int kt, float4& v0, float4& v1){
            const float* p = &Wg[(size_t)ee*K + kt*16 + kq];
            v0 = *(const float4*)p; v1 = *(const float4*)(p+4);
        };
        auto sts = [&](int buf, float4 a0, float4 a1, float4 w0, float4 w1){
            sA[buf][kq+0][ee]=a0.x; sA[buf][kq+1][ee]=a0.y;
            sA[buf][kq+2][ee]=a0.z; sA[buf][kq+3][ee]=a0.w;
            sA[buf][kq+4][ee]=a1.x; sA[buf][kq+5][ee]=a1.y;
            sA[buf][kq+6][ee]=a1.z; sA[buf][kq+7][ee]=a1.w;
            sW[buf][kq+0][ee]=w0.x; sW[buf][kq+1][ee]=w0.y;
            sW[buf][kq+2][ee]=w0.z; sW[buf][kq+3][ee]=w0.w;
            sW[buf][kq+4][ee]=w1.x; sW[buf][kq+5][ee]=w1.y;
            sW[buf][kq+6][ee]=w1.z; sW[buf][kq+7][ee]=w1.w;
        };
        ldA(0, pa0, pa1); ldW(0, pw0, pw1);
        sts(0, pa0, pa1, pw0, pw1);
        __syncthreads();
        float acc[8][8];
        #pragma unroll
        for(int j=0;j<8;j++)
            #pragma unroll
            for(int i=0;i<8;i++) acc[j][i]=0.f;
        const int KT = K/16;
        #pragma unroll 1
        for(int kt=0; kt<KT; kt++){
            if(kt+1 < KT){ ldA(kt+1, pa0, pa1); ldW(kt+1, pw0, pw1); }
            const int buf = kt&1;
            #pragma unroll
            for(int k=0;k<16;k++){
                float4 a0 = *(const float4*)&sA[buf][k][ty*8];
                float4 a1 = *(const float4*)&sA[buf][k][ty*8+4];
                float4 w0 = *(const float4*)&sW[buf][k][tx*8];
                float4 w1 = *(const float4*)&sW[buf][k][tx*8+4];
                float av[8]={a0.x,a0.y,a0.z,a0.w,a1.x,a1.y,a1.z,a1.w};
                float wv[8]={w0.x,w0.y,w0.z,w0.w,w1.x,w1.y,w1.z,w1.w};
                #pragma unroll
                for(int j=0;j<8;j++)
                    #pragma unroll
                    for(int i=0;i<8;i++) acc[j][i] += av[j]*wv[i];
            }
            if(kt+1 < KT) sts((kt+1)&1, pa0, pa1, pw0, pw1);
            __syncthreads();
        }
        #pragma unroll
        for(int j=0;j<8;j++){
            int rg = tile*128 + ty*8 + j;
            if(rg >= M) continue;
            float v[8];
            #pragma unroll
            for(int i=0;i<8;i++){ v[i]=acc[j][i]+bb[i]; if(MODE>=1) v[i]=silu_(v[i]); }
            *(float4*)&O[(size_t)rg*128+tx*8]   = make_float4(v[0],v[1],v[2],v[3]);
            *(float4*)&O[(size_t)rg*128+tx*8+4] = make_float4(v[4],v[5],v[6],v[7]);
        }
    }
}

// ---------------- node concat [h | agg/cnt] ----------------
__global__ void k_nodecat(const float* __restrict__ h){
    int idx = blockIdx.x*blockDim.x + threadIdx.x;
    if(idx >= NN*64) return;
    int n = idx>>6, g = idx&63;
    float4 v;
    if(g<32) v = *(const float4*)&h[(size_t)n*128 + g*4];
    else{
        float inv = 1.f/fmaxf(g_cnt_col[n],1.f);
        const float* a = &g_aggsum[(size_t)n*128 + (g-32)*4];
        v = make_float4(a[0]*inv,a[1]*inv,a[2]*inv,a[3]*inv);
    }
    *(float4*)&g_ncat[(size_t)n*256 + g*4] = v;
}

// ---------------- x_out ----------------
__global__ void k_xout(const float* __restrict__ x, float* __restrict__ xout){
    int idx = blockIdx.x*blockDim.x + threadIdx.x;
    if(idx >= NN*CC*3) return;
    int n = idx/(CC*3);
    xout[idx] = x[idx] + g_xsum[idx]/fmaxf(g_cnt_row[n],1.f);
}

// ---------------- layernorm ----------------
__global__ void k_ln(const float* __restrict__ h, const float* __restrict__ lng,
                     const float* __restrict__ lnb, float* __restrict__ out){
    __shared__ float red[8];
    int n = blockIdx.x, t = threadIdx.x;
    float y = h[(size_t)n*128+t] + g_ef[(size_t)n*128+t];
    float s = y;
    #pragma unroll
    for(int o=16;o>0;o>>=1) s += __shfl_xor_sync(0xffffffffu, s, o);
    if((t&31)==0) red[t>>5] = s;
    __syncthreads();
    float mu = (red[0]+red[1]+red[2]+red[3]) * (1.f/128.f);
    float d = y - mu;
    float v = d*d;
    #pragma unroll
    for(int o=16;o>0;o>>=1) v += __shfl_xor_sync(0xffffffffu, v, o);
    if((t&31)==0) red[4+(t>>5)] = v;
    __syncthreads();
    float var = (red[4]+red[5]+red[6]+red[7]) * (1.f/128.f);
    out[(size_t)n*128+t] = d*rsqrtf(var+1e-5f)*lng[t] + lnb[t];
}

// ======================= host launcher =======================
extern "C" void kernel_launch(void* const* d_in, const int* in_sizes, int n_in,
                              void* d_out, int out_size){
    const float* h    = (const float*)d_in[0];
    const float* x    = (const float*)d_in[1];
    const int*   row  = (const int*)  d_in[2];
    const int*   col  = (const int*)  d_in[3];
    const float* attr = (const float*)d_in[4];
    const float* cw   = (const float*)d_in[5];
    const float* radW = (const float*)d_in[6];  const float* radB = (const float*)d_in[7];
    const float* e1W  = (const float*)d_in[8];  const float* e1B  = (const float*)d_in[9];
    const float* e2W  = (const float*)d_in[10]; const float* e2B  = (const float*)d_in[11];
    const float* attW = (const float*)d_in[12]; const float* attB = (const float*)d_in[13];
    const float* c1W  = (const float*)d_in[14]; const float* c1B  = (const float*)d_in[15];
    const float* c2W  = (const float*)d_in[16]; const float* c2B  = (const float*)d_in[17];
    const float* n1W  = (const float*)d_in[18]; const float* n1B  = (const float*)d_in[19];
    const float* n2W  = (const float*)d_in[20]; const float* n2B  = (const float*)d_in[21];
    const float* lng  = (const float*)d_in[22]; const float* lnb  = (const float*)d_in[23];
    float* outH = (float*)d_out;
    float* outX = outH + (size_t)NN*128;

    void *p_rfeat,*p_ef,*p_ncat,*p_agg,*p_cntc;
    cudaGetSymbolAddress(&p_rfeat,  g_rfeat);
    cudaGetSymbolAddress(&p_ef,     g_ef);
    cudaGetSymbolAddress(&p_ncat,   g_ncat);
    cudaGetSymbolAddress(&p_agg,    g_aggsum);
    cudaGetSymbolAddress(&p_cntc,   g_cnt_col);

    cudaFuncSetAttribute(k_e1,   cudaFuncAttributeMaxDynamicSharedMemorySize, E1SM);
    cudaFuncSetAttribute(k_e2c1, cudaFuncAttributeMaxDynamicSharedMemorySize, E2SM);

    const int ZT = NN*128 + NN + NN*CC*3 + NN;
    k_zero<<<(ZT+255)/256, 256>>>();
    k_prep<<<(NN+255)/256, 256>>>(x, cw);
    k_hconv<<<(NN*64+255)/256, 256>>>(h);
    k_aconv<<<(NN*112+255)/256, 256>>>(attr);
    k_wcvt<<<(2*128*64+255)/256, 256>>>(e2W, c1W);
    k_waug<<<128, 256>>>(e1W, radW, radB);
    k_geom<<<NE/8, 256>>>(x, row, col, cw);

    // ef1(bf16) = silu([h_r|h_c|radial'|rinv] @ Waug^T + e1B)
    k_e1<<<304,256,E1SM>>>(e1B, row, col, TE128);
    // fused e2+gate+agg + c1 + c2 + roller + trans scatter
    k_e2c1<<<148,256,E2SM>>>(e2B, c1B, c2W, c2B, row, col, attW, attB,
                             x, (float*)p_agg, (float*)p_cntc, TE128);
    // node path (fp32 SIMT)
    k_nodecat<<<(NN*64+255)/256, 256>>>(h);
    k_xout<<<(NN*CC*3+255)/256, 256>>>(x, outX);
    kgemm<256,1><<<304,256>>>((const float*)p_ncat, n1W, n1B, (float*)p_rfeat, NN, TN128);
    kgemm<128,0><<<304,256>>>((const float*)p_rfeat, n2W, n2B, (float*)p_ef, NN, TN128);
    k_ln<<<NN, 128>>>(h, lng, lnb, outH);
}

// round 10
// speedup vs baseline: 5.6083x; 1.0279x over previous
#include <cuda_runtime.h>
#include <cuda_bf16.h>
#include <math.h>
#include <stdint.h>

#define NN 20000
#define NE 320000
#define CC 14
#define TE128 (NE/128)              // 2500
#define TN128 ((NN+127)/128)        // 157

// ---------------- scratch ----------------
__device__ __align__(16) float g_radial[(size_t)NE*128];  // bf16 [E][256] = radial*rinv
__device__ __align__(16) float g_ef1[(size_t)NE*64];      // bf16 [E][128] e1 out
__device__ float g_rinv[NE];
__device__ float g_csum[NN];
__device__ float g_pool3[NN*3];
__device__ float g_aggsum[(size_t)NN*128];
__device__ float g_cnt_col[NN];
__device__ float g_xsum[NN*CC*3];
__device__ float g_cnt_row[NN];
__device__ __align__(16) float g_hbf[NN*64];      // bf16 h
__device__ __align__(16) float g_abf[NN*112];     // bf16 attr
__device__ __align__(16) float g_waug[128*272];   // bf16 [128][544] augmented e1 weight
__device__ __align__(16) float g_we2[128*64];     // bf16 e2W
__device__ __align__(16) float g_wc1[128*64];     // bf16 c1W

__device__ __forceinline__ float sigm(float v){ return 1.f/(1.f+__expf(-v)); }
__device__ __forceinline__ float silu_(float v){ return v*sigm(v); }
__device__ __forceinline__ uint32_t pk2(float lo, float hi){
    __nv_bfloat162 t = __floats2bfloat162_rn(lo, hi);
    return *(uint32_t*)&t;
}
__device__ __forceinline__ void mma16(float* c, const uint32_t* a, const uint32_t* b){
    asm volatile("mma.sync.aligned.m16n8k16.row.col.f32.bf16.bf16.f32 "
        "{%0,%1,%2,%3}, {%4,%5,%6,%7}, {%8,%9}, {%0,%1,%2,%3};"
        : "+f"(c[0]),"+f"(c[1]),"+f"(c[2]),"+f"(c[3])
        : "r"(a[0]),"r"(a[1]),"r"(a[2]),"r"(a[3]), "r"(b[0]),"r"(b[1]));
}

// ---------------- zero accumulators ----------------
__global__ void k_zero(){
    int i = blockIdx.x*blockDim.x + threadIdx.x;
    const int A = NN*128, B = A+NN, D = B+NN*CC*3, T = D+NN;
    if(i >= T) return;
    if(i < A) g_aggsum[i]=0.f;
    else if(i < B) g_cnt_col[i-A]=0.f;
    else if(i < D) g_xsum[i-B]=0.f;
    else g_cnt_row[i-D]=0.f;
}

// ---------------- node prep ----------------
__global__ void k_prep(const float* __restrict__ x, const float* __restrict__ cw){
    int n = blockIdx.x*blockDim.x + threadIdx.x;
    if(n >= NN) return;
    float cnt=0.f, px=0.f, py=0.f, pz=0.f;
    #pragma unroll
    for(int i=0;i<CC;i++){
        float w = cw[n*CC+i];
        if(w != 0.f){
            cnt += 1.f;
            const float* xp = &x[(n*CC+i)*3];
            px += xp[0]; py += xp[1]; pz += xp[2];
        }
    }
    g_csum[n] = cnt;
    float inv = 1.f/cnt;
    g_pool3[n*3+0]=px*inv; g_pool3[n*3+1]=py*inv; g_pool3[n*3+2]=pz*inv;
}

// ---------------- h -> bf16 ----------------
__global__ void k_hconv(const float* __restrict__ h){
    int i = blockIdx.x*blockDim.x + threadIdx.x;
    if(i >= NN*64) return;
    float2 v = ((const float2*)h)[i];
    ((uint32_t*)g_hbf)[i] = pk2(v.x, v.y);
}
// ---------------- attr -> bf16 ----------------
__global__ void k_aconv(const float* __restrict__ attr){
    int i = blockIdx.x*blockDim.x + threadIdx.x;
    if(i >= NN*112) return;
    float2 v = ((const float2*)attr)[i];
    ((uint32_t*)g_abf)[i] = pk2(v.x, v.y);
}
// ---------------- e2W / c1W -> bf16 ----------------
__global__ void k_wcvt(const float* __restrict__ e2W, const float* __restrict__ c1W){
    int i = blockIdx.x*blockDim.x + threadIdx.x;
    if(i >= 2*128*64) return;
    if(i < 128*64){ float2 v=((const float2*)e2W)[i]; ((uint32_t*)g_we2)[i]=pk2(v.x,v.y); }
    else { int j=i-128*64; float2 v=((const float2*)c1W)[j]; ((uint32_t*)g_wc1)[j]=pk2(v.x,v.y); }
}

// ---------------- build augmented e1 weight (bf16, 272 kp = 544 k) ----------
__global__ void k_waug(const float* __restrict__ e1W, const float* __restrict__ radW,
                       const float* __restrict__ radB){
    __shared__ float s[128];
    int n = blockIdx.x, tid = threadIdx.x;
    if(tid < 128) s[tid] = e1W[n*384 + 256 + tid];
    __syncthreads();
    uint32_t* out = (uint32_t*)g_waug + n*272;
    if(tid < 128) out[tid] = pk2(e1W[n*384 + 2*tid], e1W[n*384 + 2*tid + 1]);
    else if(tid-128 < 128){
        int kpl = tid-128;
        int kk = 2*kpl;
        float d0=0.f, d1=0.f;
        #pragma unroll 4
        for(int j=0;j<128;j++){
            float sj = s[j];
            d0 += sj*radW[j*256+kk];
            d1 += sj*radW[j*256+kk+1];
        }
        out[128+kpl] = pk2(d0,d1);
    }
    if(tid==0){
        float bc=0.f;
        for(int j=0;j<128;j++) bc += s[j]*radB[j];
        out[256] = pk2(bc, 0.f);
    }
    if(tid>=1 && tid<16) out[256+tid] = 0u;
}

// ---------------- per-edge geometry (warp/edge), bf16 attr in -------------
#define GS 992
__global__ void k_geom(const float* __restrict__ x, const int* __restrict__ row,
                       const int* __restrict__ col, const float* __restrict__ cw){
    __shared__ float sm[8][GS];
    int warp = threadIdx.x>>5, lane = threadIdx.x&31;
    int e = blockIdx.x*8 + warp;
    if(e >= NE) return;
    float* s = sm[warp];
    int r = row[e], c = col[e];
    const int oCWR=0,oCWC=14,oXR=28,oXC=70,oAR=112,oAC=336,oM=560,oT=756;
    const uint32_t* ab = (const uint32_t*)g_abf;
    if(lane < CC){ s[oCWR+lane]=cw[r*CC+lane]; s[oCWC+lane]=cw[c*CC+lane]; }
    for(int i=lane;i<42;i+=32){ s[oXR+i]=x[r*42+i]; s[oXC+i]=x[c*42+i]; }
    for(int i=lane;i<112;i+=32){
        uint32_t ur = ab[r*112+i], uc = ab[c*112+i];
        __nv_bfloat162 br = *(__nv_bfloat162*)&ur;
        __nv_bfloat162 bc = *(__nv_bfloat162*)&uc;
        s[oAR+2*i]=__low2float(br); s[oAR+2*i+1]=__high2float(br);
        s[oAC+2*i]=__low2float(bc); s[oAC+2*i+1]=__high2float(bc);
    }
    __syncwarp();
    for(int idx=lane; idx<196; idx+=32){
        int i = idx/14, j = idx - i*14;
        float dx = s[oXR+i*3+0]-s[oXC+j*3+0];
        float dy = s[oXR+i*3+1]-s[oXC+j*3+1];
        float dz = s[oXR+i*3+2]-s[oXC+j*3+2];
        float d = sqrtf(dx*dx+dy*dy+dz*dz);
        s[oM+idx] = d * s[oCWR+i] * s[oCWC+j];
    }
    __syncwarp();
    int b = lane&15, hh = lane>>4;
    {
        float acj[CC];
        #pragma unroll
        for(int j=0;j<CC;j++) acj[j] = s[oAC + j*16 + b];
        #pragma unroll
        for(int i0=0;i0<7;i0++){
            int i = hh*7 + i0;
            float t = 0.f;
            #pragma unroll
            for(int j=0;j<CC;j++) t += s[oM + i*14 + j]*acj[j];
            s[oT + i*16 + b] = t;
        }
    }
    __syncwarp();
    float racc[8] = {0,0,0,0,0,0,0,0};
    {
        float tb[CC];
        #pragma unroll
        for(int i=0;i<CC;i++) tb[i] = s[oT + i*16 + b];
        #pragma unroll
        for(int i=0;i<CC;i++){
            float tv = tb[i];
            #pragma unroll
            for(int q=0;q<8;q++) racc[q] += s[oAR + i*16 + hh*8 + q]*tv;
        }
    }
    float sq = 0.f;
    #pragma unroll
    for(int q=0;q<8;q++) sq += racc[q]*racc[q];
    #pragma unroll
    for(int o=16;o>0;o>>=1) sq += __shfl_xor_sync(0xffffffffu, sq, o);
    float rinv = 1.f/(sqrtf(sq)+1.f);
    __nv_bfloat16* go = (__nv_bfloat16*)g_radial + (size_t)e*256;
    #pragma unroll
    for(int q=0;q<8;q++) go[(hh*8+q)*16 + b] = __float2bfloat16(racc[q]*rinv);
    if(lane==0) g_rinv[e] = rinv;
}

// ===== e1 GEMM: K=544, BK=32, 3-stage smem ring, prefetch distance 2 =====
#define E1SM 53760
__global__ void __launch_bounds__(256,2) k_e1(
    const float* __restrict__ e1B, const int* __restrict__ rowi,
    const int* __restrict__ coli, int tiles)
{
    extern __shared__ uint32_t dsm[];
    uint32_t* SA = dsm;                 // 3*16*136
    uint32_t* SW = dsm + 6528;          // 3*16*136
    int* sRow = (int*)(dsm + 13056);
    int* sCol = sRow + 128;
    float* sBias = (float*)(sCol + 128);
    const int tid=threadIdx.x, wid=tid>>5, lane=tid&31;
    const int warpM=(wid&3)*32, warpN=(wid>>2)*64;
    const int ee=tid>>1, q=tid&1;
    const int r4=lane>>2, c4=lane&3;
    const uint32_t* hbf=(const uint32_t*)g_hbf;
    const uint32_t* rad=(const uint32_t*)g_radial;
    const uint32_t* waug=(const uint32_t*)g_waug;
    uint32_t* Obf=(uint32_t*)g_ef1;
    if(tid<128) sBias[tid]=e1B[tid];

    for(int tile=blockIdx.x; tile<tiles; tile+=gridDim.x){
        if(tid<128){ sRow[tid]=rowi[tile*128+tid]; sCol[tid]=coli[tile*128+tid]; }
        __syncthreads();
        const int rg = tile*128 + ee;
        auto ldA = [&](int kt, uint4& u0, uint4& u1){
            const int kp = kt*16 + q*8;
            if(kp < 64){ const uint32_t* p=&hbf[sRow[ee]*64+kp];
                u0=*(const uint4*)p; u1=*(const uint4*)(p+4); }
            else if(kp < 128){ const uint32_t* p=&hbf[sCol[ee]*64+(kp-64)];
                u0=*(const uint4*)p; u1=*(const uint4*)(p+4); }
            else if(kp < 256){ const uint32_t* p=&rad[(size_t)rg*128+(kp-128)];
                u0=*(const uint4*)p; u1=*(const uint4*)(p+4); }
            else if(kp == 256){ u0=make_uint4(pk2(g_rinv[rg],0.f),0u,0u,0u);
                u1=make_uint4(0u,0u,0u,0u); }
            else { u0=make_uint4(0u,0u,0u,0u); u1=u0; }
        };
        auto ldW = [&](int kt, uint4& u0, uint4& u1){
            const uint32_t* p=&waug[ee*272 + kt*16 + q*8];
            u0=*(const uint4*)p; u1=*(const uint4*)(p+4);
        };
        auto sts = [&](int b, uint4 a0, uint4 a1, uint4 w0, uint4 w1){
            uint32_t* pa=&SA[b*2176 + (q*8)*136 + ee];
            pa[0]=a0.x; pa[136]=a0.y; pa[272]=a0.z; pa[408]=a0.w;
            pa[544]=a1.x; pa[680]=a1.y; pa[816]=a1.z; pa[952]=a1.w;
            uint32_t* pw=&SW[b*2176 + (q*8)*136 + ee];
            pw[0]=w0.x; pw[136]=w0.y; pw[272]=w0.z; pw[408]=w0.w;
            pw[544]=w1.x; pw[680]=w1.y; pw[816]=w1.z; pw[952]=w1.w;
        };

        float acc[2][8][4];
        #pragma unroll
        for(int am=0;am<2;am++)
            #pragma unroll
            for(int bn=0;bn<8;bn++)
                #pragma unroll
                for(int i=0;i<4;i++) acc[am][bn][i]=0.f;

        uint4 a0,a1,w0,w1;
        ldA(0,a0,a1); ldW(0,w0,w1); sts(0,a0,a1,w0,w1);
        ldA(1,a0,a1); ldW(1,w0,w1); sts(1,a0,a1,w0,w1);
        __syncthreads();

        #pragma unroll 1
        for(int kt=0; kt<17; kt++){
            bool pf = kt < 15;
            if(pf){ ldA(kt+2,a0,a1); ldW(kt+2,w0,w1); }
            const uint32_t* Ab=&SA[(kt%3)*2176];
            const uint32_t* Wb=&SW[(kt%3)*2176];
            #pragma unroll
            for(int g=0; g<2; g++){
                uint32_t bfr[8][2];
                #pragma unroll
                for(int bn=0;bn<8;bn++){
                    int n = warpN + bn*8 + r4;
                    bfr[bn][0] = Wb[(g*8+c4)*136 + n];
                    bfr[bn][1] = Wb[(g*8+c4+4)*136 + n];
                }
                #pragma unroll
                for(int am=0;am<2;am++){
                    int m0 = warpM + am*16 + r4;
                    uint32_t af[4] = { Ab[(g*8+c4)*136+m0], Ab[(g*8+c4)*136+m0+8],
                                       Ab[(g*8+c4+4)*136+m0], Ab[(g*8+c4+4)*136+m0+8] };
                    #pragma unroll
                    for(int bn=0;bn<8;bn++) mma16(acc[am][bn], af, bfr[bn]);
                }
            }
            if(pf) sts((kt+2)%3, a0,a1,w0,w1);
            __syncthreads();
        }

        #pragma unroll
        for(int am=0;am<2;am++)
            #pragma unroll
            for(int hf=0;hf<2;hf++){
                int rl = warpM + am*16 + r4 + hf*8;
                int rgo = tile*128 + rl;
                uint32_t* op = &Obf[(size_t)rgo*64];
                #pragma unroll
                for(int bn=0;bn<8;bn++){
                    int c0 = warpN + bn*8 + c4*2;
                    float v0 = silu_(acc[am][bn][hf*2]   + sBias[c0]);
                    float v1 = silu_(acc[am][bn][hf*2+1] + sBias[c0+1]);
                    op[c0>>1] = pk2(v0, v1);
                }
            }
        __syncthreads();
    }
}

// ===== fused e2 + gate + agg + c1 + c2 + roller + trans scatter ==========
#define E2SM 181824
__global__ void __launch_bounds__(256) k_e2c1(
    const float* __restrict__ e2B, const float* __restrict__ c1B,
    const float* __restrict__ c2Wf, const float* __restrict__ c2bf,
    const int* __restrict__ rowi, const int* __restrict__ coli,
    const float* __restrict__ attWg, const float* __restrict__ attbg,
    const float* __restrict__ x,
    float* __restrict__ agg, float* __restrict__ cnt, int tiles)
{
    extern __shared__ uint32_t dsm[];
    uint32_t* SA   = dsm;            // 2 x 64x136
    uint32_t* SW2  = dsm + 17408;    // 64x136
    uint32_t* SW3  = dsm + 26112;    // 64x136
    uint32_t* SEF  = dsm + 34816;    // 64x136 (phase C: sCh fp32 128x16)
    uint32_t* SC2P = dsm + 43520;    // 64x16
    int*   sRow   = (int*)(dsm + 44544);
    int*   sCol   = sRow + 128;
    float* sBias  = (float*)(sCol + 128);
    float* sBias2 = sBias + 128;
    float* sAtt   = sBias2 + 128;
    float* sDot   = sAtt + 128;      // 256
    float* scb    = sDot + 256;      // 16
    const int tid=threadIdx.x, wid=tid>>5, lane=tid&31;
    const int warpM=(wid&3)*32, warpN=(wid>>2)*64;
    const int r4=lane>>2, c4=lane&3;
    const uint32_t* Abf=(const uint32_t*)g_ef1;
    const uint32_t* W2g=(const uint32_t*)g_we2;
    const uint32_t* W3g=(const uint32_t*)g_wc1;

    for(int idx=tid; idx<128*64; idx+=256){
        int n = idx>>6, kp = idx&63;
        SW2[kp*136+n] = W2g[idx];
        SW3[kp*136+n] = W3g[idx];
    }
    for(int idx=tid; idx<64*16; idx+=256){
        int kp = idx>>4, n = idx&15;
        SC2P[idx] = (n<14)? pk2(c2Wf[n*128+2*kp], c2Wf[n*128+2*kp+1]) : 0u;
    }
    if(tid<16) scb[tid] = (tid<14)? c2bf[tid] : 0.f;
    if(tid<128){ sBias[tid]=e2B[tid]; sBias2[tid]=c1B[tid]; sAtt[tid]=attWg[tid]; }
    const float attb = attbg[0];

    auto ldAfull = [&](int t, uint4* v){
        const uint32_t* p = &Abf[(size_t)(t*128 + (tid>>1))*64 + (tid&1)*32];
        #pragma unroll
        for(int j=0;j<8;j++) v[j] = ((const uint4*)p)[j];
    };
    auto stsA = [&](int b, const uint4* v){
        uint32_t* base = &SA[b*8704 + ((tid&1)*32)*136 + (tid>>1)];
        #pragma unroll
        for(int j=0;j<8;j++){
            base[(j*4+0)*136]=v[j].x; base[(j*4+1)*136]=v[j].y;
            base[(j*4+2)*136]=v[j].z; base[(j*4+3)*136]=v[j].w;
        }
    };
    float acc[2][8][4];
    auto gemm128 = [&](const uint32_t* Ab, const uint32_t* Wb){
        #pragma unroll
        for(int g=0; g<8; g++){
            uint32_t bfr[8][2];
            #pragma unroll
            for(int bn=0;bn<8;bn++){
                int n = warpN + bn*8 + r4;
                bfr[bn][0] = Wb[(g*8+c4)*136 + n];
                bfr[bn][1] = Wb[(g*8+c4+4)*136 + n];
            }
            #pragma unroll
            for(int am=0;am<2;am++){
                int m0 = warpM + am*16 + r4;
                uint32_t af[4] = { Ab[(g*8+c4)*136+m0], Ab[(g*8+c4)*136+m0+8],
                                   Ab[(g*8+c4+4)*136+m0], Ab[(g*8+c4+4)*136+m0+8] };
                #pragma unroll
                for(int bn=0;bn<8;bn++) mma16(acc[am][bn], af, bfr[bn]);
            }
        }
    };

    { uint4 v[8]; ldAfull(blockIdx.x, v); stsA(0, v); }
    int pb = 0;

    for(int tile=blockIdx.x; tile<tiles; tile+=gridDim.x){
        if(tid<128){ sRow[tid]=rowi[tile*128+tid]; sCol[tid]=coli[tile*128+tid]; }
        __syncthreads();
        int nt = tile + gridDim.x;
        bool pf = nt < tiles;
        uint4 an[8];
        if(pf) ldAfull(nt, an);

        #pragma unroll
        for(int am=0;am<2;am++)
            #pragma unroll
            for(int bn=0;bn<8;bn++)
                #pragma unroll
                for(int i=0;i<4;i++) acc[am][bn][i]=0.f;
        gemm128(&SA[pb*8704], SW2);
        if(pf) stsA(pb^1, an);

        #pragma unroll
        for(int am=0;am<2;am++)
            #pragma unroll
            for(int bn=0;bn<8;bn++){
                int c0 = warpN + bn*8 + c4*2;
                float* a = acc[am][bn];
                a[0]=silu_(a[0]+sBias[c0]);   a[1]=silu_(a[1]+sBias[c0+1]);
                a[2]=silu_(a[2]+sBias[c0]);   a[3]=silu_(a[3]+sBias[c0+1]);
            }
        {
            float dot[2][2] = {{0.f,0.f},{0.f,0.f}};
            #pragma unroll
            for(int am=0;am<2;am++)
                #pragma unroll
                for(int bn=0;bn<8;bn++){
                    int c0 = warpN + bn*8 + c4*2;
                    float w0=sAtt[c0], w1=sAtt[c0+1];
                    dot[am][0] += acc[am][bn][0]*w0 + acc[am][bn][1]*w1;
                    dot[am][1] += acc[am][bn][2]*w0 + acc[am][bn][3]*w1;
                }
            #pragma unroll
            for(int am=0;am<2;am++)
                #pragma unroll
                for(int hf=0;hf<2;hf++){
                    dot[am][hf] += __shfl_xor_sync(0xffffffffu, dot[am][hf], 1);
                    dot[am][hf] += __shfl_xor_sync(0xffffffffu, dot[am][hf], 2);
                }
            if(c4==0){
                #pragma unroll
                for(int am=0;am<2;am++){
                    sDot[(wid>>2)*128 + warpM+am*16+r4]   = dot[am][0];
                    sDot[(wid>>2)*128 + warpM+am*16+r4+8] = dot[am][1];
                }
            }
            __syncthreads();
            #pragma unroll
            for(int am=0;am<2;am++)
                #pragma unroll
                for(int hf=0;hf<2;hf++){
                    int rl = warpM + am*16 + r4 + hf*8;
                    float g = sigm(sDot[rl] + sDot[128+rl] + attb);
                    #pragma unroll
                    for(int bn=0;bn<8;bn++){
                        acc[am][bn][hf*2]   *= g;
                        acc[am][bn][hf*2+1] *= g;
                    }
                }
        }
        #pragma unroll
        for(int am=0;am<2;am++)
            #pragma unroll
            for(int hf=0;hf<2;hf++){
                int rl = warpM + am*16 + r4 + hf*8;
                int cc = sCol[rl];
                float* ag = &agg[(size_t)cc*128];
                #pragma unroll
                for(int bn=0;bn<8;bn++){
                    int c0 = warpN + bn*8 + c4*2;
                    float v0 = acc[am][bn][hf*2], v1 = acc[am][bn][hf*2+1];
                    atomicAdd(ag+c0,   v0);
                    atomicAdd(ag+c0+1, v1);
                    SEF[(c0>>1)*136 + rl] = pk2(v0, v1);
                }
                if(warpN==0 && c4==0) atomicAdd(&cnt[cc], 1.f);
            }
        __syncthreads();

        #pragma unroll
        for(int am=0;am<2;am++)
            #pragma unroll
            for(int bn=0;bn<8;bn++)
                #pragma unroll
                for(int i=0;i<4;i++) acc[am][bn][i]=0.f;
        gemm128(SEF, SW3);
        #pragma unroll
        for(int am=0;am<2;am++)
            #pragma unroll
            for(int hf=0;hf<2;hf++){
                int rl = warpM + am*16 + r4 + hf*8;
                #pragma unroll
                for(int bn=0;bn<8;bn++){
                    int c0 = warpN + bn*8 + c4*2;
                    float v0 = silu_(acc[am][bn][hf*2]   + sBias2[c0]);
                    float v1 = silu_(acc[am][bn][hf*2+1] + sBias2[c0+1]);
                    SA[pb*8704 + (c0>>1)*136 + rl] = pk2(v0, v1);
                }
            }
        __syncthreads();

        if(wid < 4){
            float accC[2][2][4];
            #pragma unroll
            for(int am=0;am<2;am++)
                #pragma unroll
                for(int bn=0;bn<2;bn++)
                    #pragma unroll
                    for(int i=0;i<4;i++) accC[am][bn][i]=0.f;
            #pragma unroll
            for(int g=0; g<8; g++){
                uint32_t bfr[2][2];
                #pragma unroll
                for(int bn=0;bn<2;bn++){
                    int n = bn*8 + r4;
                    bfr[bn][0] = SC2P[(g*8+c4)*16 + n];
                    bfr[bn][1] = SC2P[(g*8+c4+4)*16 + n];
                }
                #pragma unroll
                for(int am=0;am<2;am++){
                    int m0 = warpM + am*16 + r4;
                    uint32_t af[4] = { SA[pb*8704+(g*8+c4)*136+m0],
                                       SA[pb*8704+(g*8+c4)*136+m0+8],
                                       SA[pb*8704+(g*8+c4+4)*136+m0],
                                       SA[pb*8704+(g*8+c4+4)*136+m0+8] };
                    #pragma unroll
                    for(int bn=0;bn<2;bn++) mma16(accC[am][bn], af, bfr[bn]);
                }
            }
            float* sCh = (float*)SEF;
            #pragma unroll
            for(int am=0;am<2;am++)
                #pragma unroll
                for(int hf=0;hf<2;hf++){
                    int rl = warpM + am*16 + r4 + hf*8;
                    #pragma unroll
                    for(int bn=0;bn<2;bn++){
                        int c0 = bn*8 + c4*2;
                        sCh[rl*16+c0]   = accC[am][bn][hf*2];
                        sCh[rl*16+c0+1] = accC[am][bn][hf*2+1];
                    }
                }
        }
        __syncthreads();

        if(tid < 128){
            const float* sCh = (const float*)SEF;
            int rl = tid;
            int r = sRow[rl], c = sCol[rl];
            float P[15]; P[0]=0.f;
            #pragma unroll
            for(int j=0;j<14;j++) P[j+1] = P[j] + sCh[rl*16+j] + scb[j];
            int cs = (int)(g_csum[r]+0.5f);
            int w = 15 - cs;
            float invw = 1.f/(float)w;
            float px=g_pool3[c*3], py=g_pool3[c*3+1], pz=g_pool3[c*3+2];
            #pragma unroll
            for(int i=0;i<14;i++){
                int e2 = min(i+w, 14);
                float pooled = (P[e2]-P[i])*invw;
                const float* xp = &x[((size_t)r*14+i)*3];
                atomicAdd(&g_xsum[(r*14+i)*3+0], (xp[0]-px)*pooled);
                atomicAdd(&g_xsum[(r*14+i)*3+1], (xp[1]-py)*pooled);
                atomicAdd(&g_xsum[(r*14+i)*3+2], (xp[2]-pz)*pooled);
            }
            atomicAdd(&g_cnt_row[r], 1.f);
        }
        __syncthreads();
        pb ^= 1;
    }
}

// ===== fused node path: [h|agg] -> n1 -> n2 -> residual+LN -> out =====
#define NODESM 208896
__global__ void __launch_bounds__(256,1) k_node(
    const float* __restrict__ h, const float* __restrict__ n1W,
    const float* __restrict__ n1B, const float* __restrict__ n2W,
    const float* __restrict__ n2B, const float* __restrict__ lng,
    const float* __restrict__ lnb, float* __restrict__ out, int tiles)
{
    extern __shared__ uint32_t dsm[];
    uint32_t* SW1 = dsm;            // 128kp x 136
    uint32_t* SA  = dsm + 17408;    // 128kp x 136
    uint32_t* SW2 = dsm + 34816;    // 64kp x 136
    uint32_t* SH  = dsm + 43520;    // 64kp x 136
    __shared__ float sB1[128], sB2[128], sG[128], sBt[128];
    __shared__ float sSum[256], sSq[256];
    const int tid=threadIdx.x, wid=tid>>5, lane=tid&31;
    const int warpM=(wid&3)*32, warpN=(wid>>2)*64;
    const int r4=lane>>2, c4=lane&3;
    const uint32_t* hbf=(const uint32_t*)g_hbf;

    for(int idx=tid; idx<128*128; idx+=256){
        int kp=idx>>7, n=idx&127;
        SW1[kp*136+n] = pk2(n1W[n*256+2*kp], n1W[n*256+2*kp+1]);
    }
    for(int idx=tid; idx<64*128; idx+=256){
        int kp=idx>>6, n=idx&63;      // careful: decode below
        (void)kp; (void)n;
    }
    for(int idx=tid; idx<64*128; idx+=256){
        int kp=idx/128, n=idx%128;
        SW2[kp*136+n] = pk2(n2W[n*128+2*kp], n2W[n*128+2*kp+1]);
    }
    if(tid<128){ sB1[tid]=n1B[tid]; sB2[tid]=n2B[tid]; sG[tid]=lng[tid]; sBt[tid]=lnb[tid]; }
    __syncthreads();

    float acc[2][8][4];
    auto gemmK = [&](const uint32_t* Ab, const uint32_t* Wb, int ng){
        for(int g=0; g<ng; g++){
            uint32_t bfr[8][2];
            #pragma unroll
            for(int bn=0;bn<8;bn++){
                int n = warpN + bn*8 + r4;
                bfr[bn][0] = Wb[(g*8+c4)*136 + n];
                bfr[bn][1] = Wb[(g*8+c4+4)*136 + n];
            }
            #pragma unroll
            for(int am=0;am<2;am++){
                int m0 = warpM + am*16 + r4;
                uint32_t af[4] = { Ab[(g*8+c4)*136+m0], Ab[(g*8+c4)*136+m0+8],
                                   Ab[(g*8+c4+4)*136+m0], Ab[(g*8+c4+4)*136+m0+8] };
                #pragma unroll
                for(int bn=0;bn<8;bn++) mma16(acc[am][bn], af, bfr[bn]);
            }
        }
    };

    for(int tile=blockIdx.x; tile<tiles; tile+=gridDim.x){
        // gather A = [h | agg/cnt] bf16
        {
            int rl = tid>>1, q = tid&1;
            int n = min(tile*128+rl, NN-1);
            if(q==0){
                const uint4* p = (const uint4*)&hbf[n*64];
                uint32_t* d = &SA[rl];
                #pragma unroll
                for(int j=0;j<16;j++){
                    uint4 u = p[j];
                    d[(j*4+0)*136]=u.x; d[(j*4+1)*136]=u.y;
                    d[(j*4+2)*136]=u.z; d[(j*4+3)*136]=u.w;
                }
            } else {
                float inv = 1.f/fmaxf(g_cnt_col[n],1.f);
                const float4* p = (const float4*)&g_aggsum[(size_t)n*128];
                uint32_t* d = &SA[64*136 + rl];
                #pragma unroll
                for(int j=0;j<32;j++){
                    float4 v = p[j];
                    d[(j*2+0)*136]=pk2(v.x*inv, v.y*inv);
                    d[(j*2+1)*136]=pk2(v.z*inv, v.w*inv);
                }
            }
        }
        __syncthreads();
        // n1: K=256
        #pragma unroll
        for(int am=0;am<2;am++)
            #pragma unroll
            for(int bn=0;bn<8;bn++)
                #pragma unroll
                for(int i=0;i<4;i++) acc[am][bn][i]=0.f;
        gemmK(SA, SW1, 16);
        #pragma unroll
        for(int am=0;am<2;am++)
            #pragma unroll
            for(int hf=0;hf<2;hf++){
                int rl = warpM + am*16 + r4 + hf*8;
                #pragma unroll
                for(int bn=0;bn<8;bn++){
                    int c0 = warpN + bn*8 + c4*2;
                    float v0 = silu_(acc[am][bn][hf*2]   + sB1[c0]);
                    float v1 = silu_(acc[am][bn][hf*2+1] + sB1[c0+1]);
                    SH[(c0>>1)*136 + rl] = pk2(v0, v1);
                }
            }
        __syncthreads();
        // n2: K=128
        #pragma unroll
        for(int am=0;am<2;am++)
            #pragma unroll
            for(int bn=0;bn<8;bn++)
                #pragma unroll
                for(int i=0;i<4;i++) acc[am][bn][i]=0.f;
        gemmK(SH, SW2, 8);
        // residual + LN
        #pragma unroll
        for(int am=0;am<2;am++)
            #pragma unroll
            for(int hf=0;hf<2;hf++){
                int rl = warpM + am*16 + r4 + hf*8;
                int rg = tile*128 + rl;
                int hn = min(rg, NN-1);
                float s=0.f, sq=0.f;
                #pragma unroll
                for(int bn=0;bn<8;bn++){
                    int c0 = warpN + bn*8 + c4*2;
                    float y0 = acc[am][bn][hf*2]   + sB2[c0]   + h[(size_t)hn*128+c0];
                    float y1 = acc[am][bn][hf*2+1] + sB2[c0+1] + h[(size_t)hn*128+c0+1];
                    acc[am][bn][hf*2]=y0; acc[am][bn][hf*2+1]=y1;
                    s += y0+y1; sq += y0*y0+y1*y1;
                }
                s  += __shfl_xor_sync(0xffffffffu, s, 1);
                s  += __shfl_xor_sync(0xffffffffu, s, 2);
                sq += __shfl_xor_sync(0xffffffffu, sq, 1);
                sq += __shfl_xor_sync(0xffffffffu, sq, 2);
                if(c4==0){
                    sSum[(wid>>2)*128+rl]=s;
                    sSq[(wid>>2)*128+rl]=sq;
                }
            }
        __syncthreads();
        #pragma unroll
        for(int am=0;am<2;am++)
            #pragma unroll
            for(int hf=0;hf<2;hf++){
                int rl = warpM + am*16 + r4 + hf*8;
                int rg = tile*128 + rl;
                if(rg < NN){
                    float tot = sSum[rl]+sSum[128+rl];
                    float mu = tot*(1.f/128.f);
                    float var = (sSq[rl]+sSq[128+rl])*(1.f/128.f) - mu*mu;
                    float is = rsqrtf(fmaxf(var,0.f)+1e-5f);
                    float* op = &out[(size_t)rg*128];
                    #pragma unroll
                    for(int bn=0;bn<8;bn++){
                        int c0 = warpN + bn*8 + c4*2;
                        op[c0]   = (acc[am][bn][hf*2]  -mu)*is*sG[c0]  +sBt[c0];
                        op[c0+1] = (acc[am][bn][hf*2+1]-mu)*is*sG[c0+1]+sBt[c0+1];
                    }
                }
            }
        __syncthreads();
    }
}

// ---------------- x_out ----------------
__global__ void k_xout(const float* __restrict__ x, float* __restrict__ xout){
    int idx = blockIdx.x*blockDim.x + threadIdx.x;
    if(idx >= NN*CC*3) return;
    int n = idx/(CC*3);
    xout[idx] = x[idx] + g_xsum[idx]/fmaxf(g_cnt_row[n],1.f);
}

// ======================= host launcher =======================
extern "C" void kernel_launch(void* const* d_in, const int* in_sizes, int n_in,
                              void* d_out, int out_size){
    const float* h    = (const float*)d_in[0];
    const float* x    = (const float*)d_in[1];
    const int*   row  = (const int*)  d_in[2];
    const int*   col  = (const int*)  d_in[3];
    const float* attr = (const float*)d_in[4];
    const float* cw   = (const float*)d_in[5];
    const float* radW = (const float*)d_in[6];  const float* radB = (const float*)d_in[7];
    const float* e1W  = (const float*)d_in[8];  const float* e1B  = (const float*)d_in[9];
    const float* e2W  = (const float*)d_in[10]; const float* e2B  = (const float*)d_in[11];
    const float* attW = (const float*)d_in[12]; const float* attB = (const float*)d_in[13];
    const float* c1W  = (const float*)d_in[14]; const float* c1B  = (const float*)d_in[15];
    const float* c2W  = (const float*)d_in[16]; const float* c2B  = (const float*)d_in[17];
    const float* n1W  = (const float*)d_in[18]; const float* n1B  = (const float*)d_in[19];
    const float* n2W  = (const float*)d_in[20]; const float* n2B  = (const float*)d_in[21];
    const float* lng  = (const float*)d_in[22]; const float* lnb  = (const float*)d_in[23];
    float* outH = (float*)d_out;
    float* outX = outH + (size_t)NN*128;

    void *p_agg,*p_cntc;
    cudaGetSymbolAddress(&p_agg,  g_aggsum);
    cudaGetSymbolAddress(&p_cntc, g_cnt_col);

    cudaFuncSetAttribute(k_e1,   cudaFuncAttributeMaxDynamicSharedMemorySize, E1SM);
    cudaFuncSetAttribute(k_e2c1, cudaFuncAttributeMaxDynamicSharedMemorySize, E2SM);
    cudaFuncSetAttribute(k_node, cudaFuncAttributeMaxDynamicSharedMemorySize, NODESM);

    const int ZT = NN*128 + NN + NN*CC*3 + NN;
    k_zero<<<(ZT+255)/256, 256>>>();
    k_prep<<<(NN+255)/256, 256>>>(x, cw);
    k_hconv<<<(NN*64+255)/256, 256>>>(h);
    k_aconv<<<(NN*112+255)/256, 256>>>(attr);
    k_wcvt<<<(2*128*64+255)/256, 256>>>(e2W, c1W);
    k_waug<<<128, 256>>>(e1W, radW, radB);
    k_geom<<<NE/8, 256>>>(x, row, col, cw);

    // ef1(bf16) = silu([h_r|h_c|radial'|rinv] @ Waug^T + e1B)
    k_e1<<<304,256,E1SM>>>(e1B, row, col, TE128);
    // fused e2+gate+agg + c1 + c2 + roller + trans scatter
    k_e2c1<<<148,256,E2SM>>>(e2B, c1B, c2W, c2B, row, col, attW, attB,
                             x, (float*)p_agg, (float*)p_cntc, TE128);
    // fused node path -> outH
    k_node<<<TN128,256,NODESM>>>(h, n1W, n1B, n2W, n2B, lng, lnb, outH, TN128);
    k_xout<<<(NN*CC*3+255)/256, 256>>>(x, outX);
}

// round 12
// speedup vs baseline: 6.1326x; 1.0935x over previous
#include <cuda_runtime.h>
#include <cuda_bf16.h>
#include <math.h>
#include <stdint.h>

#define NN 20000
#define NE 320000
#define CC 14
#define TE128 (NE/128)              // 2500
#define TN128 ((NN+127)/128)        // 157

// ---------------- scratch ----------------
__device__ __align__(16) float g_radial[(size_t)NE*128];  // bf16 [E][256] = radial*rinv
__device__ __align__(16) float g_ef1[(size_t)NE*64];      // bf16 [E][128] e1 out
__device__ float g_rinv[NE];
__device__ float g_csum[NN];
__device__ float g_pool3[NN*3];
__device__ float g_aggsum[(size_t)NN*128];
__device__ float g_cnt_col[NN];
__device__ float g_xsum[NN*CC*3];
__device__ float g_cnt_row[NN];
__device__ __align__(16) float g_hbf[NN*64];      // bf16 h
__device__ __align__(16) float g_abf[NN*112];     // bf16 attr
__device__ __align__(16) float g_waug[128*272];   // bf16 [128][544] augmented e1 weight
__device__ __align__(16) float g_we2[128*64];     // bf16 e2W
__device__ __align__(16) float g_wc1[128*64];     // bf16 c1W

__device__ __forceinline__ float sigm(float v){ return 1.f/(1.f+__expf(-v)); }
__device__ __forceinline__ float silu_(float v){ return v*sigm(v); }
__device__ __forceinline__ uint32_t pk2(float lo, float hi){
    __nv_bfloat162 t = __floats2bfloat162_rn(lo, hi);
    return *(uint32_t*)&t;
}
__device__ __forceinline__ void mma16(float* c, const uint32_t* a, const uint32_t* b){
    asm volatile("mma.sync.aligned.m16n8k16.row.col.f32.bf16.bf16.f32 "
        "{%0,%1,%2,%3}, {%4,%5,%6,%7}, {%8,%9}, {%0,%1,%2,%3};"
        : "+f"(c[0]),"+f"(c[1]),"+f"(c[2]),"+f"(c[3])
        : "r"(a[0]),"r"(a[1]),"r"(a[2]),"r"(a[3]), "r"(b[0]),"r"(b[1]));
}

// ---------------- merged prep: zero + hconv + aconv + wcvt + nodeprep -------
__global__ void k_prepall(const float* __restrict__ x, const float* __restrict__ cw,
                          const float* __restrict__ h, const float* __restrict__ attr,
                          const float* __restrict__ e2W, const float* __restrict__ c1W){
    long long i = (long long)blockIdx.x*256 + threadIdx.x;
    const long long ZA = (long long)NN*128;
    const long long ZB = ZA + NN;
    const long long ZD = ZB + (long long)NN*42;
    const long long ZE = ZD + NN;
    const long long HC = ZE + (long long)NN*64;
    const long long AC = HC + (long long)NN*112;
    const long long WC = AC + 2*128*64;
    const long long PR = WC + NN;
    if(i < ZA) g_aggsum[i]=0.f;
    else if(i < ZB) g_cnt_col[i-ZA]=0.f;
    else if(i < ZD) g_xsum[i-ZB]=0.f;
    else if(i < ZE) g_cnt_row[i-ZD]=0.f;
    else if(i < HC){ long long j=i-ZE; float2 v=((const float2*)h)[j];
        ((uint32_t*)g_hbf)[j]=pk2(v.x,v.y); }
    else if(i < AC){ long long j=i-HC; float2 v=((const float2*)attr)[j];
        ((uint32_t*)g_abf)[j]=pk2(v.x,v.y); }
    else if(i < WC){ long long j=i-AC;
        if(j < 128*64){ float2 v=((const float2*)e2W)[j]; ((uint32_t*)g_we2)[j]=pk2(v.x,v.y); }
        else { long long k=j-128*64; float2 v=((const float2*)c1W)[k]; ((uint32_t*)g_wc1)[k]=pk2(v.x,v.y); }
    }
    else if(i < PR){
        int n = (int)(i-WC);
        float cnt=0.f, px=0.f, py=0.f, pz=0.f;
        #pragma unroll
        for(int k=0;k<CC;k++){
            float w = cw[n*CC+k];
            if(w != 0.f){
                cnt += 1.f;
                const float* xp = &x[(n*CC+k)*3];
                px += xp[0]; py += xp[1]; pz += xp[2];
            }
        }
        g_csum[n] = cnt;
        float inv = 1.f/cnt;
        g_pool3[n*3+0]=px*inv; g_pool3[n*3+1]=py*inv; g_pool3[n*3+2]=pz*inv;
    }
}
#define PREP_TOTAL ((long long)NN*128 + NN + (long long)NN*42 + NN + (long long)NN*64 + (long long)NN*112 + 2*128*64 + NN)

// ---------------- build augmented e1 weight (bf16, 272 kp = 544 k) ----------
__global__ void k_waug(const float* __restrict__ e1W, const float* __restrict__ radW,
                       const float* __restrict__ radB){
    __shared__ float s[128];
    int n = blockIdx.x, tid = threadIdx.x;
    if(tid < 128) s[tid] = e1W[n*384 + 256 + tid];
    __syncthreads();
    uint32_t* out = (uint32_t*)g_waug + n*272;
    if(tid < 128) out[tid] = pk2(e1W[n*384 + 2*tid], e1W[n*384 + 2*tid + 1]);
    else if(tid-128 < 128){
        int kpl = tid-128;
        int kk = 2*kpl;
        float d0=0.f, d1=0.f;
        #pragma unroll 4
        for(int j=0;j<128;j++){
            float sj = s[j];
            d0 += sj*radW[j*256+kk];
            d1 += sj*radW[j*256+kk+1];
        }
        out[128+kpl] = pk2(d0,d1);
    }
    if(tid==0){
        float bc=0.f;
        for(int j=0;j<128;j++) bc += s[j]*radB[j];
        out[256] = pk2(bc, 0.f);
    }
    if(tid>=1 && tid<16) out[256+tid] = 0u;
}

// ---------------- geometry via tensor cores: 4 MMAs per edge ---------------
// radial = (cwr*Ar)^T @ dist @ (cwc*Ac), dist computed straight into A-fragment.
__global__ void __launch_bounds__(256) k_geom(const float* __restrict__ x,
        const int* __restrict__ row, const int* __restrict__ col,
        const float* __restrict__ cw){
    __shared__ float sX[8][88];          // xr[42]@0, xc[42]@44
    __shared__ float sCW[8][32];         // cwr@0, cwc@16
    __shared__ uint32_t sAR[8][112];     // attrR bf16x2 [i][b] pairs along b
    __shared__ uint32_t sAC[8][112];
    __shared__ float sT[8][256];         // T fp32 [i][b]
    const int warp=threadIdx.x>>5, lane=threadIdx.x&31;
    const int e = blockIdx.x*8 + warp;
    if(e >= NE) return;
    const int r=row[e], c=col[e];
    const uint32_t* ab=(const uint32_t*)g_abf;
    if(lane<CC){ sCW[warp][lane]=cw[r*CC+lane]; sCW[warp][16+lane]=cw[c*CC+lane]; }
    for(int i=lane;i<42;i+=32){ sX[warp][i]=x[r*42+i]; sX[warp][44+i]=x[c*42+i]; }
    for(int i=lane;i<112;i+=32){ sAR[warp][i]=ab[r*112+i]; sAC[warp][i]=ab[c*112+i]; }
    __syncwarp();
    const int r4=lane>>2, c4=lane&3;
    auto dist=[&](int i,int j)->float{
        if(i>=CC||j>=CC) return 0.f;
        float dx=sX[warp][i*3]  -sX[warp][44+j*3];
        float dy=sX[warp][i*3+1]-sX[warp][44+j*3+1];
        float dz=sX[warp][i*3+2]-sX[warp][44+j*3+2];
        return sqrtf(dx*dx+dy*dy+dz*dz);
    };
    uint32_t aD[4];
    {
        int j0=2*c4, j2=2*c4+8;
        aD[0]=pk2(dist(r4,j0),  dist(r4,j0+1));
        aD[1]=pk2(dist(r4+8,j0),dist(r4+8,j0+1));
        aD[2]=pk2(dist(r4,j2),  dist(r4,j2+1));
        aD[3]=pk2(dist(r4+8,j2),dist(r4+8,j2+1));
    }
    auto acv=[&](int j,int b)->float{
        if(j>=CC) return 0.f;
        uint32_t w = sAC[warp][j*8 + (b>>1)];
        __nv_bfloat162 t=*(__nv_bfloat162*)&w;
        float v=(b&1)? __high2float(t): __low2float(t);
        return v*sCW[warp][16+j];
    };
    float T0[4]={0,0,0,0}, T1[4]={0,0,0,0};
    {
        uint32_t b0[2], b1[2];
        b0[0]=pk2(acv(2*c4,r4),    acv(2*c4+1,r4));
        b0[1]=pk2(acv(2*c4+8,r4),  acv(2*c4+9,r4));
        b1[0]=pk2(acv(2*c4,r4+8),  acv(2*c4+1,r4+8));
        b1[1]=pk2(acv(2*c4+8,r4+8),acv(2*c4+9,r4+8));
        mma16(T0,aD,b0);
        mma16(T1,aD,b1);
    }
    {
        float* st=sT[warp];
        st[r4*16+2*c4]       =T0[0]; st[r4*16+2*c4+1]     =T0[1];
        st[(r4+8)*16+2*c4]   =T0[2]; st[(r4+8)*16+2*c4+1] =T0[3];
        st[r4*16+8+2*c4]     =T1[0]; st[r4*16+8+2*c4+1]   =T1[1];
        st[(r4+8)*16+8+2*c4] =T1[2]; st[(r4+8)*16+8+2*c4+1]=T1[3];
    }
    __syncwarp();
    auto arv=[&](int i,int a)->float{
        if(i>=CC) return 0.f;
        uint32_t w = sAR[warp][i*8 + (a>>1)];
        __nv_bfloat162 t=*(__nv_bfloat162*)&w;
        float v=(a&1)? __high2float(t): __low2float(t);
        return v*sCW[warp][i];
    };
    uint32_t aR[4];
    aR[0]=pk2(arv(2*c4,r4),    arv(2*c4+1,r4));
    aR[1]=pk2(arv(2*c4,r4+8),  arv(2*c4+1,r4+8));
    aR[2]=pk2(arv(2*c4+8,r4),  arv(2*c4+9,r4));
    aR[3]=pk2(arv(2*c4+8,r4+8),arv(2*c4+9,r4+8));
    float R0[4]={0,0,0,0}, R1[4]={0,0,0,0};
    {
        const float* st=sT[warp];
        uint32_t b0[2], b1[2];
        b0[0]=pk2(st[(2*c4)*16+r4],    st[(2*c4+1)*16+r4]);
        b0[1]=pk2(st[(2*c4+8)*16+r4],  st[(2*c4+9)*16+r4]);
        b1[0]=pk2(st[(2*c4)*16+r4+8],  st[(2*c4+1)*16+r4+8]);
        b1[1]=pk2(st[(2*c4+8)*16+r4+8],st[(2*c4+9)*16+r4+8]);
        mma16(R0,aR,b0);
        mma16(R1,aR,b1);
    }
    float sq = R0[0]*R0[0]+R0[1]*R0[1]+R0[2]*R0[2]+R0[3]*R0[3]
             + R1[0]*R1[0]+R1[1]*R1[1]+R1[2]*R1[2]+R1[3]*R1[3];
    #pragma unroll
    for(int o=16;o>0;o>>=1) sq += __shfl_xor_sync(0xffffffffu,sq,o);
    float rinv = 1.f/(sqrtf(sq)+1.f);
    uint32_t* go=(uint32_t*)g_radial + (size_t)e*128;
    go[r4*8 + c4]         = pk2(R0[0]*rinv, R0[1]*rinv);
    go[(r4+8)*8 + c4]     = pk2(R0[2]*rinv, R0[3]*rinv);
    go[r4*8 + 4 + c4]     = pk2(R1[0]*rinv, R1[1]*rinv);
    go[(r4+8)*8 + 4 + c4] = pk2(R1[2]*rinv, R1[3]*rinv);
    if(lane==0) g_rinv[e]=rinv;
}

// ===== e1 GEMM: K=544, BK=32, 3-stage smem ring, prefetch distance 2 =====
#define E1SM 53760
__global__ void __launch_bounds__(256,2) k_e1(
    const float* __restrict__ e1B, const int* __restrict__ rowi,
    const int* __restrict__ coli, int tiles)
{
    extern __shared__ uint32_t dsm[];
    uint32_t* SA = dsm;                 // 3*16*136
    uint32_t* SW = dsm + 6528;          // 3*16*136
    int* sRow = (int*)(dsm + 13056);
    int* sCol = sRow + 128;
    float* sBias = (float*)(sCol + 128);
    const int tid=threadIdx.x, wid=tid>>5, lane=tid&31;
    const int warpM=(wid&3)*32, warpN=(wid>>2)*64;
    const int ee=tid>>1, q=tid&1;
    const int r4=lane>>2, c4=lane&3;
    const uint32_t* hbf=(const uint32_t*)g_hbf;
    const uint32_t* rad=(const uint32_t*)g_radial;
    const uint32_t* waug=(const uint32_t*)g_waug;
    uint32_t* Obf=(uint32_t*)g_ef1;
    if(tid<128) sBias[tid]=e1B[tid];

    for(int tile=blockIdx.x; tile<tiles; tile+=gridDim.x){
        if(tid<128){ sRow[tid]=rowi[tile*128+tid]; sCol[tid]=coli[tile*128+tid]; }
        __syncthreads();
        const int rg = tile*128 + ee;
        auto ldA = [&](int kt, uint4& u0, uint4& u1){
            const int kp = kt*16 + q*8;
            if(kp < 64){ const uint32_t* p=&hbf[sRow[ee]*64+kp];
                u0=*(const uint4*)p; u1=*(const uint4*)(p+4); }
            else if(kp < 128){ const uint32_t* p=&hbf[sCol[ee]*64+(kp-64)];
                u0=*(const uint4*)p; u1=*(const uint4*)(p+4); }
            else if(kp < 256){ const uint32_t* p=&rad[(size_t)rg*128+(kp-128)];
                u0=*(const uint4*)p; u1=*(const uint4*)(p+4); }
            else if(kp == 256){ u0=make_uint4(pk2(g_rinv[rg],0.f),0u,0u,0u);
                u1=make_uint4(0u,0u,0u,0u); }
            else { u0=make_uint4(0u,0u,0u,0u); u1=u0; }
        };
        auto ldW = [&](int kt, uint4& u0, uint4& u1){
            const uint32_t* p=&waug[ee*272 + kt*16 + q*8];
            u0=*(const uint4*)p; u1=*(const uint4*)(p+4);
        };
        auto sts = [&](int b, uint4 a0, uint4 a1, uint4 w0, uint4 w1){
            uint32_t* pa=&SA[b*2176 + (q*8)*136 + ee];
            pa[0]=a0.x; pa[136]=a0.y; pa[272]=a0.z; pa[408]=a0.w;
            pa[544]=a1.x; pa[680]=a1.y; pa[816]=a1.z; pa[952]=a1.w;
            uint32_t* pw=&SW[b*2176 + (q*8)*136 + ee];
            pw[0]=w0.x; pw[136]=w0.y; pw[272]=w0.z; pw[408]=w0.w;
            pw[544]=w1.x; pw[680]=w1.y; pw[816]=w1.z; pw[952]=w1.w;
        };

        float acc[2][8][4];
        #pragma unroll
        for(int am=0;am<2;am++)
            #pragma unroll
            for(int bn=0;bn<8;bn++)
                #pragma unroll
                for(int i=0;i<4;i++) acc[am][bn][i]=0.f;

        uint4 a0,a1,w0,w1;
        ldA(0,a0,a1); ldW(0,w0,w1); sts(0,a0,a1,w0,w1);
        ldA(1,a0,a1); ldW(1,w0,w1); sts(1,a0,a1,w0,w1);
        __syncthreads();

        #pragma unroll 1
        for(int kt=0; kt<17; kt++){
            bool pf = kt < 15;
            if(pf){ ldA(kt+2,a0,a1); ldW(kt+2,w0,w1); }
            const uint32_t* Ab=&SA[(kt%3)*2176];
            const uint32_t* Wb=&SW[(kt%3)*2176];
            #pragma unroll
            for(int g=0; g<2; g++){
                uint32_t bfr[8][2];
                #pragma unroll
                for(int bn=0;bn<8;bn++){
                    int n = warpN + bn*8 + r4;
                    bfr[bn][0] = Wb[(g*8+c4)*136 + n];
                    bfr[bn][1] = Wb[(g*8+c4+4)*136 + n];
                }
                #pragma unroll
                for(int am=0;am<2;am++){
                    int m0 = warpM + am*16 + r4;
                    uint32_t af[4] = { Ab[(g*8+c4)*136+m0], Ab[(g*8+c4)*136+m0+8],
                                       Ab[(g*8+c4+4)*136+m0], Ab[(g*8+c4+4)*136+m0+8] };
                    #pragma unroll
                    for(int bn=0;bn<8;bn++) mma16(acc[am][bn], af, bfr[bn]);
                }
            }
            if(pf) sts((kt+2)%3, a0,a1,w0,w1);
            __syncthreads();
        }

        #pragma unroll
        for(int am=0;am<2;am++)
            #pragma unroll
            for(int hf=0;hf<2;hf++){
                int rl = warpM + am*16 + r4 + hf*8;
                int rgo = tile*128 + rl;
                uint32_t* op = &Obf[(size_t)rgo*64];
                #pragma unroll
                for(int bn=0;bn<8;bn++){
                    int c0 = warpN + bn*8 + c4*2;
                    float v0 = silu_(acc[am][bn][hf*2]   + sBias[c0]);
                    float v1 = silu_(acc[am][bn][hf*2+1] + sBias[c0+1]);
                    op[c0>>1] = pk2(v0, v1);
                }
            }
        __syncthreads();
    }
}

// ===== fused e2 + gate + agg + c1 + c2 + roller + trans scatter ==========
#define E2SM 181824
__global__ void __launch_bounds__(256) k_e2c1(
    const float* __restrict__ e2B, const float* __restrict__ c1B,
    const float* __restrict__ c2Wf, const float* __restrict__ c2bf,
    const int* __restrict__ rowi, const int* __restrict__ coli,
    const float* __restrict__ attWg, const float* __restrict__ attbg,
    const float* __restrict__ x,
    float* __restrict__ agg, float* __restrict__ cnt, int tiles)
{
    extern __shared__ uint32_t dsm[];
    uint32_t* SA   = dsm;            // 2 x 64x136
    uint32_t* SW2  = dsm + 17408;    // 64x136
    uint32_t* SW3  = dsm + 26112;    // 64x136
    uint32_t* SEF  = dsm + 34816;    // 64x136 (phase C: sCh fp32 128x16)
    uint32_t* SC2P = dsm + 43520;    // 64x16
    int*   sRow   = (int*)(dsm + 44544);
    int*   sCol   = sRow + 128;
    float* sBias  = (float*)(sCol + 128);
    float* sBias2 = sBias + 128;
    float* sAtt   = sBias2 + 128;
    float* sDot   = sAtt + 128;      // 256
    float* scb    = sDot + 256;      // 16
    const int tid=threadIdx.x, wid=tid>>5, lane=tid&31;
    const int warpM=(wid&3)*32, warpN=(wid>>2)*64;
    const int r4=lane>>2, c4=lane&3;
    const uint32_t* Abf=(const uint32_t*)g_ef1;
    const uint32_t* W2g=(const uint32_t*)g_we2;
    const uint32_t* W3g=(const uint32_t*)g_wc1;

    for(int idx=tid; idx<128*64; idx+=256){
        int n = idx>>6, kp = idx&63;
        SW2[kp*136+n] = W2g[idx];
        SW3[kp*136+n] = W3g[idx];
    }
    for(int idx=tid; idx<64*16; idx+=256){
        int kp = idx>>4, n = idx&15;
        SC2P[idx] = (n<14)? pk2(c2Wf[n*128+2*kp], c2Wf[n*128+2*kp+1]) : 0u;
    }
    if(tid<16) scb[tid] = (tid<14)? c2bf[tid] : 0.f;
    if(tid<128){ sBias[tid]=e2B[tid]; sBias2[tid]=c1B[tid]; sAtt[tid]=attWg[tid]; }
    const float attb = attbg[0];

    auto ldAfull = [&](int t, uint4* v){
        const uint32_t* p = &Abf[(size_t)(t*128 + (tid>>1))*64 + (tid&1)*32];
        #pragma unroll
        for(int j=0;j<8;j++) v[j] = ((const uint4*)p)[j];
    };
    auto stsA = [&](int b, const uint4* v){
        uint32_t* base = &SA[b*8704 + ((tid&1)*32)*136 + (tid>>1)];
        #pragma unroll
        for(int j=0;j<8;j++){
            base[(j*4+0)*136]=v[j].x; base[(j*4+1)*136]=v[j].y;
            base[(j*4+2)*136]=v[j].z; base[(j*4+3)*136]=v[j].w;
        }
    };
    float acc[2][8][4];
    auto gemm128 = [&](const uint32_t* Ab, const uint32_t* Wb){
        #pragma unroll
        for(int g=0; g<8; g++){
            uint32_t bfr[8][2];
            #pragma unroll
            for(int bn=0;bn<8;bn++){
                int n = warpN + bn*8 + r4;
                bfr[bn][0] = Wb[(g*8+c4)*136 + n];
                bfr[bn][1] = Wb[(g*8+c4+4)*136 + n];
            }
            #pragma unroll
            for(int am=0;am<2;am++){
                int m0 = warpM + am*16 + r4;
                uint32_t af[4] = { Ab[(g*8+c4)*136+m0], Ab[(g*8+c4)*136+m0+8],
                                   Ab[(g*8+c4+4)*136+m0], Ab[(g*8+c4+4)*136+m0+8] };
                #pragma unroll
                for(int bn=0;bn<8;bn++) mma16(acc[am][bn], af, bfr[bn]);
            }
        }
    };

    { uint4 v[8]; ldAfull(blockIdx.x, v); stsA(0, v); }
    int pb = 0;

    for(int tile=blockIdx.x; tile<tiles; tile+=gridDim.x){
        if(tid<128){ sRow[tid]=rowi[tile*128+tid]; sCol[tid]=coli[tile*128+tid]; }
        __syncthreads();
        int nt = tile + gridDim.x;
        bool pf = nt < tiles;
        uint4 an[8];
        if(pf) ldAfull(nt, an);

        #pragma unroll
        for(int am=0;am<2;am++)
            #pragma unroll
            for(int bn=0;bn<8;bn++)
                #pragma unroll
                for(int i=0;i<4;i++) acc[am][bn][i]=0.f;
        gemm128(&SA[pb*8704], SW2);
        if(pf) stsA(pb^1, an);

        #pragma unroll
        for(int am=0;am<2;am++)
            #pragma unroll
            for(int bn=0;bn<8;bn++){
                int c0 = warpN + bn*8 + c4*2;
                float* a = acc[am][bn];
                a[0]=silu_(a[0]+sBias[c0]);   a[1]=silu_(a[1]+sBias[c0+1]);
                a[2]=silu_(a[2]+sBias[c0]);   a[3]=silu_(a[3]+sBias[c0+1]);
            }
        {
            float dot[2][2] = {{0.f,0.f},{0.f,0.f}};
            #pragma unroll
            for(int am=0;am<2;am++)
                #pragma unroll
                for(int bn=0;bn<8;bn++){
                    int c0 = warpN + bn*8 + c4*2;
                    float w0=sAtt[c0], w1=sAtt[c0+1];
                    dot[am][0] += acc[am][bn][0]*w0 + acc[am][bn][1]*w1;
                    dot[am][1] += acc[am][bn][2]*w0 + acc[am][bn][3]*w1;
                }
            #pragma unroll
            for(int am=0;am<2;am++)
                #pragma unroll
                for(int hf=0;hf<2;hf++){
                    dot[am][hf] += __shfl_xor_sync(0xffffffffu, dot[am][hf], 1);
                    dot[am][hf] += __shfl_xor_sync(0xffffffffu, dot[am][hf], 2);
                }
            if(c4==0){
                #pragma unroll
                for(int am=0;am<2;am++){
                    sDot[(wid>>2)*128 + warpM+am*16+r4]   = dot[am][0];
                    sDot[(wid>>2)*128 + warpM+am*16+r4+8] = dot[am][1];
                }
            }
            __syncthreads();
            #pragma unroll
            for(int am=0;am<2;am++)
                #pragma unroll
                for(int hf=0;hf<2;hf++){
                    int rl = warpM + am*16 + r4 + hf*8;
                    float g = sigm(sDot[rl] + sDot[128+rl] + attb);
                    #pragma unroll
                    for(int bn=0;bn<8;bn++){
                        acc[am][bn][hf*2]   *= g;
                        acc[am][bn][hf*2+1] *= g;
                    }
                }
        }
        #pragma unroll
        for(int am=0;am<2;am++)
            #pragma unroll
            for(int hf=0;hf<2;hf++){
                int rl = warpM + am*16 + r4 + hf*8;
                int cc = sCol[rl];
                float* ag = &agg[(size_t)cc*128];
                #pragma unroll
                for(int bn=0;bn<8;bn++){
                    int c0 = warpN + bn*8 + c4*2;
                    float v0 = acc[am][bn][hf*2], v1 = acc[am][bn][hf*2+1];
                    atomicAdd(ag+c0,   v0);
                    atomicAdd(ag+c0+1, v1);
                    SEF[(c0>>1)*136 + rl] = pk2(v0, v1);
                }
                if(warpN==0 && c4==0) atomicAdd(&cnt[cc], 1.f);
            }
        __syncthreads();

        #pragma unroll
        for(int am=0;am<2;am++)
            #pragma unroll
            for(int bn=0;bn<8;bn++)
                #pragma unroll
                for(int i=0;i<4;i++) acc[am][bn][i]=0.f;
        gemm128(SEF, SW3);
        #pragma unroll
        for(int am=0;am<2;am++)
            #pragma unroll
            for(int hf=0;hf<2;hf++){
                int rl = warpM + am*16 + r4 + hf*8;
                #pragma unroll
                for(int bn=0;bn<8;bn++){
                    int c0 = warpN + bn*8 + c4*2;
                    float v0 = silu_(acc[am][bn][hf*2]   + sBias2[c0]);
                    float v1 = silu_(acc[am][bn][hf*2+1] + sBias2[c0+1]);
                    SA[pb*8704 + (c0>>1)*136 + rl] = pk2(v0, v1);
                }
            }
        __syncthreads();

        if(wid < 4){
            float accC[2][2][4];
            #pragma unroll
            for(int am=0;am<2;am++)
                #pragma unroll
                for(int bn=0;bn<2;bn++)
                    #pragma unroll
                    for(int i=0;i<4;i++) accC[am][bn][i]=0.f;
            #pragma unroll
            for(int g=0; g<8; g++){
                uint32_t bfr[2][2];
                #pragma unroll
                for(int bn=0;bn<2;bn++){
                    int n = bn*8 + r4;
                    bfr[bn][0] = SC2P[(g*8+c4)*16 + n];
                    bfr[bn][1] = SC2P[(g*8+c4+4)*16 + n];
                }
                #pragma unroll
                for(int am=0;am<2;am++){
                    int m0 = warpM + am*16 + r4;
                    uint32_t af[4] = { SA[pb*8704+(g*8+c4)*136+m0],
                                       SA[pb*8704+(g*8+c4)*136+m0+8],
                                       SA[pb*8704+(g*8+c4+4)*136+m0],
                                       SA[pb*8704+(g*8+c4+4)*136+m0+8] };
                    #pragma unroll
                    for(int bn=0;bn<2;bn++) mma16(accC[am][bn], af, bfr[bn]);
                }
            }
            float* sCh = (float*)SEF;
            #pragma unroll
            for(int am=0;am<2;am++)
                #pragma unroll
                for(int hf=0;hf<2;hf++){
                    int rl = warpM + am*16 + r4 + hf*8;
                    #pragma unroll
                    for(int bn=0;bn<2;bn++){
                        int c0 = bn*8 + c4*2;
                        sCh[rl*16+c0]   = accC[am][bn][hf*2];
                        sCh[rl*16+c0+1] = accC[am][bn][hf*2+1];
                    }
                }
        }
        __syncthreads();

        if(tid < 128){
            const float* sCh = (const float*)SEF;
            int rl = tid;
            int r = sRow[rl], c = sCol[rl];
            float P[15]; P[0]=0.f;
            #pragma unroll
            for(int j=0;j<14;j++) P[j+1] = P[j] + sCh[rl*16+j] + scb[j];
            int cs = (int)(g_csum[r]+0.5f);
            int w = 15 - cs;
            float invw = 1.f/(float)w;
            float px=g_pool3[c*3], py=g_pool3[c*3+1], pz=g_pool3[c*3+2];
            #pragma unroll
            for(int i=0;i<14;i++){
                int e2 = min(i+w, 14);
                float pooled = (P[e2]-P[i])*invw;
                const float* xp = &x[((size_t)r*14+i)*3];
                atomicAdd(&g_xsum[(r*14+i)*3+0], (xp[0]-px)*pooled);
                atomicAdd(&g_xsum[(r*14+i)*3+1], (xp[1]-py)*pooled);
                atomicAdd(&g_xsum[(r*14+i)*3+2], (xp[2]-pz)*pooled);
            }
            atomicAdd(&g_cnt_row[r], 1.f);
        }
        __syncthreads();
        pb ^= 1;
    }
}

// ===== fused node path: [h|agg] -> n1 -> n2 -> residual+LN -> out =====
#define NODESM 208896
__global__ void __launch_bounds__(256,1) k_node(
    const float* __restrict__ h, const float* __restrict__ n1W,
    const float* __restrict__ n1B, const float* __restrict__ n2W,
    const float* __restrict__ n2B, const float* __restrict__ lng,
    const float* __restrict__ lnb, float* __restrict__ out, int tiles)
{
    extern __shared__ uint32_t dsm[];
    uint32_t* SW1 = dsm;            // 128kp x 136
    uint32_t* SA  = dsm + 17408;    // 128kp x 136
    uint32_t* SW2 = dsm + 34816;    // 64kp x 136
    uint32_t* SH  = dsm + 43520;    // 64kp x 136
    __shared__ float sB1[128], sB2[128], sG[128], sBt[128];
    __shared__ float sSum[256], sSq[256];
    const int tid=threadIdx.x, wid=tid>>5, lane=tid&31;
    const int warpM=(wid&3)*32, warpN=(wid>>2)*64;
    const int r4=lane>>2, c4=lane&3;
    const uint32_t* hbf=(const uint32_t*)g_hbf;

    for(int idx=tid; idx<128*128; idx+=256){
        int kp=idx>>7, n=idx&127;
        SW1[kp*136+n] = pk2(n1W[n*256+2*kp], n1W[n*256+2*kp+1]);
    }
    for(int idx=tid; idx<64*128; idx+=256){
        int kp=idx/128, n=idx%128;
        SW2[kp*136+n] = pk2(n2W[n*128+2*kp], n2W[n*128+2*kp+1]);
    }
    if(tid<128){ sB1[tid]=n1B[tid]; sB2[tid]=n2B[tid]; sG[tid]=lng[tid]; sBt[tid]=lnb[tid]; }
    __syncthreads();

    float acc[2][8][4];
    auto gemmK = [&](const uint32_t* Ab, const uint32_t* Wb, int ng){
        for(int g=0; g<ng; g++){
            uint32_t bfr[8][2];
            #pragma unroll
            for(int bn=0;bn<8;bn++){
                int n = warpN + bn*8 + r4;
                bfr[bn][0] = Wb[(g*8+c4)*136 + n];
                bfr[bn][1] = Wb[(g*8+c4+4)*136 + n];
            }
            #pragma unroll
            for(int am=0;am<2;am++){
                int m0 = warpM + am*16 + r4;
                uint32_t af[4] = { Ab[(g*8+c4)*136+m0], Ab[(g*8+c4)*136+m0+8],
                                   Ab[(g*8+c4+4)*136+m0], Ab[(g*8+c4+4)*136+m0+8] };
                #pragma unroll
                for(int bn=0;bn<8;bn++) mma16(acc[am][bn], af, bfr[bn]);
            }
        }
    };

    for(int tile=blockIdx.x; tile<tiles; tile+=gridDim.x){
        {
            int rl = tid>>1, q = tid&1;
            int n = min(tile*128+rl, NN-1);
            if(q==0){
                const uint4* p = (const uint4*)&hbf[n*64];
                uint32_t* d = &SA[rl];
                #pragma unroll
                for(int j=0;j<16;j++){
                    uint4 u = p[j];
                    d[(j*4+0)*136]=u.x; d[(j*4+1)*136]=u.y;
                    d[(j*4+2)*136]=u.z; d[(j*4+3)*136]=u.w;
                }
            } else {
                float inv = 1.f/fmaxf(g_cnt_col[n],1.f);
                const float4* p = (const float4*)&g_aggsum[(size_t)n*128];
                uint32_t* d = &SA[64*136 + rl];
                #pragma unroll
                for(int j=0;j<32;j++){
                    float4 v = p[j];
                    d[(j*2+0)*136]=pk2(v.x*inv, v.y*inv);
                    d[(j*2+1)*136]=pk2(v.z*inv, v.w*inv);
                }
            }
        }
        __syncthreads();
        #pragma unroll
        for(int am=0;am<2;am++)
            #pragma unroll
            for(int bn=0;bn<8;bn++)
                #pragma unroll
                for(int i=0;i<4;i++) acc[am][bn][i]=0.f;
        gemmK(SA, SW1, 16);
        #pragma unroll
        for(int am=0;am<2;am++)
            #pragma unroll
            for(int hf=0;hf<2;hf++){
                int rl = warpM + am*16 + r4 + hf*8;
                #pragma unroll
                for(int bn=0;bn<8;bn++){
                    int c0 = warpN + bn*8 + c4*2;
                    float v0 = silu_(acc[am][bn][hf*2]   + sB1[c0]);
                    float v1 = silu_(acc[am][bn][hf*2+1] + sB1[c0+1]);
                    SH[(c0>>1)*136 + rl] = pk2(v0, v1);
                }
            }
        __syncthreads();
        #pragma unroll
        for(int am=0;am<2;am++)
            #pragma unroll
            for(int bn=0;bn<8;bn++)
                #pragma unroll
                for(int i=0;i<4;i++) acc[am][bn][i]=0.f;
        gemmK(SH, SW2, 8);
        #pragma unroll
        for(int am=0;am<2;am++)
            #pragma unroll
            for(int hf=0;hf<2;hf++){
                int rl = warpM + am*16 + r4 + hf*8;
                int rg = tile*128 + rl;
                int hn = min(rg, NN-1);
                float s=0.f, sq=0.f;
                #pragma unroll
                for(int bn=0;bn<8;bn++){
                    int c0 = warpN + bn*8 + c4*2;
                    float y0 = acc[am][bn][hf*2]   + sB2[c0]   + h[(size_t)hn*128+c0];
                    float y1 = acc[am][bn][hf*2+1] + sB2[c0+1] + h[(size_t)hn*128+c0+1];
                    acc[am][bn][hf*2]=y0; acc[am][bn][hf*2+1]=y1;
                    s += y0+y1; sq += y0*y0+y1*y1;
                }
                s  += __shfl_xor_sync(0xffffffffu, s, 1);
                s  += __shfl_xor_sync(0xffffffffu, s, 2);
                sq += __shfl_xor_sync(0xffffffffu, sq, 1);
                sq += __shfl_xor_sync(0xffffffffu, sq, 2);
                if(c4==0){
                    sSum[(wid>>2)*128+rl]=s;
                    sSq[(wid>>2)*128+rl]=sq;
                }
            }
        __syncthreads();
        #pragma unroll
        for(int am=0;am<2;am++)
            #pragma unroll
            for(int hf=0;hf<2;hf++){
                int rl = warpM + am*16 + r4 + hf*8;
                int rg = tile*128 + rl;
                if(rg < NN){
                    float tot = sSum[rl]+sSum[128+rl];
                    float mu = tot*(1.f/128.f);
                    float var = (sSq[rl]+sSq[128+rl])*(1.f/128.f) - mu*mu;
                    float is = rsqrtf(fmaxf(var,0.f)+1e-5f);
                    float* op = &out[(size_t)rg*128];
                    #pragma unroll
                    for(int bn=0;bn<8;bn++){
                        int c0 = warpN + bn*8 + c4*2;
                        op[c0]   = (acc[am][bn][hf*2]  -mu)*is*sG[c0]  +sBt[c0];
                        op[c0+1] = (acc[am][bn][hf*2+1]-mu)*is*sG[c0+1]+sBt[c0+1];
                    }
                }
            }
        __syncthreads();
    }
}

// ---------------- x_out ----------------
__global__ void k_xout(const float* __restrict__ x, float* __restrict__ xout){
    int idx = blockIdx.x*blockDim.x + threadIdx.x;
    if(idx >= NN*CC*3) return;
    int n = idx/(CC*3);
    xout[idx] = x[idx] + g_xsum[idx]/fmaxf(g_cnt_row[n],1.f);
}

// ======================= host launcher =======================
extern "C" void kernel_launch(void* const* d_in, const int* in_sizes, int n_in,
                              void* d_out, int out_size){
    const float* h    = (const float*)d_in[0];
    const float* x    = (const float*)d_in[1];
    const int*   row  = (const int*)  d_in[2];
    const int*   col  = (const int*)  d_in[3];
    const float* attr = (const float*)d_in[4];
    const float* cw   = (const float*)d_in[5];
    const float* radW = (const float*)d_in[6];  const float* radB = (const float*)d_in[7];
    const float* e1W  = (const float*)d_in[8];  const float* e1B  = (const float*)d_in[9];
    const float* e2W  = (const float*)d_in[10]; const float* e2B  = (const float*)d_in[11];
    const float* attW = (const float*)d_in[12]; const float* attB = (const float*)d_in[13];
    const float* c1W  = (const float*)d_in[14]; const float* c1B  = (const float*)d_in[15];
    const float* c2W  = (const float*)d_in[16]; const float* c2B  = (const float*)d_in[17];
    const float* n1W  = (const float*)d_in[18]; const float* n1B  = (const float*)d_in[19];
    const float* n2W  = (const float*)d_in[20]; const float* n2B  = (const float*)d_in[21];
    const float* lng  = (const float*)d_in[22]; const float* lnb  = (const float*)d_in[23];
    float* outH = (float*)d_out;
    float* outX = outH + (size_t)NN*128;

    void *p_agg,*p_cntc;
    cudaGetSymbolAddress(&p_agg,  g_aggsum);
    cudaGetSymbolAddress(&p_cntc, g_cnt_col);

    cudaFuncSetAttribute(k_e1,   cudaFuncAttributeMaxDynamicSharedMemorySize, E1SM);
    cudaFuncSetAttribute(k_e2c1, cudaFuncAttributeMaxDynamicSharedMemorySize, E2SM);
    cudaFuncSetAttribute(k_node, cudaFuncAttributeMaxDynamicSharedMemorySize, NODESM);

    k_prepall<<<(int)((PREP_TOTAL+255)/256), 256>>>(x, cw, h, attr, e2W, c1W);
    k_waug<<<128, 256>>>(e1W, radW, radB);
    k_geom<<<NE/8, 256>>>(x, row, col, cw);

    // ef1(bf16) = silu([h_r|h_c|radial'|rinv] @ Waug^T + e1B)
    k_e1<<<304,256,E1SM>>>(e1B, row, col, TE128);
    // fused e2+gate+agg + c1 + c2 + roller + trans scatter
    k_e2c1<<<148,256,E2SM>>>(e2B, c1B, c2W, c2B, row, col, attW, attB,
                             x, (float*)p_agg, (float*)p_cntc, TE128);
    // fused node path -> outH
    k_node<<<TN128,256,NODESM>>>(h, n1W, n1B, n2W, n2B, lng, lnb, outH, TN128);
    k_xout<<<(NN*CC*3+255)/256, 256>>>(x, outX);
}

// round 13
// speedup vs baseline: 6.3822x; 1.0407x over previous
#include <cuda_runtime.h>
#include <cuda_bf16.h>
#include <math.h>
#include <stdint.h>

#define NN 20000
#define NE 320000
#define CC 14
#define TE128 (NE/128)              // 2500
#define TN128 ((NN+127)/128)        // 157

// ---------------- scratch ----------------
__device__ __align__(16) float g_radial[(size_t)NE*128];  // bf16 [E][256] = radial*rinv
__device__ __align__(16) float g_ef1[(size_t)NE*64];      // bf16 [E][128] e1 out
__device__ float g_rinv[NE];
__device__ float g_csum[NN];
__device__ float g_pool3[NN*3];
__device__ float g_aggsum[(size_t)NN*128];
__device__ float g_cnt_col[NN];
__device__ float g_xsum[NN*CC*3];
__device__ float g_cnt_row[NN];
__device__ __align__(16) float g_hbf[NN*64];      // bf16 h
__device__ __align__(16) float g_abf[NN*112];     // bf16 attr
__device__ __align__(16) float g_waug[128*272];   // bf16 [128][544] augmented e1 weight
__device__ __align__(16) float g_we2[128*64];     // bf16 e2W
__device__ __align__(16) float g_wc1[128*64];     // bf16 c1W

__device__ __forceinline__ float sigm(float v){ return 1.f/(1.f+__expf(-v)); }
__device__ __forceinline__ float silu_(float v){ return v*sigm(v); }
__device__ __forceinline__ uint32_t pk2(float lo, float hi){
    __nv_bfloat162 t = __floats2bfloat162_rn(lo, hi);
    return *(uint32_t*)&t;
}
__device__ __forceinline__ void mma16(float* c, const uint32_t* a, const uint32_t* b){
    asm volatile("mma.sync.aligned.m16n8k16.row.col.f32.bf16.bf16.f32 "
        "{%0,%1,%2,%3}, {%4,%5,%6,%7}, {%8,%9}, {%0,%1,%2,%3};"
        : "+f"(c[0]),"+f"(c[1]),"+f"(c[2]),"+f"(c[3])
        : "r"(a[0]),"r"(a[1]),"r"(a[2]),"r"(a[3]), "r"(b[0]),"r"(b[1]));
}
__device__ __forceinline__ void red2(float* addr, float a, float b){
    asm volatile("red.global.add.v2.f32 [%0], {%1, %2};"
        :: "l"(addr), "f"(a), "f"(b) : "memory");
}

// ---------------- merged prep: zero + hconv + aconv + wcvt + nodeprep -------
__global__ void k_prepall(const float* __restrict__ x, const float* __restrict__ cw,
                          const float* __restrict__ h, const float* __restrict__ attr,
                          const float* __restrict__ e2W, const float* __restrict__ c1W){
    long long i = (long long)blockIdx.x*256 + threadIdx.x;
    const long long ZA = (long long)NN*128;
    const long long ZB = ZA + NN;
    const long long ZD = ZB + (long long)NN*42;
    const long long ZE = ZD + NN;
    const long long HC = ZE + (long long)NN*64;
    const long long AC = HC + (long long)NN*112;
    const long long WC = AC + 2*128*64;
    const long long PR = WC + NN;
    if(i < ZA) g_aggsum[i]=0.f;
    else if(i < ZB) g_cnt_col[i-ZA]=0.f;
    else if(i < ZD) g_xsum[i-ZB]=0.f;
    else if(i < ZE) g_cnt_row[i-ZD]=0.f;
    else if(i < HC){ long long j=i-ZE; float2 v=((const float2*)h)[j];
        ((uint32_t*)g_hbf)[j]=pk2(v.x,v.y); }
    else if(i < AC){ long long j=i-HC; float2 v=((const float2*)attr)[j];
        ((uint32_t*)g_abf)[j]=pk2(v.x,v.y); }
    else if(i < WC){ long long j=i-AC;
        if(j < 128*64){ float2 v=((const float2*)e2W)[j]; ((uint32_t*)g_we2)[j]=pk2(v.x,v.y); }
        else { long long k=j-128*64; float2 v=((const float2*)c1W)[k]; ((uint32_t*)g_wc1)[k]=pk2(v.x,v.y); }
    }
    else if(i < PR){
        int n = (int)(i-WC);
        float cnt=0.f, px=0.f, py=0.f, pz=0.f;
        #pragma unroll
        for(int k=0;k<CC;k++){
            float w = cw[n*CC+k];
            if(w != 0.f){
                cnt += 1.f;
                const float* xp = &x[(n*CC+k)*3];
                px += xp[0]; py += xp[1]; pz += xp[2];
            }
        }
        g_csum[n] = cnt;
        float inv = 1.f/cnt;
        g_pool3[n*3+0]=px*inv; g_pool3[n*3+1]=py*inv; g_pool3[n*3+2]=pz*inv;
    }
}
#define PREP_TOTAL ((long long)NN*128 + NN + (long long)NN*42 + NN + (long long)NN*64 + (long long)NN*112 + 2*128*64 + NN)

// ---------------- build augmented e1 weight (bf16, 272 kp = 544 k) ----------
__global__ void k_waug(const float* __restrict__ e1W, const float* __restrict__ radW,
                       const float* __restrict__ radB){
    __shared__ float s[128];
    int n = blockIdx.x, tid = threadIdx.x;
    if(tid < 128) s[tid] = e1W[n*384 + 256 + tid];
    __syncthreads();
    uint32_t* out = (uint32_t*)g_waug + n*272;
    if(tid < 128) out[tid] = pk2(e1W[n*384 + 2*tid], e1W[n*384 + 2*tid + 1]);
    else if(tid-128 < 128){
        int kpl = tid-128;
        int kk = 2*kpl;
        float d0=0.f, d1=0.f;
        #pragma unroll 4
        for(int j=0;j<128;j++){
            float sj = s[j];
            d0 += sj*radW[j*256+kk];
            d1 += sj*radW[j*256+kk+1];
        }
        out[128+kpl] = pk2(d0,d1);
    }
    if(tid==0){
        float bc=0.f;
        for(int j=0;j<128;j++) bc += s[j]*radB[j];
        out[256] = pk2(bc, 0.f);
    }
    if(tid>=1 && tid<16) out[256+tid] = 0u;
}

// ---------------- geometry via tensor cores: 4 MMAs per edge ---------------
__global__ void __launch_bounds__(256) k_geom(const float* __restrict__ x,
        const int* __restrict__ row, const int* __restrict__ col,
        const float* __restrict__ cw){
    __shared__ float sX[8][88];
    __shared__ float sCW[8][32];
    __shared__ uint32_t sAR[8][112];
    __shared__ uint32_t sAC[8][112];
    __shared__ float sT[8][256];
    const int warp=threadIdx.x>>5, lane=threadIdx.x&31;
    const int e = blockIdx.x*8 + warp;
    if(e >= NE) return;
    const int r=row[e], c=col[e];
    const uint32_t* ab=(const uint32_t*)g_abf;
    if(lane<CC){ sCW[warp][lane]=cw[r*CC+lane]; sCW[warp][16+lane]=cw[c*CC+lane]; }
    if(lane==0){ atomicAdd(&g_cnt_row[r],1.f); atomicAdd(&g_cnt_col[c],1.f); }
    for(int i=lane;i<42;i+=32){ sX[warp][i]=x[r*42+i]; sX[warp][44+i]=x[c*42+i]; }
    for(int i=lane;i<112;i+=32){ sAR[warp][i]=ab[r*112+i]; sAC[warp][i]=ab[c*112+i]; }
    __syncwarp();
    const int r4=lane>>2, c4=lane&3;
    auto dist=[&](int i,int j)->float{
        if(i>=CC||j>=CC) return 0.f;
        float dx=sX[warp][i*3]  -sX[warp][44+j*3];
        float dy=sX[warp][i*3+1]-sX[warp][44+j*3+1];
        float dz=sX[warp][i*3+2]-sX[warp][44+j*3+2];
        return sqrtf(dx*dx+dy*dy+dz*dz);
    };
    uint32_t aD[4];
    {
        int j0=2*c4, j2=2*c4+8;
        aD[0]=pk2(dist(r4,j0),  dist(r4,j0+1));
        aD[1]=pk2(dist(r4+8,j0),dist(r4+8,j0+1));
        aD[2]=pk2(dist(r4,j2),  dist(r4,j2+1));
        aD[3]=pk2(dist(r4+8,j2),dist(r4+8,j2+1));
    }
    auto acv=[&](int j,int b)->float{
        if(j>=CC) return 0.f;
        uint32_t w = sAC[warp][j*8 + (b>>1)];
        __nv_bfloat162 t=*(__nv_bfloat162*)&w;
        float v=(b&1)? __high2float(t): __low2float(t);
        return v*sCW[warp][16+j];
    };
    float T0[4]={0,0,0,0}, T1[4]={0,0,0,0};
    {
        uint32_t b0[2], b1[2];
        b0[0]=pk2(acv(2*c4,r4),    acv(2*c4+1,r4));
        b0[1]=pk2(acv(2*c4+8,r4),  acv(2*c4+9,r4));
        b1[0]=pk2(acv(2*c4,r4+8),  acv(2*c4+1,r4+8));
        b1[1]=pk2(acv(2*c4+8,r4+8),acv(2*c4+9,r4+8));
        mma16(T0,aD,b0);
        mma16(T1,aD,b1);
    }
    {
        float* st=sT[warp];
        st[r4*16+2*c4]       =T0[0]; st[r4*16+2*c4+1]     =T0[1];
        st[(r4+8)*16+2*c4]   =T0[2]; st[(r4+8)*16+2*c4+1] =T0[3];
        st[r4*16+8+2*c4]     =T1[0]; st[r4*16+8+2*c4+1]   =T1[1];
        st[(r4+8)*16+8+2*c4] =T1[2]; st[(r4+8)*16+8+2*c4+1]=T1[3];
    }
    __syncwarp();
    auto arv=[&](int i,int a)->float{
        if(i>=CC) return 0.f;
        uint32_t w = sAR[warp][i*8 + (a>>1)];
        __nv_bfloat162 t=*(__nv_bfloat162*)&w;
        float v=(a&1)? __high2float(t): __low2float(t);
        return v*sCW[warp][i];
    };
    uint32_t aR[4];
    aR[0]=pk2(arv(2*c4,r4),    arv(2*c4+1,r4));
    aR[1]=pk2(arv(2*c4,r4+8),  arv(2*c4+1,r4+8));
    aR[2]=pk2(arv(2*c4+8,r4),  arv(2*c4+9,r4));
    aR[3]=pk2(arv(2*c4+8,r4+8),arv(2*c4+9,r4+8));
    float R0[4]={0,0,0,0}, R1[4]={0,0,0,0};
    {
        const float* st=sT[warp];
        uint32_t b0[2], b1[2];
        b0[0]=pk2(st[(2*c4)*16+r4],    st[(2*c4+1)*16+r4]);
        b0[1]=pk2(st[(2*c4+8)*16+r4],  st[(2*c4+9)*16+r4]);
        b1[0]=pk2(st[(2*c4)*16+r4+8],  st[(2*c4+1)*16+r4+8]);
        b1[1]=pk2(st[(2*c4+8)*16+r4+8],st[(2*c4+9)*16+r4+8]);
        mma16(R0,aR,b0);
        mma16(R1,aR,b1);
    }
    float sq = R0[0]*R0[0]+R0[1]*R0[1]+R0[2]*R0[2]+R0[3]*R0[3]
             + R1[0]*R1[0]+R1[1]*R1[1]+R1[2]*R1[2]+R1[3]*R1[3];
    #pragma unroll
    for(int o=16;o>0;o>>=1) sq += __shfl_xor_sync(0xffffffffu,sq,o);
    float rinv = 1.f/(sqrtf(sq)+1.f);
    uint32_t* go=(uint32_t*)g_radial + (size_t)e*128;
    go[r4*8 + c4]         = pk2(R0[0]*rinv, R0[1]*rinv);
    go[(r4+8)*8 + c4]     = pk2(R0[2]*rinv, R0[3]*rinv);
    go[r4*8 + 4 + c4]     = pk2(R1[0]*rinv, R1[1]*rinv);
    go[(r4+8)*8 + 4 + c4] = pk2(R1[2]*rinv, R1[3]*rinv);
    if(lane==0) g_rinv[e]=rinv;
}

// ===== e1 GEMM: K=544, BK=32, 3-stage smem ring, prefetch distance 2 =====
#define E1SM 53760
__global__ void __launch_bounds__(256,2) k_e1(
    const float* __restrict__ e1B, const int* __restrict__ rowi,
    const int* __restrict__ coli, int tiles)
{
    extern __shared__ uint32_t dsm[];
    uint32_t* SA = dsm;
    uint32_t* SW = dsm + 6528;
    int* sRow = (int*)(dsm + 13056);
    int* sCol = sRow + 128;
    float* sBias = (float*)(sCol + 128);
    const int tid=threadIdx.x, wid=tid>>5, lane=tid&31;
    const int warpM=(wid&3)*32, warpN=(wid>>2)*64;
    const int ee=tid>>1, q=tid&1;
    const int r4=lane>>2, c4=lane&3;
    const uint32_t* hbf=(const uint32_t*)g_hbf;
    const uint32_t* rad=(const uint32_t*)g_radial;
    const uint32_t* waug=(const uint32_t*)g_waug;
    uint32_t* Obf=(uint32_t*)g_ef1;
    if(tid<128) sBias[tid]=e1B[tid];

    for(int tile=blockIdx.x; tile<tiles; tile+=gridDim.x){
        if(tid<128){ sRow[tid]=rowi[tile*128+tid]; sCol[tid]=coli[tile*128+tid]; }
        __syncthreads();
        const int rg = tile*128 + ee;
        auto ldA = [&](int kt, uint4& u0, uint4& u1){
            const int kp = kt*16 + q*8;
            if(kp < 64){ const uint32_t* p=&hbf[sRow[ee]*64+kp];
                u0=*(const uint4*)p; u1=*(const uint4*)(p+4); }
            else if(kp < 128){ const uint32_t* p=&hbf[sCol[ee]*64+(kp-64)];
                u0=*(const uint4*)p; u1=*(const uint4*)(p+4); }
            else if(kp < 256){ const uint32_t* p=&rad[(size_t)rg*128+(kp-128)];
                u0=*(const uint4*)p; u1=*(const uint4*)(p+4); }
            else if(kp == 256){ u0=make_uint4(pk2(g_rinv[rg],0.f),0u,0u,0u);
                u1=make_uint4(0u,0u,0u,0u); }
            else { u0=make_uint4(0u,0u,0u,0u); u1=u0; }
        };
        auto ldW = [&](int kt, uint4& u0, uint4& u1){
            const uint32_t* p=&waug[ee*272 + kt*16 + q*8];
            u0=*(const uint4*)p; u1=*(const uint4*)(p+4);
        };
        auto sts = [&](int b, uint4 a0, uint4 a1, uint4 w0, uint4 w1){
            uint32_t* pa=&SA[b*2176 + (q*8)*136 + ee];
            pa[0]=a0.x; pa[136]=a0.y; pa[272]=a0.z; pa[408]=a0.w;
            pa[544]=a1.x; pa[680]=a1.y; pa[816]=a1.z; pa[952]=a1.w;
            uint32_t* pw=&SW[b*2176 + (q*8)*136 + ee];
            pw[0]=w0.x; pw[136]=w0.y; pw[272]=w0.z; pw[408]=w0.w;
            pw[544]=w1.x; pw[680]=w1.y; pw[816]=w1.z; pw[952]=w1.w;
        };

        float acc[2][8][4];
        #pragma unroll
        for(int am=0;am<2;am++)
            #pragma unroll
            for(int bn=0;bn<8;bn++)
                #pragma unroll
                for(int i=0;i<4;i++) acc[am][bn][i]=0.f;

        uint4 a0,a1,w0,w1;
        ldA(0,a0,a1); ldW(0,w0,w1); sts(0,a0,a1,w0,w1);
        ldA(1,a0,a1); ldW(1,w0,w1); sts(1,a0,a1,w0,w1);
        __syncthreads();

        #pragma unroll 1
        for(int kt=0; kt<17; kt++){
            bool pf = kt < 15;
            if(pf){ ldA(kt+2,a0,a1); ldW(kt+2,w0,w1); }
            const uint32_t* Ab=&SA[(kt%3)*2176];
            const uint32_t* Wb=&SW[(kt%3)*2176];
            #pragma unroll
            for(int g=0; g<2; g++){
                uint32_t bfr[8][2];
                #pragma unroll
                for(int bn=0;bn<8;bn++){
                    int n = warpN + bn*8 + r4;
                    bfr[bn][0] = Wb[(g*8+c4)*136 + n];
                    bfr[bn][1] = Wb[(g*8+c4+4)*136 + n];
                }
                #pragma unroll
                for(int am=0;am<2;am++){
                    int m0 = warpM + am*16 + r4;
                    uint32_t af[4] = { Ab[(g*8+c4)*136+m0], Ab[(g*8+c4)*136+m0+8],
                                       Ab[(g*8+c4+4)*136+m0], Ab[(g*8+c4+4)*136+m0+8] };
                    #pragma unroll
                    for(int bn=0;bn<8;bn++) mma16(acc[am][bn], af, bfr[bn]);
                }
            }
            if(pf) sts((kt+2)%3, a0,a1,w0,w1);
            __syncthreads();
        }

        #pragma unroll
        for(int am=0;am<2;am++)
            #pragma unroll
            for(int hf=0;hf<2;hf++){
                int rl = warpM + am*16 + r4 + hf*8;
                int rgo = tile*128 + rl;
                uint32_t* op = &Obf[(size_t)rgo*64];
                #pragma unroll
                for(int bn=0;bn<8;bn++){
                    int c0 = warpN + bn*8 + c4*2;
                    float v0 = silu_(acc[am][bn][hf*2]   + sBias[c0]);
                    float v1 = silu_(acc[am][bn][hf*2+1] + sBias[c0+1]);
                    op[c0>>1] = pk2(v0, v1);
                }
            }
        __syncthreads();
    }
}

// ===== fused e2 + gate + agg + c1 + c2 + roller + trans scatter ==========
#define E2SM 181824
__global__ void __launch_bounds__(256) k_e2c1(
    const float* __restrict__ e2B, const float* __restrict__ c1B,
    const float* __restrict__ c2Wf, const float* __restrict__ c2bf,
    const int* __restrict__ rowi, const int* __restrict__ coli,
    const float* __restrict__ attWg, const float* __restrict__ attbg,
    const float* __restrict__ x,
    float* __restrict__ agg, float* __restrict__ cnt, int tiles)
{
    extern __shared__ uint32_t dsm[];
    uint32_t* SA   = dsm;
    uint32_t* SW2  = dsm + 17408;
    uint32_t* SW3  = dsm + 26112;
    uint32_t* SEF  = dsm + 34816;
    uint32_t* SC2P = dsm + 43520;
    int*   sRow   = (int*)(dsm + 44544);
    int*   sCol   = sRow + 128;
    float* sBias  = (float*)(sCol + 128);
    float* sBias2 = sBias + 128;
    float* sAtt   = sBias2 + 128;
    float* sDot   = sAtt + 128;
    float* scb    = sDot + 256;
    const int tid=threadIdx.x, wid=tid>>5, lane=tid&31;
    const int warpM=(wid&3)*32, warpN=(wid>>2)*64;
    const int r4=lane>>2, c4=lane&3;
    const uint32_t* Abf=(const uint32_t*)g_ef1;
    const uint32_t* W2g=(const uint32_t*)g_we2;
    const uint32_t* W3g=(const uint32_t*)g_wc1;

    for(int idx=tid; idx<128*64; idx+=256){
        int n = idx>>6, kp = idx&63;
        SW2[kp*136+n] = W2g[idx];
        SW3[kp*136+n] = W3g[idx];
    }
    for(int idx=tid; idx<64*16; idx+=256){
        int kp = idx>>4, n = idx&15;
        SC2P[idx] = (n<14)? pk2(c2Wf[n*128+2*kp], c2Wf[n*128+2*kp+1]) : 0u;
    }
    if(tid<16) scb[tid] = (tid<14)? c2bf[tid] : 0.f;
    if(tid<128){ sBias[tid]=e2B[tid]; sBias2[tid]=c1B[tid]; sAtt[tid]=attWg[tid]; }
    const float attb = attbg[0];

    auto ldAfull = [&](int t, uint4* v){
        const uint32_t* p = &Abf[(size_t)(t*128 + (tid>>1))*64 + (tid&1)*32];
        #pragma unroll
        for(int j=0;j<8;j++) v[j] = ((const uint4*)p)[j];
    };
    auto stsA = [&](int b, const uint4* v){
        uint32_t* base = &SA[b*8704 + ((tid&1)*32)*136 + (tid>>1)];
        #pragma unroll
        for(int j=0;j<8;j++){
            base[(j*4+0)*136]=v[j].x; base[(j*4+1)*136]=v[j].y;
            base[(j*4+2)*136]=v[j].z; base[(j*4+3)*136]=v[j].w;
        }
    };
    float acc[2][8][4];
    auto gemm128 = [&](const uint32_t* Ab, const uint32_t* Wb){
        #pragma unroll
        for(int g=0; g<8; g++){
            uint32_t bfr[8][2];
            #pragma unroll
            for(int bn=0;bn<8;bn++){
                int n = warpN + bn*8 + r4;
                bfr[bn][0] = Wb[(g*8+c4)*136 + n];
                bfr[bn][1] = Wb[(g*8+c4+4)*136 + n];
            }
            #pragma unroll
            for(int am=0;am<2;am++){
                int m0 = warpM + am*16 + r4;
                uint32_t af[4] = { Ab[(g*8+c4)*136+m0], Ab[(g*8+c4)*136+m0+8],
                                   Ab[(g*8+c4+4)*136+m0], Ab[(g*8+c4+4)*136+m0+8] };
                #pragma unroll
                for(int bn=0;bn<8;bn++) mma16(acc[am][bn], af, bfr[bn]);
            }
        }
    };

    { uint4 v[8]; ldAfull(blockIdx.x, v); stsA(0, v); }
    int pb = 0;

    for(int tile=blockIdx.x; tile<tiles; tile+=gridDim.x){
        if(tid<128){ sRow[tid]=rowi[tile*128+tid]; sCol[tid]=coli[tile*128+tid]; }
        __syncthreads();
        int nt = tile + gridDim.x;
        bool pf = nt < tiles;
        uint4 an[8];
        if(pf) ldAfull(nt, an);

        #pragma unroll
        for(int am=0;am<2;am++)
            #pragma unroll
            for(int bn=0;bn<8;bn++)
                #pragma unroll
                for(int i=0;i<4;i++) acc[am][bn][i]=0.f;
        gemm128(&SA[pb*8704], SW2);
        if(pf) stsA(pb^1, an);

        #pragma unroll
        for(int am=0;am<2;am++)
            #pragma unroll
            for(int bn=0;bn<8;bn++){
                int c0 = warpN + bn*8 + c4*2;
                float* a = acc[am][bn];
                a[0]=silu_(a[0]+sBias[c0]);   a[1]=silu_(a[1]+sBias[c0+1]);
                a[2]=silu_(a[2]+sBias[c0]);   a[3]=silu_(a[3]+sBias[c0+1]);
            }
        {
            float dot[2][2] = {{0.f,0.f},{0.f,0.f}};
            #pragma unroll
            for(int am=0;am<2;am++)
                #pragma unroll
                for(int bn=0;bn<8;bn++){
                    int c0 = warpN + bn*8 + c4*2;
                    float w0=sAtt[c0], w1=sAtt[c0+1];
                    dot[am][0] += acc[am][bn][0]*w0 + acc[am][bn][1]*w1;
                    dot[am][1] += acc[am][bn][2]*w0 + acc[am][bn][3]*w1;
                }
            #pragma unroll
            for(int am=0;am<2;am++)
                #pragma unroll
                for(int hf=0;hf<2;hf++){
                    dot[am][hf] += __shfl_xor_sync(0xffffffffu, dot[am][hf], 1);
                    dot[am][hf] += __shfl_xor_sync(0xffffffffu, dot[am][hf], 2);
                }
            if(c4==0){
                #pragma unroll
                for(int am=0;am<2;am++){
                    sDot[(wid>>2)*128 + warpM+am*16+r4]   = dot[am][0];
                    sDot[(wid>>2)*128 + warpM+am*16+r4+8] = dot[am][1];
                }
            }
            __syncthreads();
            #pragma unroll
            for(int am=0;am<2;am++)
                #pragma unroll
                for(int hf=0;hf<2;hf++){
                    int rl = warpM + am*16 + r4 + hf*8;
                    float g = sigm(sDot[rl] + sDot[128+rl] + attb);
                    #pragma unroll
                    for(int bn=0;bn<8;bn++){
                        acc[am][bn][hf*2]   *= g;
                        acc[am][bn][hf*2+1] *= g;
                    }
                }
        }
        // scatter agg (vector red) + stage ef into SEF
        #pragma unroll
        for(int am=0;am<2;am++)
            #pragma unroll
            for(int hf=0;hf<2;hf++){
                int rl = warpM + am*16 + r4 + hf*8;
                int cc = sCol[rl];
                float* ag = &agg[(size_t)cc*128];
                #pragma unroll
                for(int bn=0;bn<8;bn++){
                    int c0 = warpN + bn*8 + c4*2;
                    float v0 = acc[am][bn][hf*2], v1 = acc[am][bn][hf*2+1];
                    red2(ag+c0, v0, v1);
                    SEF[(c0>>1)*136 + rl] = pk2(v0, v1);
                }
            }
        __syncthreads();

        #pragma unroll
        for(int am=0;am<2;am++)
            #pragma unroll
            for(int bn=0;bn<8;bn++)
                #pragma unroll
                for(int i=0;i<4;i++) acc[am][bn][i]=0.f;
        gemm128(SEF, SW3);
        #pragma unroll
        for(int am=0;am<2;am++)
            #pragma unroll
            for(int hf=0;hf<2;hf++){
                int rl = warpM + am*16 + r4 + hf*8;
                #pragma unroll
                for(int bn=0;bn<8;bn++){
                    int c0 = warpN + bn*8 + c4*2;
                    float v0 = silu_(acc[am][bn][hf*2]   + sBias2[c0]);
                    float v1 = silu_(acc[am][bn][hf*2+1] + sBias2[c0+1]);
                    SA[pb*8704 + (c0>>1)*136 + rl] = pk2(v0, v1);
                }
            }
        __syncthreads();

        if(wid < 4){
            float accC[2][2][4];
            #pragma unroll
            for(int am=0;am<2;am++)
                #pragma unroll
                for(int bn=0;bn<2;bn++)
                    #pragma unroll
                    for(int i=0;i<4;i++) accC[am][bn][i]=0.f;
            #pragma unroll
            for(int g=0; g<8; g++){
                uint32_t bfr[2][2];
                #pragma unroll
                for(int bn=0;bn<2;bn++){
                    int n = bn*8 + r4;
                    bfr[bn][0] = SC2P[(g*8+c4)*16 + n];
                    bfr[bn][1] = SC2P[(g*8+c4+4)*16 + n];
                }
                #pragma unroll
                for(int am=0;am<2;am++){
                    int m0 = warpM + am*16 + r4;
                    uint32_t af[4] = { SA[pb*8704+(g*8+c4)*136+m0],
                                       SA[pb*8704+(g*8+c4)*136+m0+8],
                                       SA[pb*8704+(g*8+c4+4)*136+m0],
                                       SA[pb*8704+(g*8+c4+4)*136+m0+8] };
                    #pragma unroll
                    for(int bn=0;bn<2;bn++) mma16(accC[am][bn], af, bfr[bn]);
                }
            }
            float* sCh = (float*)SEF;
            #pragma unroll
            for(int am=0;am<2;am++)
                #pragma unroll
                for(int hf=0;hf<2;hf++){
                    int rl = warpM + am*16 + r4 + hf*8;
                    #pragma unroll
                    for(int bn=0;bn<2;bn++){
                        int c0 = bn*8 + c4*2;
                        sCh[rl*16+c0]   = accC[am][bn][hf*2];
                        sCh[rl*16+c0+1] = accC[am][bn][hf*2+1];
                    }
                }
        }
        __syncthreads();

        if(tid < 128){
            const float* sCh = (const float*)SEF;
            int rl = tid;
            int r = sRow[rl], c = sCol[rl];
            float P[15]; P[0]=0.f;
            #pragma unroll
            for(int j=0;j<14;j++) P[j+1] = P[j] + sCh[rl*16+j] + scb[j];
            int cs = (int)(g_csum[r]+0.5f);
            int w = 15 - cs;
            float invw = 1.f/(float)w;
            float px=g_pool3[c*3], py=g_pool3[c*3+1], pz=g_pool3[c*3+2];
            float vals[42];
            #pragma unroll
            for(int i=0;i<14;i++){
                int e2 = min(i+w, 14);
                float pooled = (P[e2]-P[i])*invw;
                const float* xp = &x[((size_t)r*14+i)*3];
                vals[i*3+0] = (xp[0]-px)*pooled;
                vals[i*3+1] = (xp[1]-py)*pooled;
                vals[i*3+2] = (xp[2]-pz)*pooled;
            }
            float* base = &g_xsum[r*42];
            #pragma unroll
            for(int t=0;t<21;t++) red2(base+2*t, vals[2*t], vals[2*t+1]);
        }
        __syncthreads();
        pb ^= 1;
    }
}

// ===== fused node path: [h|agg] -> n1 -> n2 -> residual+LN -> out =====
#define NODESM 208896
__global__ void __launch_bounds__(256,1) k_node(
    const float* __restrict__ h, const float* __restrict__ n1W,
    const float* __restrict__ n1B, const float* __restrict__ n2W,
    const float* __restrict__ n2B, const float* __restrict__ lng,
    const float* __restrict__ lnb, float* __restrict__ out, int tiles)
{
    extern __shared__ uint32_t dsm[];
    uint32_t* SW1 = dsm;
    uint32_t* SA  = dsm + 17408;
    uint32_t* SW2 = dsm + 34816;
    uint32_t* SH  = dsm + 43520;
    __shared__ float sB1[128], sB2[128], sG[128], sBt[128];
    __shared__ float sSum[256], sSq[256];
    const int tid=threadIdx.x, wid=tid>>5, lane=tid&31;
    const int warpM=(wid&3)*32, warpN=(wid>>2)*64;
    const int r4=lane>>2, c4=lane&3;
    const uint32_t* hbf=(const uint32_t*)g_hbf;

    for(int idx=tid; idx<128*128; idx+=256){
        int kp=idx>>7, n=idx&127;
        SW1[kp*136+n] = pk2(n1W[n*256+2*kp], n1W[n*256+2*kp+1]);
    }
    for(int idx=tid; idx<64*128; idx+=256){
        int kp=idx/128, n=idx%128;
        SW2[kp*136+n] = pk2(n2W[n*128+2*kp], n2W[n*128+2*kp+1]);
    }
    if(tid<128){ sB1[tid]=n1B[tid]; sB2[tid]=n2B[tid]; sG[tid]=lng[tid]; sBt[tid]=lnb[tid]; }
    __syncthreads();

    float acc[2][8][4];
    auto gemmK = [&](const uint32_t* Ab, const uint32_t* Wb, int ng){
        for(int g=0; g<ng; g++){
            uint32_t bfr[8][2];
            #pragma unroll
            for(int bn=0;bn<8;bn++){
                int n = warpN + bn*8 + r4;
                bfr[bn][0] = Wb[(g*8+c4)*136 + n];
                bfr[bn][1] = Wb[(g*8+c4+4)*136 + n];
            }
            #pragma unroll
            for(int am=0;am<2;am++){
                int m0 = warpM + am*16 + r4;
                uint32_t af[4] = { Ab[(g*8+c4)*136+m0], Ab[(g*8+c4)*136+m0+8],
                                   Ab[(g*8+c4+4)*136+m0], Ab[(g*8+c4+4)*136+m0+8] };
                #pragma unroll
                for(int bn=0;bn<8;bn++) mma16(acc[am][bn], af, bfr[bn]);
            }
        }
    };

    for(int tile=blockIdx.x; tile<tiles; tile+=gridDim.x){
        {
            int rl = tid>>1, q = tid&1;
            int n = min(tile*128+rl, NN-1);
            if(q==0){
                const uint4* p = (const uint4*)&hbf[n*64];
                uint32_t* d = &SA[rl];
                #pragma unroll
                for(int j=0;j<16;j++){
                    uint4 u = p[j];
                    d[(j*4+0)*136]=u.x; d[(j*4+1)*136]=u.y;
                    d[(j*4+2)*136]=u.z; d[(j*4+3)*136]=u.w;
                }
            } else {
                float inv = 1.f/fmaxf(g_cnt_col[n],1.f);
                const float4* p = (const float4*)&g_aggsum[(size_t)n*128];
                uint32_t* d = &SA[64*136 + rl];
                #pragma unroll
                for(int j=0;j<32;j++){
                    float4 v = p[j];
                    d[(j*2+0)*136]=pk2(v.x*inv, v.y*inv);
                    d[(j*2+1)*136]=pk2(v.z*inv, v.w*inv);
                }
            }
        }
        __syncthreads();
        #pragma unroll
        for(int am=0;am<2;am++)
            #pragma unroll
            for(int bn=0;bn<8;bn++)
                #pragma unroll
                for(int i=0;i<4;i++) acc[am][bn][i]=0.f;
        gemmK(SA, SW1, 16);
        #pragma unroll
        for(int am=0;am<2;am++)
            #pragma unroll
            for(int hf=0;hf<2;hf++){
                int rl = warpM + am*16 + r4 + hf*8;
                #pragma unroll
                for(int bn=0;bn<8;bn++){
                    int c0 = warpN + bn*8 + c4*2;
                    float v0 = silu_(acc[am][bn][hf*2]   + sB1[c0]);
                    float v1 = silu_(acc[am][bn][hf*2+1] + sB1[c0+1]);
                    SH[(c0>>1)*136 + rl] = pk2(v0, v1);
                }
            }
        __syncthreads();
        #pragma unroll
        for(int am=0;am<2;am++)
            #pragma unroll
            for(int bn=0;bn<8;bn++)
                #pragma unroll
                for(int i=0;i<4;i++) acc[am][bn][i]=0.f;
        gemmK(SH, SW2, 8);
        #pragma unroll
        for(int am=0;am<2;am++)
            #pragma unroll
            for(int hf=0;hf<2;hf++){
                int rl = warpM + am*16 + r4 + hf*8;
                int rg = tile*128 + rl;
                int hn = min(rg, NN-1);
                float s=0.f, sq=0.f;
                #pragma unroll
                for(int bn=0;bn<8;bn++){
                    int c0 = warpN + bn*8 + c4*2;
                    float y0 = acc[am][bn][hf*2]   + sB2[c0]   + h[(size_t)hn*128+c0];
                    float y1 = acc[am][bn][hf*2+1] + sB2[c0+1] + h[(size_t)hn*128+c0+1];
                    acc[am][bn][hf*2]=y0; acc[am][bn][hf*2+1]=y1;
                    s += y0+y1; sq += y0*y0+y1*y1;
                }
                s  += __shfl_xor_sync(0xffffffffu, s, 1);
                s  += __shfl_xor_sync(0xffffffffu, s, 2);
                sq += __shfl_xor_sync(0xffffffffu, sq, 1);
                sq += __shfl_xor_sync(0xffffffffu, sq, 2);
                if(c4==0){
                    sSum[(wid>>2)*128+rl]=s;
                    sSq[(wid>>2)*128+rl]=sq;
                }
            }
        __syncthreads();
        #pragma unroll
        for(int am=0;am<2;am++)
            #pragma unroll
            for(int hf=0;hf<2;hf++){
                int rl = warpM + am*16 + r4 + hf*8;
                int rg = tile*128 + rl;
                if(rg < NN){
                    float tot = sSum[rl]+sSum[128+rl];
                    float mu = tot*(1.f/128.f);
                    float var = (sSq[rl]+sSq[128+rl])*(1.f/128.f) - mu*mu;
                    float is = rsqrtf(fmaxf(var,0.f)+1e-5f);
                    float* op = &out[(size_t)rg*128];
                    #pragma unroll
                    for(int bn=0;bn<8;bn++){
                        int c0 = warpN + bn*8 + c4*2;
                        op[c0]   = (acc[am][bn][hf*2]  -mu)*is*sG[c0]  +sBt[c0];
                        op[c0+1] = (acc[am][bn][hf*2+1]-mu)*is*sG[c0+1]+sBt[c0+1];
                    }
                }
            }
        __syncthreads();
    }
}

// ---------------- x_out ----------------
__global__ void k_xout(const float* __restrict__ x, float* __restrict__ xout){
    int idx = blockIdx.x*blockDim.x + threadIdx.x;
    if(idx >= NN*CC*3) return;
    int n = idx/(CC*3);
    xout[idx] = x[idx] + g_xsum[idx]/fmaxf(g_cnt_row[n],1.f);
}

// ======================= host launcher =======================
extern "C" void kernel_launch(void* const* d_in, const int* in_sizes, int n_in,
                              void* d_out, int out_size){
    const float* h    = (const float*)d_in[0];
    const float* x    = (const float*)d_in[1];
    const int*   row  = (const int*)  d_in[2];
    const int*   col  = (const int*)  d_in[3];
    const float* attr = (const float*)d_in[4];
    const float* cw   = (const float*)d_in[5];
    const float* radW = (const float*)d_in[6];  const float* radB = (const float*)d_in[7];
    const float* e1W  = (const float*)d_in[8];  const float* e1B  = (const float*)d_in[9];
    const float* e2W  = (const float*)d_in[10]; const float* e2B  = (const float*)d_in[11];
    const float* attW = (const float*)d_in[12]; const float* attB = (const float*)d_in[13];
    const float* c1W  = (const float*)d_in[14]; const float* c1B  = (const float*)d_in[15];
    const float* c2W  = (const float*)d_in[16]; const float* c2B  = (const float*)d_in[17];
    const float* n1W  = (const float*)d_in[18]; const float* n1B  = (const float*)d_in[19];
    const float* n2W  = (const float*)d_in[20]; const float* n2B  = (const float*)d_in[21];
    const float* lng  = (const float*)d_in[22]; const float* lnb  = (const float*)d_in[23];
    float* outH = (float*)d_out;
    float* outX = outH + (size_t)NN*128;

    void *p_agg,*p_cntc;
    cudaGetSymbolAddress(&p_agg,  g_aggsum);
    cudaGetSymbolAddress(&p_cntc, g_cnt_col);

    cudaFuncSetAttribute(k_e1,   cudaFuncAttributeMaxDynamicSharedMemorySize, E1SM);
    cudaFuncSetAttribute(k_e2c1, cudaFuncAttributeMaxDynamicSharedMemorySize, E2SM);
    cudaFuncSetAttribute(k_node, cudaFuncAttributeMaxDynamicSharedMemorySize, NODESM);

    k_prepall<<<(int)((PREP_TOTAL+255)/256), 256>>>(x, cw, h, attr, e2W, c1W);
    k_waug<<<128, 256>>>(e1W, radW, radB);
    k_geom<<<NE/8, 256>>>(x, row, col, cw);

    k_e1<<<304,256,E1SM>>>(e1B, row, col, TE128);
    k_e2c1<<<148,256,E2SM>>>(e2B, c1B, c2W, c2B, row, col, attW, attB,
                             x, (float*)p_agg, (float*)p_cntc, TE128);
    k_node<<<TN128,256,NODESM>>>(h, n1W, n1B, n2W, n2B, lng, lnb, outH, TN128);
    k_xout<<<(NN*CC*3+255)/256, 256>>>(x, outX);
}

// round 14
// speedup vs baseline: 6.4683x; 1.0135x over previous
#include <cuda_runtime.h>
#include <cuda_bf16.h>
#include <math.h>
#include <stdint.h>

#define NN 20000
#define NE 320000
#define CC 14
#define TE128 (NE/128)              // 2500
#define TN128 ((NN+127)/128)        // 157

// ---------------- scratch ----------------
__device__ __align__(16) float g_radial[(size_t)NE*128];  // bf16 [E][256] = radial*rinv
__device__ __align__(16) float g_ef1[(size_t)NE*64];      // bf16 [E][128] e1 out
__device__ float g_rinv[NE];
__device__ float g_csum[NN];
__device__ float g_pool3[NN*3];
__device__ float g_aggsum[(size_t)NN*128];
__device__ float g_cnt_col[NN];
__device__ float g_xsum[NN*CC*3];
__device__ float g_cnt_row[NN];
__device__ __align__(16) float g_hbf[NN*64];      // bf16 h
__device__ __align__(16) float g_abf[NN*112];     // bf16 attr
__device__ __align__(16) float g_waug[128*272];   // bf16 [128][544] augmented e1 weight
__device__ __align__(16) float g_we2[128*64];     // bf16 e2W
__device__ __align__(16) float g_wc1[128*64];     // bf16 c1W

__device__ __forceinline__ float sigm(float v){ return 1.f/(1.f+__expf(-v)); }
__device__ __forceinline__ float silu_(float v){ return v*sigm(v); }
__device__ __forceinline__ uint32_t pk2(float lo, float hi){
    __nv_bfloat162 t = __floats2bfloat162_rn(lo, hi);
    return *(uint32_t*)&t;
}
__device__ __forceinline__ void mma16(float* c, const uint32_t* a, const uint32_t* b){
    asm volatile("mma.sync.aligned.m16n8k16.row.col.f32.bf16.bf16.f32 "
        "{%0,%1,%2,%3}, {%4,%5,%6,%7}, {%8,%9}, {%0,%1,%2,%3};"
        : "+f"(c[0]),"+f"(c[1]),"+f"(c[2]),"+f"(c[3])
        : "r"(a[0]),"r"(a[1]),"r"(a[2]),"r"(a[3]), "r"(b[0]),"r"(b[1]));
}
__device__ __forceinline__ void red2(float* addr, float a, float b){
    asm volatile("red.global.add.v2.f32 [%0], {%1, %2};"
        :: "l"(addr), "f"(a), "f"(b) : "memory");
}
__device__ __forceinline__ uint32_t smem_u32(const void* p){
    uint32_t a;
    asm("{ .reg .u64 t; cvta.to.shared.u64 t, %1; cvt.u32.u64 %0, t; }" : "=r"(a) : "l"(p));
    return a;
}
__device__ __forceinline__ void cp16(uint32_t dst, const void* src){
    asm volatile("cp.async.ca.shared.global [%0], [%1], 16;" :: "r"(dst), "l"(src) : "memory");
}
#define CPC() asm volatile("cp.async.commit_group;" ::: "memory")

// ---------------- merged prep ----------------
__global__ void k_prepall(const float* __restrict__ x, const float* __restrict__ cw,
                          const float* __restrict__ h, const float* __restrict__ attr,
                          const float* __restrict__ e2W, const float* __restrict__ c1W){
    long long i = (long long)blockIdx.x*256 + threadIdx.x;
    const long long ZA = (long long)NN*128;
    const long long ZB = ZA + NN;
    const long long ZD = ZB + (long long)NN*42;
    const long long ZE = ZD + NN;
    const long long HC = ZE + (long long)NN*64;
    const long long AC = HC + (long long)NN*112;
    const long long WC = AC + 2*128*64;
    const long long PR = WC + NN;
    if(i < ZA) g_aggsum[i]=0.f;
    else if(i < ZB) g_cnt_col[i-ZA]=0.f;
    else if(i < ZD) g_xsum[i-ZB]=0.f;
    else if(i < ZE) g_cnt_row[i-ZD]=0.f;
    else if(i < HC){ long long j=i-ZE; float2 v=((const float2*)h)[j];
        ((uint32_t*)g_hbf)[j]=pk2(v.x,v.y); }
    else if(i < AC){ long long j=i-HC; float2 v=((const float2*)attr)[j];
        ((uint32_t*)g_abf)[j]=pk2(v.x,v.y); }
    else if(i < WC){ long long j=i-AC;
        if(j < 128*64){ float2 v=((const float2*)e2W)[j]; ((uint32_t*)g_we2)[j]=pk2(v.x,v.y); }
        else { long long k=j-128*64; float2 v=((const float2*)c1W)[k]; ((uint32_t*)g_wc1)[k]=pk2(v.x,v.y); }
    }
    else if(i < PR){
        int n = (int)(i-WC);
        float cnt=0.f, px=0.f, py=0.f, pz=0.f;
        #pragma unroll
        for(int k=0;k<CC;k++){
            float w = cw[n*CC+k];
            if(w != 0.f){
                cnt += 1.f;
                const float* xp = &x[(n*CC+k)*3];
                px += xp[0]; py += xp[1]; pz += xp[2];
            }
        }
        g_csum[n] = cnt;
        float inv = 1.f/cnt;
        g_pool3[n*3+0]=px*inv; g_pool3[n*3+1]=py*inv; g_pool3[n*3+2]=pz*inv;
    }
}
#define PREP_TOTAL ((long long)NN*128 + NN + (long long)NN*42 + NN + (long long)NN*64 + (long long)NN*112 + 2*128*64 + NN)

// ---------------- build augmented e1 weight ----------------
__global__ void k_waug(const float* __restrict__ e1W, const float* __restrict__ radW,
                       const float* __restrict__ radB){
    __shared__ float s[128];
    int n = blockIdx.x, tid = threadIdx.x;
    if(tid < 128) s[tid] = e1W[n*384 + 256 + tid];
    __syncthreads();
    uint32_t* out = (uint32_t*)g_waug + n*272;
    if(tid < 128) out[tid] = pk2(e1W[n*384 + 2*tid], e1W[n*384 + 2*tid + 1]);
    else if(tid-128 < 128){
        int kpl = tid-128;
        int kk = 2*kpl;
        float d0=0.f, d1=0.f;
        #pragma unroll 4
        for(int j=0;j<128;j++){
            float sj = s[j];
            d0 += sj*radW[j*256+kk];
            d1 += sj*radW[j*256+kk+1];
        }
        out[128+kpl] = pk2(d0,d1);
    }
    if(tid==0){
        float bc=0.f;
        for(int j=0;j<128;j++) bc += s[j]*radB[j];
        out[256] = pk2(bc, 0.f);
    }
    if(tid>=1 && tid<16) out[256+tid] = 0u;
}

// ---------------- geometry via tensor cores ---------------
__global__ void __launch_bounds__(256) k_geom(const float* __restrict__ x,
        const int* __restrict__ row, const int* __restrict__ col,
        const float* __restrict__ cw){
    __shared__ float sX[8][88];
    __shared__ float sCW[8][32];
    __shared__ uint32_t sAR[8][112];
    __shared__ uint32_t sAC[8][112];
    __shared__ float sT[8][256];
    const int warp=threadIdx.x>>5, lane=threadIdx.x&31;
    const int e = blockIdx.x*8 + warp;
    if(e >= NE) return;
    const int r=row[e], c=col[e];
    const uint32_t* ab=(const uint32_t*)g_abf;
    if(lane<CC){ sCW[warp][lane]=cw[r*CC+lane]; sCW[warp][16+lane]=cw[c*CC+lane]; }
    if(lane==0){ atomicAdd(&g_cnt_row[r],1.f); atomicAdd(&g_cnt_col[c],1.f); }
    for(int i=lane;i<42;i+=32){ sX[warp][i]=x[r*42+i]; sX[warp][44+i]=x[c*42+i]; }
    for(int i=lane;i<112;i+=32){ sAR[warp][i]=ab[r*112+i]; sAC[warp][i]=ab[c*112+i]; }
    __syncwarp();
    const int r4=lane>>2, c4=lane&3;
    auto dist=[&](int i,int j)->float{
        if(i>=CC||j>=CC) return 0.f;
        float dx=sX[warp][i*3]  -sX[warp][44+j*3];
        float dy=sX[warp][i*3+1]-sX[warp][44+j*3+1];
        float dz=sX[warp][i*3+2]-sX[warp][44+j*3+2];
        return sqrtf(dx*dx+dy*dy+dz*dz);
    };
    uint32_t aD[4];
    {
        int j0=2*c4, j2=2*c4+8;
        aD[0]=pk2(dist(r4,j0),  dist(r4,j0+1));
        aD[1]=pk2(dist(r4+8,j0),dist(r4+8,j0+1));
        aD[2]=pk2(dist(r4,j2),  dist(r4,j2+1));
        aD[3]=pk2(dist(r4+8,j2),dist(r4+8,j2+1));
    }
    auto acv=[&](int j,int b)->float{
        if(j>=CC) return 0.f;
        uint32_t w = sAC[warp][j*8 + (b>>1)];
        __nv_bfloat162 t=*(__nv_bfloat162*)&w;
        float v=(b&1)? __high2float(t): __low2float(t);
        return v*sCW[warp][16+j];
    };
    float T0[4]={0,0,0,0}, T1[4]={0,0,0,0};
    {
        uint32_t b0[2], b1[2];
        b0[0]=pk2(acv(2*c4,r4),    acv(2*c4+1,r4));
        b0[1]=pk2(acv(2*c4+8,r4),  acv(2*c4+9,r4));
        b1[0]=pk2(acv(2*c4,r4+8),  acv(2*c4+1,r4+8));
        b1[1]=pk2(acv(2*c4+8,r4+8),acv(2*c4+9,r4+8));
        mma16(T0,aD,b0);
        mma16(T1,aD,b1);
    }
    {
        float* st=sT[warp];
        st[r4*16+2*c4]       =T0[0]; st[r4*16+2*c4+1]     =T0[1];
        st[(r4+8)*16+2*c4]   =T0[2]; st[(r4+8)*16+2*c4+1] =T0[3];
        st[r4*16+8+2*c4]     =T1[0]; st[r4*16+8+2*c4+1]   =T1[1];
        st[(r4+8)*16+8+2*c4] =T1[2]; st[(r4+8)*16+8+2*c4+1]=T1[3];
    }
    __syncwarp();
    auto arv=[&](int i,int a)->float{
        if(i>=CC) return 0.f;
        uint32_t w = sAR[warp][i*8 + (a>>1)];
        __nv_bfloat162 t=*(__nv_bfloat162*)&w;
        float v=(a&1)? __high2float(t): __low2float(t);
        return v*sCW[warp][i];
    };
    uint32_t aR[4];
    aR[0]=pk2(arv(2*c4,r4),    arv(2*c4+1,r4));
    aR[1]=pk2(arv(2*c4,r4+8),  arv(2*c4+1,r4+8));
    aR[2]=pk2(arv(2*c4+8,r4),  arv(2*c4+9,r4));
    aR[3]=pk2(arv(2*c4+8,r4+8),arv(2*c4+9,r4+8));
    float R0[4]={0,0,0,0}, R1[4]={0,0,0,0};
    {
        const float* st=sT[warp];
        uint32_t b0[2], b1[2];
        b0[0]=pk2(st[(2*c4)*16+r4],    st[(2*c4+1)*16+r4]);
        b0[1]=pk2(st[(2*c4+8)*16+r4],  st[(2*c4+9)*16+r4]);
        b1[0]=pk2(st[(2*c4)*16+r4+8],  st[(2*c4+1)*16+r4+8]);
        b1[1]=pk2(st[(2*c4+8)*16+r4+8],st[(2*c4+9)*16+r4+8]);
        mma16(R0,aR,b0);
        mma16(R1,aR,b1);
    }
    float sq = R0[0]*R0[0]+R0[1]*R0[1]+R0[2]*R0[2]+R0[3]*R0[3]
             + R1[0]*R1[0]+R1[1]*R1[1]+R1[2]*R1[2]+R1[3]*R1[3];
    #pragma unroll
    for(int o=16;o>0;o>>=1) sq += __shfl_xor_sync(0xffffffffu,sq,o);
    float rinv = 1.f/(sqrtf(sq)+1.f);
    uint32_t* go=(uint32_t*)g_radial + (size_t)e*128;
    go[r4*8 + c4]         = pk2(R0[0]*rinv, R0[1]*rinv);
    go[(r4+8)*8 + c4]     = pk2(R0[2]*rinv, R0[3]*rinv);
    go[r4*8 + 4 + c4]     = pk2(R1[0]*rinv, R1[1]*rinv);
    go[(r4+8)*8 + 4 + c4] = pk2(R1[2]*rinv, R1[3]*rinv);
    if(lane==0) g_rinv[e]=rinv;
}

// ===== e1 GEMM: K=544, cp.async 4-stage pipeline, [m][20] smem layout =====
// stage: A 128x20 words (16 kp used) + W 128x20 words; ring of 4 stages.
#define E1SM 81920
__global__ void __launch_bounds__(256,2) k_e1(
    const float* __restrict__ e1B, const int* __restrict__ rowi,
    const int* __restrict__ coli, int tiles)
{
    extern __shared__ uint32_t dsm[];
    __shared__ int sRow[128], sCol[128];
    __shared__ float sBias[128];
    const int tid=threadIdx.x, wid=tid>>5, lane=tid&31;
    const int warpM=(wid&3)*32, warpN=(wid>>2)*64;
    const int ee=tid>>1, q=tid&1;
    const int r4=lane>>2, c4=lane&3;
    const uint32_t* hbf=(const uint32_t*)g_hbf;
    const uint32_t* rad=(const uint32_t*)g_radial;
    const uint32_t* waug=(const uint32_t*)g_waug;
    uint32_t* Obf=(uint32_t*)g_ef1;
    if(tid<128) sBias[tid]=e1B[tid];
    const uint32_t smB = smem_u32(dsm);
    const uint32_t aoffB = (uint32_t)(ee*20 + q*8)*4u;

    for(int tile=blockIdx.x; tile<tiles; tile+=gridDim.x){
        if(tid<128){ sRow[tid]=rowi[tile*128+tid]; sCol[tid]=coli[tile*128+tid]; }
        __syncthreads();
        const int rg = tile*128 + ee;

        auto issue=[&](int kt){
            const int s = kt&3;
            const uint32_t dA = smB + (uint32_t)s*10240u + aoffB;
            const uint32_t dW = smB + 40960u + (uint32_t)s*10240u + aoffB;
            const uint32_t* wsrc = &waug[ee*272 + kt*16 + q*8];
            cp16(dW, wsrc); cp16(dW+16, wsrc+4);
            const int kp = kt*16 + q*8;
            if(kp < 256){
                const uint32_t* asrc;
                if(kp < 64)       asrc = &hbf[sRow[ee]*64 + kp];
                else if(kp < 128) asrc = &hbf[sCol[ee]*64 + (kp-64)];
                else              asrc = &rad[(size_t)rg*128 + (kp-128)];
                cp16(dA, asrc); cp16(dA+16, asrc+4);
            } else {
                uint32_t* sa = dsm + s*2560 + ee*20 + q*8;
                sa[0] = (q==0)? pk2(g_rinv[rg],0.f) : 0u;
                #pragma unroll
                for(int j=1;j<8;j++) sa[j]=0u;
            }
        };

        float acc[2][8][4];
        #pragma unroll
        for(int am=0;am<2;am++)
            #pragma unroll
            for(int bn=0;bn<8;bn++)
                #pragma unroll
                for(int i=0;i<4;i++) acc[am][bn][i]=0.f;

        issue(0); CPC(); issue(1); CPC(); issue(2); CPC();

        #pragma unroll 1
        for(int kt=0; kt<17; kt++){
            asm volatile("cp.async.wait_group 2;" ::: "memory");
            __syncthreads();
            if(kt+3 <= 16) issue(kt+3);
            CPC();
            const uint32_t* Ab = dsm + (kt&3)*2560;
            const uint32_t* Wb = dsm + 10240 + (kt&3)*2560;
            #pragma unroll
            for(int g=0; g<2; g++){
                uint32_t bfr[8][2];
                #pragma unroll
                for(int bn=0;bn<8;bn++){
                    int n = warpN + bn*8 + r4;
                    bfr[bn][0] = Wb[n*20 + g*8 + c4];
                    bfr[bn][1] = Wb[n*20 + g*8 + c4 + 4];
                }
                #pragma unroll
                for(int am=0;am<2;am++){
                    int m0 = warpM + am*16 + r4;
                    uint32_t af[4] = { Ab[m0*20 + g*8 + c4],
                                       Ab[(m0+8)*20 + g*8 + c4],
                                       Ab[m0*20 + g*8 + c4 + 4],
                                       Ab[(m0+8)*20 + g*8 + c4 + 4] };
                    #pragma unroll
                    for(int bn=0;bn<8;bn++) mma16(acc[am][bn], af, bfr[bn]);
                }
            }
        }

        #pragma unroll
        for(int am=0;am<2;am++)
            #pragma unroll
            for(int hf=0;hf<2;hf++){
                int rl = warpM + am*16 + r4 + hf*8;
                int rgo = tile*128 + rl;
                uint32_t* op = &Obf[(size_t)rgo*64];
                #pragma unroll
                for(int bn=0;bn<8;bn++){
                    int c0 = warpN + bn*8 + c4*2;
                    float v0 = silu_(acc[am][bn][hf*2]   + sBias[c0]);
                    float v1 = silu_(acc[am][bn][hf*2+1] + sBias[c0+1]);
                    op[c0>>1] = pk2(v0, v1);
                }
            }
        __syncthreads();
    }
}

// ===== fused e2 + gate + agg + c1 + c2 + roller + trans scatter ==========
#define E2SM 181824
__global__ void __launch_bounds__(256) k_e2c1(
    const float* __restrict__ e2B, const float* __restrict__ c1B,
    const float* __restrict__ c2Wf, const float* __restrict__ c2bf,
    const int* __restrict__ rowi, const int* __restrict__ coli,
    const float* __restrict__ attWg, const float* __restrict__ attbg,
    const float* __restrict__ x,
    float* __restrict__ agg, float* __restrict__ cnt, int tiles)
{
    extern __shared__ uint32_t dsm[];
    uint32_t* SA   = dsm;
    uint32_t* SW2  = dsm + 17408;
    uint32_t* SW3  = dsm + 26112;
    uint32_t* SEF  = dsm + 34816;
    uint32_t* SC2P = dsm + 43520;
    int*   sRow   = (int*)(dsm + 44544);
    int*   sCol   = sRow + 128;
    float* sBias  = (float*)(sCol + 128);
    float* sBias2 = sBias + 128;
    float* sAtt   = sBias2 + 128;
    float* sDot   = sAtt + 128;
    float* scb    = sDot + 256;
    const int tid=threadIdx.x, wid=tid>>5, lane=tid&31;
    const int warpM=(wid&3)*32, warpN=(wid>>2)*64;
    const int r4=lane>>2, c4=lane&3;
    const uint32_t* Abf=(const uint32_t*)g_ef1;
    const uint32_t* W2g=(const uint32_t*)g_we2;
    const uint32_t* W3g=(const uint32_t*)g_wc1;

    for(int idx=tid; idx<128*64; idx+=256){
        int n = idx>>6, kp = idx&63;
        SW2[kp*136+n] = W2g[idx];
        SW3[kp*136+n] = W3g[idx];
    }
    for(int idx=tid; idx<64*16; idx+=256){
        int kp = idx>>4, n = idx&15;
        SC2P[idx] = (n<14)? pk2(c2Wf[n*128+2*kp], c2Wf[n*128+2*kp+1]) : 0u;
    }
    if(tid<16) scb[tid] = (tid<14)? c2bf[tid] : 0.f;
    if(tid<128){ sBias[tid]=e2B[tid]; sBias2[tid]=c1B[tid]; sAtt[tid]=attWg[tid]; }
    const float attb = attbg[0];

    auto ldAfull = [&](int t, uint4* v){
        const uint32_t* p = &Abf[(size_t)(t*128 + (tid>>1))*64 + (tid&1)*32];
        #pragma unroll
        for(int j=0;j<8;j++) v[j] = ((const uint4*)p)[j];
    };
    auto stsA = [&](int b, const uint4* v){
        uint32_t* base = &SA[b*8704 + ((tid&1)*32)*136 + (tid>>1)];
        #pragma unroll
        for(int j=0;j<8;j++){
            base[(j*4+0)*136]=v[j].x; base[(j*4+1)*136]=v[j].y;
            base[(j*4+2)*136]=v[j].z; base[(j*4+3)*136]=v[j].w;
        }
    };
    float acc[2][8][4];
    auto gemm128 = [&](const uint32_t* Ab, const uint32_t* Wb){
        #pragma unroll
        for(int g=0; g<8; g++){
            uint32_t bfr[8][2];
            #pragma unroll
            for(int bn=0;bn<8;bn++){
                int n = warpN + bn*8 + r4;
                bfr[bn][0] = Wb[(g*8+c4)*136 + n];
                bfr[bn][1] = Wb[(g*8+c4+4)*136 + n];
            }
            #pragma unroll
            for(int am=0;am<2;am++){
                int m0 = warpM + am*16 + r4;
                uint32_t af[4] = { Ab[(g*8+c4)*136+m0], Ab[(g*8+c4)*136+m0+8],
                                   Ab[(g*8+c4+4)*136+m0], Ab[(g*8+c4+4)*136+m0+8] };
                #pragma unroll
                for(int bn=0;bn<8;bn++) mma16(acc[am][bn], af, bfr[bn]);
            }
        }
    };

    { uint4 v[8]; ldAfull(blockIdx.x, v); stsA(0, v); }
    int pb = 0;

    for(int tile=blockIdx.x; tile<tiles; tile+=gridDim.x){
        if(tid<128){ sRow[tid]=rowi[tile*128+tid]; sCol[tid]=coli[tile*128+tid]; }
        __syncthreads();
        int nt = tile + gridDim.x;
        bool pf = nt < tiles;
        uint4 an[8];
        if(pf) ldAfull(nt, an);

        #pragma unroll
        for(int am=0;am<2;am++)
            #pragma unroll
            for(int bn=0;bn<8;bn++)
                #pragma unroll
                for(int i=0;i<4;i++) acc[am][bn][i]=0.f;
        gemm128(&SA[pb*8704], SW2);
        if(pf) stsA(pb^1, an);

        #pragma unroll
        for(int am=0;am<2;am++)
            #pragma unroll
            for(int bn=0;bn<8;bn++){
                int c0 = warpN + bn*8 + c4*2;
                float* a = acc[am][bn];
                a[0]=silu_(a[0]+sBias[c0]);   a[1]=silu_(a[1]+sBias[c0+1]);
                a[2]=silu_(a[2]+sBias[c0]);   a[3]=silu_(a[3]+sBias[c0+1]);
            }
        {
            float dot[2][2] = {{0.f,0.f},{0.f,0.f}};
            #pragma unroll
            for(int am=0;am<2;am++)
                #pragma unroll
                for(int bn=0;bn<8;bn++){
                    int c0 = warpN + bn*8 + c4*2;
                    float w0=sAtt[c0], w1=sAtt[c0+1];
                    dot[am][0] += acc[am][bn][0]*w0 + acc[am][bn][1]*w1;
                    dot[am][1] += acc[am][bn][2]*w0 + acc[am][bn][3]*w1;
                }
            #pragma unroll
            for(int am=0;am<2;am++)
                #pragma unroll
                for(int hf=0;hf<2;hf++){
                    dot[am][hf] += __shfl_xor_sync(0xffffffffu, dot[am][hf], 1);
                    dot[am][hf] += __shfl_xor_sync(0xffffffffu, dot[am][hf], 2);
                }
            if(c4==0){
                #pragma unroll
                for(int am=0;am<2;am++){
                    sDot[(wid>>2)*128 + warpM+am*16+r4]   = dot[am][0];
                    sDot[(wid>>2)*128 + warpM+am*16+r4+8] = dot[am][1];
                }
            }
            __syncthreads();
            #pragma unroll
            for(int am=0;am<2;am++)
                #pragma unroll
                for(int hf=0;hf<2;hf++){
                    int rl = warpM + am*16 + r4 + hf*8;
                    float g = sigm(sDot[rl] + sDot[128+rl] + attb);
                    #pragma unroll
                    for(int bn=0;bn<8;bn++){
                        acc[am][bn][hf*2]   *= g;
                        acc[am][bn][hf*2+1] *= g;
                    }
                }
        }
        #pragma unroll
        for(int am=0;am<2;am++)
            #pragma unroll
            for(int hf=0;hf<2;hf++){
                int rl = warpM + am*16 + r4 + hf*8;
                int cc = sCol[rl];
                float* ag = &agg[(size_t)cc*128];
                #pragma unroll
                for(int bn=0;bn<8;bn++){
                    int c0 = warpN + bn*8 + c4*2;
                    float v0 = acc[am][bn][hf*2], v1 = acc[am][bn][hf*2+1];
                    red2(ag+c0, v0, v1);
                    SEF[(c0>>1)*136 + rl] = pk2(v0, v1);
                }
            }
        __syncthreads();

        #pragma unroll
        for(int am=0;am<2;am++)
            #pragma unroll
            for(int bn=0;bn<8;bn++)
                #pragma unroll
                for(int i=0;i<4;i++) acc[am][bn][i]=0.f;
        gemm128(SEF, SW3);
        #pragma unroll
        for(int am=0;am<2;am++)
            #pragma unroll
            for(int hf=0;hf<2;hf++){
                int rl = warpM + am*16 + r4 + hf*8;
                #pragma unroll
                for(int bn=0;bn<8;bn++){
                    int c0 = warpN + bn*8 + c4*2;
                    float v0 = silu_(acc[am][bn][hf*2]   + sBias2[c0]);
                    float v1 = silu_(acc[am][bn][hf*2+1] + sBias2[c0+1]);
                    SA[pb*8704 + (c0>>1)*136 + rl] = pk2(v0, v1);
                }
            }
        __syncthreads();

        if(wid < 4){
            float accC[2][2][4];
            #pragma unroll
            for(int am=0;am<2;am++)
                #pragma unroll
                for(int bn=0;bn<2;bn++)
                    #pragma unroll
                    for(int i=0;i<4;i++) accC[am][bn][i]=0.f;
            #pragma unroll
            for(int g=0; g<8; g++){
                uint32_t bfr[2][2];
                #pragma unroll
                for(int bn=0;bn<2;bn++){
                    int n = bn*8 + r4;
                    bfr[bn][0] = SC2P[(g*8+c4)*16 + n];
                    bfr[bn][1] = SC2P[(g*8+c4+4)*16 + n];
                }
                #pragma unroll
                for(int am=0;am<2;am++){
                    int m0 = warpM + am*16 + r4;
                    uint32_t af[4] = { SA[pb*8704+(g*8+c4)*136+m0],
                                       SA[pb*8704+(g*8+c4)*136+m0+8],
                                       SA[pb*8704+(g*8+c4+4)*136+m0],
                                       SA[pb*8704+(g*8+c4+4)*136+m0+8] };
                    #pragma unroll
                    for(int bn=0;bn<2;bn++) mma16(accC[am][bn], af, bfr[bn]);
                }
            }
            float* sCh = (float*)SEF;
            #pragma unroll
            for(int am=0;am<2;am++)
                #pragma unroll
                for(int hf=0;hf<2;hf++){
                    int rl = warpM + am*16 + r4 + hf*8;
                    #pragma unroll
                    for(int bn=0;bn<2;bn++){
                        int c0 = bn*8 + c4*2;
                        sCh[rl*16+c0]   = accC[am][bn][hf*2];
                        sCh[rl*16+c0+1] = accC[am][bn][hf*2+1];
                    }
                }
        }
        __syncthreads();

        if(tid < 128){
            const float* sCh = (const float*)SEF;
            int rl = tid;
            int r = sRow[rl], c = sCol[rl];
            float P[15]; P[0]=0.f;
            #pragma unroll
            for(int j=0;j<14;j++) P[j+1] = P[j] + sCh[rl*16+j] + scb[j];
            int cs = (int)(g_csum[r]+0.5f);
            int w = 15 - cs;
            float invw = 1.f/(float)w;
            float px=g_pool3[c*3], py=g_pool3[c*3+1], pz=g_pool3[c*3+2];
            float vals[42];
            #pragma unroll
            for(int i=0;i<14;i++){
                int e2 = min(i+w, 14);
                float pooled = (P[e2]-P[i])*invw;
                const float* xp = &x[((size_t)r*14+i)*3];
                vals[i*3+0] = (xp[0]-px)*pooled;
                vals[i*3+1] = (xp[1]-py)*pooled;
                vals[i*3+2] = (xp[2]-pz)*pooled;
            }
            float* base = &g_xsum[r*42];
            #pragma unroll
            for(int t=0;t<21;t++) red2(base+2*t, vals[2*t], vals[2*t+1]);
        }
        __syncthreads();
        pb ^= 1;
    }
}

// ===== fused node path =====
#define NODESM 208896
__global__ void __launch_bounds__(256,1) k_node(
    const float* __restrict__ h, const float* __restrict__ n1W,
    const float* __restrict__ n1B, const float* __restrict__ n2W,
    const float* __restrict__ n2B, const float* __restrict__ lng,
    const float* __restrict__ lnb, float* __restrict__ out, int tiles)
{
    extern __shared__ uint32_t dsm[];
    uint32_t* SW1 = dsm;
    uint32_t* SA  = dsm + 17408;
    uint32_t* SW2 = dsm + 34816;
    uint32_t* SH  = dsm + 43520;
    __shared__ float sB1[128], sB2[128], sG[128], sBt[128];
    __shared__ float sSum[256], sSq[256];
    const int tid=threadIdx.x, wid=tid>>5, lane=tid&31;
    const int warpM=(wid&3)*32, warpN=(wid>>2)*64;
    const int r4=lane>>2, c4=lane&3;
    const uint32_t* hbf=(const uint32_t*)g_hbf;

    for(int idx=tid; idx<128*128; idx+=256){
        int kp=idx>>7, n=idx&127;
        SW1[kp*136+n] = pk2(n1W[n*256+2*kp], n1W[n*256+2*kp+1]);
    }
    for(int idx=tid; idx<64*128; idx+=256){
        int kp=idx/128, n=idx%128;
        SW2[kp*136+n] = pk2(n2W[n*128+2*kp], n2W[n*128+2*kp+1]);
    }
    if(tid<128){ sB1[tid]=n1B[tid]; sB2[tid]=n2B[tid]; sG[tid]=lng[tid]; sBt[tid]=lnb[tid]; }
    __syncthreads();

    float acc[2][8][4];
    auto gemmK = [&](const uint32_t* Ab, const uint32_t* Wb, int ng){
        for(int g=0; g<ng; g++){
            uint32_t bfr[8][2];
            #pragma unroll
            for(int bn=0;bn<8;bn++){
                int n = warpN + bn*8 + r4;
                bfr[bn][0] = Wb[(g*8+c4)*136 + n];
                bfr[bn][1] = Wb[(g*8+c4+4)*136 + n];
            }
            #pragma unroll
            for(int am=0;am<2;am++){
                int m0 = warpM + am*16 + r4;
                uint32_t af[4] = { Ab[(g*8+c4)*136+m0], Ab[(g*8+c4)*136+m0+8],
                                   Ab[(g*8+c4+4)*136+m0], Ab[(g*8+c4+4)*136+m0+8] };
                #pragma unroll
                for(int bn=0;bn<8;bn++) mma16(acc[am][bn], af, bfr[bn]);
            }
        }
    };

    for(int tile=blockIdx.x; tile<tiles; tile+=gridDim.x){
        {
            int rl = tid>>1, q = tid&1;
            int n = min(tile*128+rl, NN-1);
            if(q==0){
                const uint4* p = (const uint4*)&hbf[n*64];
                uint32_t* d = &SA[rl];
                #pragma unroll
                for(int j=0;j<16;j++){
                    uint4 u = p[j];
                    d[(j*4+0)*136]=u.x; d[(j*4+1)*136]=u.y;
                    d[(j*4+2)*136]=u.z; d[(j*4+3)*136]=u.w;
                }
            } else {
                float inv = 1.f/fmaxf(g_cnt_col[n],1.f);
                const float4* p = (const float4*)&g_aggsum[(size_t)n*128];
                uint32_t* d = &SA[64*136 + rl];
                #pragma unroll
                for(int j=0;j<32;j++){
                    float4 v = p[j];
                    d[(j*2+0)*136]=pk2(v.x*inv, v.y*inv);
                    d[(j*2+1)*136]=pk2(v.z*inv, v.w*inv);
                }
            }
        }
        __syncthreads();
        #pragma unroll
        for(int am=0;am<2;am++)
            #pragma unroll
            for(int bn=0;bn<8;bn++)
                #pragma unroll
                for(int i=0;i<4;i++) acc[am][bn][i]=0.f;
        gemmK(SA, SW1, 16);
        #pragma unroll
        for(int am=0;am<2;am++)
            #pragma unroll
            for(int hf=0;hf<2;hf++){
                int rl = warpM + am*16 + r4 + hf*8;
                #pragma unroll
                for(int bn=0;bn<8;bn++){
                    int c0 = warpN + bn*8 + c4*2;
                    float v0 = silu_(acc[am][bn][hf*2]   + sB1[c0]);
                    float v1 = silu_(acc[am][bn][hf*2+1] + sB1[c0+1]);
                    SH[(c0>>1)*136 + rl] = pk2(v0, v1);
                }
            }
        __syncthreads();
        #pragma unroll
        for(int am=0;am<2;am++)
            #pragma unroll
            for(int bn=0;bn<8;bn++)
                #pragma unroll
                for(int i=0;i<4;i++) acc[am][bn][i]=0.f;
        gemmK(SH, SW2, 8);
        #pragma unroll
        for(int am=0;am<2;am++)
            #pragma unroll
            for(int hf=0;hf<2;hf++){
                int rl = warpM + am*16 + r4 + hf*8;
                int rg = tile*128 + rl;
                int hn = min(rg, NN-1);
                float s=0.f, sq=0.f;
                #pragma unroll
                for(int bn=0;bn<8;bn++){
                    int c0 = warpN + bn*8 + c4*2;
                    float y0 = acc[am][bn][hf*2]   + sB2[c0]   + h[(size_t)hn*128+c0];
                    float y1 = acc[am][bn][hf*2+1] + sB2[c0+1] + h[(size_t)hn*128+c0+1];
                    acc[am][bn][hf*2]=y0; acc[am][bn][hf*2+1]=y1;
                    s += y0+y1; sq += y0*y0+y1*y1;
                }
                s  += __shfl_xor_sync(0xffffffffu, s, 1);
                s  += __shfl_xor_sync(0xffffffffu, s, 2);
                sq += __shfl_xor_sync(0xffffffffu, sq, 1);
                sq += __shfl_xor_sync(0xffffffffu, sq, 2);
                if(c4==0){
                    sSum[(wid>>2)*128+rl]=s;
                    sSq[(wid>>2)*128+rl]=sq;
                }
            }
        __syncthreads();
        #pragma unroll
        for(int am=0;am<2;am++)
            #pragma unroll
            for(int hf=0;hf<2;hf++){
                int rl = warpM + am*16 + r4 + hf*8;
                int rg = tile*128 + rl;
                if(rg < NN){
                    float tot = sSum[rl]+sSum[128+rl];
                    float mu = tot*(1.f/128.f);
                    float var = (sSq[rl]+sSq[128+rl])*(1.f/128.f) - mu*mu;
                    float is = rsqrtf(fmaxf(var,0.f)+1e-5f);
                    float* op = &out[(size_t)rg*128];
                    #pragma unroll
                    for(int bn=0;bn<8;bn++){
                        int c0 = warpN + bn*8 + c4*2;
                        op[c0]   = (acc[am][bn][hf*2]  -mu)*is*sG[c0]  +sBt[c0];
                        op[c0+1] = (acc[am][bn][hf*2+1]-mu)*is*sG[c0+1]+sBt[c0+1];
                    }
                }
            }
        __syncthreads();
    }
}

// ---------------- x_out ----------------
__global__ void k_xout(const float* __restrict__ x, float* __restrict__ xout){
    int idx = blockIdx.x*blockDim.x + threadIdx.x;
    if(idx >= NN*CC*3) return;
    int n = idx/(CC*3);
    xout[idx] = x[idx] + g_xsum[idx]/fmaxf(g_cnt_row[n],1.f);
}

// ======================= host launcher =======================
extern "C" void kernel_launch(void* const* d_in, const int* in_sizes, int n_in,
                              void* d_out, int out_size){
    const float* h    = (const float*)d_in[0];
    const float* x    = (const float*)d_in[1];
    const int*   row  = (const int*)  d_in[2];
    const int*   col  = (const int*)  d_in[3];
    const float* attr = (const float*)d_in[4];
    const float* cw   = (const float*)d_in[5];
    const float* radW = (const float*)d_in[6];  const float* radB = (const float*)d_in[7];
    const float* e1W  = (const float*)d_in[8];  const float* e1B  = (const float*)d_in[9];
    const float* e2W  = (const float*)d_in[10]; const float* e2B  = (const float*)d_in[11];
    const float* attW = (const float*)d_in[12]; const float* attB = (const float*)d_in[13];
    const float* c1W  = (const float*)d_in[14]; const float* c1B  = (const float*)d_in[15];
    const float* c2W  = (const float*)d_in[16]; const float* c2B  = (const float*)d_in[17];
    const float* n1W  = (const float*)d_in[18]; const float* n1B  = (const float*)d_in[19];
    const float* n2W  = (const float*)d_in[20]; const float* n2B  = (const float*)d_in[21];
    const float* lng  = (const float*)d_in[22]; const float* lnb  = (const float*)d_in[23];
    float* outH = (float*)d_out;
    float* outX = outH + (size_t)NN*128;

    void *p_agg,*p_cntc;
    cudaGetSymbolAddress(&p_agg,  g_aggsum);
    cudaGetSymbolAddress(&p_cntc, g_cnt_col);

    cudaFuncSetAttribute(k_e1,   cudaFuncAttributeMaxDynamicSharedMemorySize, E1SM);
    cudaFuncSetAttribute(k_e2c1, cudaFuncAttributeMaxDynamicSharedMemorySize, E2SM);
    cudaFuncSetAttribute(k_node, cudaFuncAttributeMaxDynamicSharedMemorySize, NODESM);

    k_prepall<<<(int)((PREP_TOTAL+255)/256), 256>>>(x, cw, h, attr, e2W, c1W);
    k_waug<<<128, 256>>>(e1W, radW, radB);
    k_geom<<<NE/8, 256>>>(x, row, col, cw);

    k_e1<<<304,256,E1SM>>>(e1B, row, col, TE128);
    k_e2c1<<<148,256,E2SM>>>(e2B, c1B, c2W, c2B, row, col, attW, attB,
                             x, (float*)p_agg, (float*)p_cntc, TE128);
    k_node<<<TN128,256,NODESM>>>(h, n1W, n1B, n2W, n2B, lng, lnb, outH, TN128);
    k_xout<<<(NN*CC*3+255)/256, 256>>>(x, outX);
}